// round 2
// baseline (speedup 1.0000x reference)
#include <cuda_runtime.h>
#include <cstdint>
#include <cmath>

// Problem constants
#define B_ 8
#define T_ 4096
#define E_ 512
#define H_ 8
#define D_ 64
#define M_ (B_*T_)   // 32768

// Scratch (allocation-free rule: __device__ globals)
__device__ float g_query[(size_t)M_ * E_];   // 64 MB
__device__ float g_kc[(size_t)M_ * E_];      // 64 MB (key_content)
__device__ float g_scores[(size_t)M_ * H_];  // 1 MB
__device__ float g_scale_q[B_ * E_];         // q_flat
__device__ float g_scale_k[B_ * E_];         // k_sum flat

// ---------------------------------------------------------------------------
// Tiled fp32 SGEMM: C[M,N] = op(A[M,K]) @ W[K,N] + bias + extras
//   SCALE_A: A[m,k] *= ascale[b*E_ + k]   (b = batch of row m)
//   SCALE_C: C[m,n] *= cscale[b*E_ + n]   (applied before bias)
//   ADD_C  : C[m,n] += addend[m*E_ + n]
// BM=BN=128, BK=16, 256 threads, 8x8 per-thread microtile.
// ---------------------------------------------------------------------------
template<bool SCALE_A, bool SCALE_C, bool ADD_C>
__global__ __launch_bounds__(256, 2)
void sgemm_kernel(const float* __restrict__ A, const float* __restrict__ W,
                  const float* __restrict__ bias, float* __restrict__ C,
                  const float* __restrict__ ascale,
                  const float* __restrict__ cscale,
                  const float* __restrict__ addend)
{
    constexpr int BM = 128, BN = 128, BK = 16;
    __shared__ float As[BK][BM];
    __shared__ float Bs[BK][BN];

    const int row0 = blockIdx.y * BM;
    const int col0 = blockIdx.x * BN;
    const int b    = row0 / T_;          // all rows in a 128-row tile share a batch
    const int tid  = threadIdx.x;

    // A-tile load: 128 rows x 16 k. Each thread: 1 row, 8 k-floats (2 x float4).
    const int a_row = tid & 127;         // 0..127
    const int a_k   = (tid >> 7) << 3;   // 0 or 8
    // W-tile load: 16 k x 128 n, two float4 per thread
    const int b_k   = tid >> 5;          // 0..7
    const int b_col = (tid & 31) << 2;   // 0..124
    // compute microtile position
    const int tm = (tid >> 4) << 3;      // 0..120
    const int tn = (tid & 15) << 3;      // 0..120

    float acc[8][8];
    #pragma unroll
    for (int i = 0; i < 8; i++)
        #pragma unroll
        for (int j = 0; j < 8; j++) acc[i][j] = 0.f;

    const float* Arow = A + (size_t)(row0 + a_row) * E_;

    for (int k0 = 0; k0 < E_; k0 += BK) {
        float4 av0 = *reinterpret_cast<const float4*>(Arow + k0 + a_k);
        float4 av1 = *reinterpret_cast<const float4*>(Arow + k0 + a_k + 4);
        if (SCALE_A) {
            const float* sc = ascale + b * E_ + k0 + a_k;
            av0.x *= sc[0]; av0.y *= sc[1]; av0.z *= sc[2]; av0.w *= sc[3];
            av1.x *= sc[4]; av1.y *= sc[5]; av1.z *= sc[6]; av1.w *= sc[7];
        }
        As[a_k + 0][a_row] = av0.x;
        As[a_k + 1][a_row] = av0.y;
        As[a_k + 2][a_row] = av0.z;
        As[a_k + 3][a_row] = av0.w;
        As[a_k + 4][a_row] = av1.x;
        As[a_k + 5][a_row] = av1.y;
        As[a_k + 6][a_row] = av1.z;
        As[a_k + 7][a_row] = av1.w;

        float4 w0 = *reinterpret_cast<const float4*>(W + (size_t)(k0 + b_k    ) * E_ + col0 + b_col);
        float4 w1 = *reinterpret_cast<const float4*>(W + (size_t)(k0 + b_k + 8) * E_ + col0 + b_col);
        *reinterpret_cast<float4*>(&Bs[b_k    ][b_col]) = w0;
        *reinterpret_cast<float4*>(&Bs[b_k + 8][b_col]) = w1;
        __syncthreads();

        #pragma unroll
        for (int k = 0; k < BK; k++) {
            float4 a0 = *reinterpret_cast<const float4*>(&As[k][tm]);
            float4 a1 = *reinterpret_cast<const float4*>(&As[k][tm + 4]);
            float4 bv0 = *reinterpret_cast<const float4*>(&Bs[k][tn]);
            float4 bv1 = *reinterpret_cast<const float4*>(&Bs[k][tn + 4]);
            float am[8] = {a0.x, a0.y, a0.z, a0.w, a1.x, a1.y, a1.z, a1.w};
            float bn[8] = {bv0.x, bv0.y, bv0.z, bv0.w, bv1.x, bv1.y, bv1.z, bv1.w};
            #pragma unroll
            for (int i = 0; i < 8; i++)
                #pragma unroll
                for (int j = 0; j < 8; j++)
                    acc[i][j] = fmaf(am[i], bn[j], acc[i][j]);
        }
        __syncthreads();
    }

    // epilogue
    #pragma unroll
    for (int i = 0; i < 8; i++) {
        const int m = row0 + tm + i;
        float* crow = C + (size_t)m * E_ + col0 + tn;
        const float* adrow = ADD_C ? (addend + (size_t)m * E_ + col0 + tn) : nullptr;
        #pragma unroll
        for (int jj = 0; jj < 8; jj += 4) {
            float4 v;
            float* vp = &v.x;
            #pragma unroll
            for (int u = 0; u < 4; u++) {
                const int n = col0 + tn + jj + u;
                float val = acc[i][jj + u];
                if (SCALE_C) val *= cscale[b * E_ + n];
                val += bias[n];
                if (ADD_C) val += adrow[jj + u];
                vp[u] = val;
            }
            *reinterpret_cast<float4*>(crow + jj) = v;
        }
    }
}

// ---------------------------------------------------------------------------
// scores[m,h] = dot(X[m,:], Wa[:,h]) + ba[h];  Wa is (E,H) row-major.
// One warp per row; Wa staged transposed in smem (conflict-free).
// ---------------------------------------------------------------------------
__global__ __launch_bounds__(256)
void scores_kernel(const float* __restrict__ X, const float* __restrict__ Wa,
                   const float* __restrict__ ba, float* __restrict__ S)
{
    __shared__ float wT[H_][E_];   // 16 KB, wT[h][e] = Wa[e*H + h]
    __shared__ float bsh[H_];
    const int tid = threadIdx.x;
    for (int i = tid; i < E_ * H_; i += 256) wT[i & (H_ - 1)][i >> 3] = Wa[i];
    if (tid < H_) bsh[tid] = ba[tid];
    __syncthreads();

    const int warp = tid >> 5, lane = tid & 31;
    const int m = blockIdx.x * 8 + warp;
    const float* xr = X + (size_t)m * E_;

    float s[H_] = {0.f, 0.f, 0.f, 0.f, 0.f, 0.f, 0.f, 0.f};
    for (int e = lane; e < E_; e += 32) {
        const float xv = xr[e];
        #pragma unroll
        for (int h = 0; h < H_; h++) s[h] = fmaf(xv, wT[h][e], s[h]);
    }
    #pragma unroll
    for (int off = 16; off; off >>= 1)
        #pragma unroll
        for (int h = 0; h < H_; h++) s[h] += __shfl_xor_sync(0xffffffffu, s[h], off);
    if (lane < H_) S[(size_t)m * H_ + lane] = s[lane] + bsh[lane];
}

// ---------------------------------------------------------------------------
// Softmax over T (masked, scaled by 1/sqrt(D)) + weighted pooling over content.
// One block per (b,h). Output: outscale[b*E + h*D + d].
// ---------------------------------------------------------------------------
__global__ __launch_bounds__(256)
void pool_kernel(const float* __restrict__ S, const float* __restrict__ content,
                 const unsigned char* __restrict__ mask, float* __restrict__ outscale)
{
    const int b = blockIdx.x >> 3;
    const int h = blockIdx.x & 7;
    __shared__ float w[T_];       // 16 KB
    __shared__ float red[256];
    const int tid = threadIdx.x;

    float mx = -INFINITY;
    for (int t = tid; t < T_; t += 256) {
        float s = S[((size_t)b * T_ + t) * H_ + h] * 0.125f;  // 1/sqrt(64)
        if (mask[b * T_ + t]) s = -INFINITY;
        w[t] = s;
        mx = fmaxf(mx, s);
    }
    red[tid] = mx; __syncthreads();
    #pragma unroll
    for (int s2 = 128; s2 > 0; s2 >>= 1) {
        if (tid < s2) red[tid] = fmaxf(red[tid], red[tid + s2]);
        __syncthreads();
    }
    mx = red[0];
    __syncthreads();

    float sum = 0.f;
    for (int t = tid; t < T_; t += 256) {
        const float e = expf(w[t] - mx);   // expf(-inf)=0 handles mask
        w[t] = e;
        sum += e;
    }
    red[tid] = sum; __syncthreads();
    #pragma unroll
    for (int s2 = 128; s2 > 0; s2 >>= 1) {
        if (tid < s2) red[tid] += red[tid + s2];
        __syncthreads();
    }
    const float inv = 1.f / red[0];
    __syncthreads();

    // pooling: 4 t-groups x 64 d-lanes
    const int d = tid & 63;
    const int g = tid >> 6;
    float acc = 0.f;
    const float* cp = content + (size_t)b * T_ * E_ + h * D_ + d;
    for (int t = g; t < T_; t += 16) {
        #pragma unroll
        for (int u = 0; u < 4; u++)
            acc = fmaf(w[t + 4 * u], cp[(size_t)(t + 4 * u) * E_], acc);
    }
    red[tid] = acc; __syncthreads();
    if (tid < 64) {
        acc = red[tid] + red[tid + 64] + red[tid + 128] + red[tid + 192];
        outscale[b * E_ + h * D_ + d] = acc * inv;
    }
}

// ---------------------------------------------------------------------------
// Launch sequence
// ---------------------------------------------------------------------------
extern "C" void kernel_launch(void* const* d_in, const int* in_sizes, int n_in,
                              void* d_out, int out_size)
{
    const float* x            = (const float*)d_in[0];   // q (k,v ignored by module)
    const unsigned char* mask = (const unsigned char*)d_in[3];
    const float* Wq  = (const float*)d_in[4];
    const float* bq  = (const float*)d_in[5];
    const float* Waq = (const float*)d_in[6];
    const float* baq = (const float*)d_in[7];
    const float* Wk  = (const float*)d_in[8];
    const float* bk  = (const float*)d_in[9];
    const float* Wak = (const float*)d_in[10];
    const float* bak = (const float*)d_in[11];
    const float* Wo  = (const float*)d_in[12];
    const float* bo  = (const float*)d_in[13];
    float* out = (float*)d_out;

    float *q_, *kc_, *sc_, *sq_, *sk_;
    cudaGetSymbolAddress((void**)&q_,  g_query);
    cudaGetSymbolAddress((void**)&kc_, g_kc);
    cudaGetSymbolAddress((void**)&sc_, g_scores);
    cudaGetSymbolAddress((void**)&sq_, g_scale_q);
    cudaGetSymbolAddress((void**)&sk_, g_scale_k);

    const dim3 gemmGrid(E_ / 128, M_ / 128);  // (4, 256)

    // 1) query = x @ Wq + bq
    sgemm_kernel<false, false, false><<<gemmGrid, 256>>>(x, Wq, bq, q_, nullptr, nullptr, nullptr);
    // 2) q_scores = query @ Waq + baq
    scores_kernel<<<M_ / 8, 256>>>(q_, Waq, baq, sc_);
    // 3) q_flat = masked-softmax-pool(q_scores, query)
    pool_kernel<<<B_ * H_, 256>>>(sc_, q_, mask, sq_);
    // 4) key_content = (x @ Wk + bk) * q_flat[b,:]
    sgemm_kernel<false, true, false><<<gemmGrid, 256>>>(x, Wk, bk, kc_, nullptr, sq_, nullptr);
    // 5) k_scores = key_content @ Wak + bak
    scores_kernel<<<M_ / 8, 256>>>(kc_, Wak, bak, sc_);
    // 6) k_flat = masked-softmax-pool(k_scores, key_content)
    pool_kernel<<<B_ * H_, 256>>>(sc_, kc_, mask, sk_);
    // 7) out = (query * k_flat[b,:]) @ Wo + bo + query
    sgemm_kernel<true, false, true><<<gemmGrid, 256>>>(q_, Wo, bo, out, sk_, nullptr, q_);
}

// round 4
// speedup vs baseline: 1.9884x; 1.9884x over previous
#include <cuda_runtime.h>
#include <cuda_bf16.h>
#include <cstdint>
#include <cmath>

// Problem constants
#define B_ 8
#define T_ 4096
#define E_ 512
#define H_ 8
#define D_ 64
#define M_ (B_*T_)   // 32768

// ---------------------------------------------------------------------------
// Scratch (__device__ globals per allocation-free rule)
// ---------------------------------------------------------------------------
__device__ float g_query[(size_t)M_ * E_];           // 64 MB
__device__ float g_kc[(size_t)M_ * E_];              // 64 MB
__device__ float g_scores[(size_t)M_ * H_];          // 1 MB
__device__ float g_w[B_ * H_ * T_];                  // softmax weights, 1 MB
__device__ float g_partial[8 * B_ * H_ * D_];        // pool partials
__device__ float g_scale_q[B_ * E_];
__device__ float g_scale_k[B_ * E_];
__device__ __nv_bfloat16 g_ah[(size_t)M_ * E_];      // 32 MB  A hi
__device__ __nv_bfloat16 g_al[(size_t)M_ * E_];      // 32 MB  A lo
__device__ __nv_bfloat16 g_wqh[E_ * E_], g_wql[E_ * E_];   // W^T [N][K] bf16
__device__ __nv_bfloat16 g_wkh[E_ * E_];
__device__ __nv_bfloat16 g_woh[E_ * E_];

// ---------------------------------------------------------------------------
// HMMA helpers (PTX sm_80+, works on compute_103 virtual arch)
// ---------------------------------------------------------------------------
__device__ __forceinline__ uint32_t smem_u32(const void* p) {
    uint32_t a;
    asm("{ .reg .u64 t; cvta.to.shared.u64 t, %1; cvt.u32.u64 %0, t; }" : "=r"(a) : "l"(p));
    return a;
}
__device__ __forceinline__ void ldm_x4(uint32_t& r0, uint32_t& r1, uint32_t& r2, uint32_t& r3,
                                       uint32_t addr) {
    asm volatile("ldmatrix.sync.aligned.m8n8.x4.shared.b16 {%0,%1,%2,%3}, [%4];"
                 : "=r"(r0), "=r"(r1), "=r"(r2), "=r"(r3) : "r"(addr));
}
__device__ __forceinline__ void mma16816(float* c, const uint32_t* a, const uint32_t* b) {
    asm volatile(
        "mma.sync.aligned.m16n8k16.row.col.f32.bf16.bf16.f32 "
        "{%0,%1,%2,%3}, {%4,%5,%6,%7}, {%8,%9}, {%0,%1,%2,%3};"
        : "+f"(c[0]), "+f"(c[1]), "+f"(c[2]), "+f"(c[3])
        : "r"(a[0]), "r"(a[1]), "r"(a[2]), "r"(a[3]), "r"(b[0]), "r"(b[1]));
}

// ---------------------------------------------------------------------------
// HMMA GEMM: C[M,512] = sum_seg A_seg[M,512] @ Bt_seg^T + bias (+extras)
// Bt operands are pre-transposed [N][K] bf16 (K-major) -> mma row.col direct.
// Tile 128x128, BK=32, 8 warps (2x4), warp tile 64x32, double-buffered smem.
// ---------------------------------------------------------------------------
template<int NSEG, bool SCALE_C, bool ADD_C>
__global__ __launch_bounds__(256, 2)
void hmma_gemm(const __nv_bfloat16* __restrict__ A0, const __nv_bfloat16* __restrict__ A1,
               const __nv_bfloat16* __restrict__ A2,
               const __nv_bfloat16* __restrict__ Bt0, const __nv_bfloat16* __restrict__ Bt1,
               const __nv_bfloat16* __restrict__ Bt2,
               const float* __restrict__ bias, float* __restrict__ C,
               const float* __restrict__ cscale, const float* __restrict__ addend)
{
    constexpr int LDT = 40;  // padded smem stride in bf16 (80B -> conflict-free)
    __shared__ __align__(16) __nv_bfloat16 As[2][128 * LDT];
    __shared__ __align__(16) __nv_bfloat16 Bs[2][128 * LDT];

    const int tid  = threadIdx.x;
    const int wid  = tid >> 5;
    const int lane = tid & 31;
    const int wm   = wid & 1;          // 0..1 (M)
    const int wn   = wid >> 1;         // 0..3 (N)
    const int row0 = blockIdx.y * 128;
    const int col0 = blockIdx.x * 128;
    const int b    = row0 / T_;

    const __nv_bfloat16* aseg[3] = {A0, A1, A2};
    const __nv_bfloat16* bseg[3] = {Bt0, Bt1, Bt2};

    // tile loader mapping: thread -> (row, k-half)
    const int lrow  = tid & 127;
    const int lhalf = tid >> 7;        // 0/1 -> k offset 0/16

    float acc[4][4][4];
    #pragma unroll
    for (int i = 0; i < 4; i++)
        #pragma unroll
        for (int j = 0; j < 4; j++)
            #pragma unroll
            for (int u = 0; u < 4; u++) acc[i][j][u] = 0.f;

    constexpr int NIT = NSEG * 16;     // 512/32 iters per segment

    uint4 ar0, ar1, br0, br1;
    // preload iter 0
    {
        const __nv_bfloat16* ga = aseg[0] + (size_t)(row0 + lrow) * E_ + lhalf * 16;
        const __nv_bfloat16* gb = bseg[0] + (size_t)(col0 + lrow) * E_ + lhalf * 16;
        ar0 = reinterpret_cast<const uint4*>(ga)[0];
        ar1 = reinterpret_cast<const uint4*>(ga)[1];
        br0 = reinterpret_cast<const uint4*>(gb)[0];
        br1 = reinterpret_cast<const uint4*>(gb)[1];
        __nv_bfloat16* sa = &As[0][lrow * LDT + lhalf * 16];
        __nv_bfloat16* sb = &Bs[0][lrow * LDT + lhalf * 16];
        reinterpret_cast<uint4*>(sa)[0] = ar0;
        reinterpret_cast<uint4*>(sa)[1] = ar1;
        reinterpret_cast<uint4*>(sb)[0] = br0;
        reinterpret_cast<uint4*>(sb)[1] = br1;
    }
    __syncthreads();

    const int r   = lane & 7;
    const int sel = lane >> 3;

    for (int i = 0; i < NIT; i++) {
        const int buf = i & 1;
        if (i + 1 < NIT) {             // prefetch next tile into regs (LDG overlaps mma)
            const int seg = (i + 1) >> 4;
            const int k0  = ((i + 1) & 15) * 32;
            const __nv_bfloat16* ga = aseg[seg] + (size_t)(row0 + lrow) * E_ + k0 + lhalf * 16;
            const __nv_bfloat16* gb = bseg[seg] + (size_t)(col0 + lrow) * E_ + k0 + lhalf * 16;
            ar0 = reinterpret_cast<const uint4*>(ga)[0];
            ar1 = reinterpret_cast<const uint4*>(ga)[1];
            br0 = reinterpret_cast<const uint4*>(gb)[0];
            br1 = reinterpret_cast<const uint4*>(gb)[1];
        }

        const uint32_t abase = smem_u32(&As[buf][0]);
        const uint32_t bbase = smem_u32(&Bs[buf][0]);
        #pragma unroll
        for (int ks = 0; ks < 2; ks++) {
            const int k = ks * 16;
            uint32_t bfr[4][2];
            #pragma unroll
            for (int p = 0; p < 2; p++) {
                uint32_t addr = bbase +
                    (uint32_t)((wn * 32 + p * 16 + r + (sel >> 1) * 8) * LDT + k + (sel & 1) * 8) * 2;
                ldm_x4(bfr[2 * p][0], bfr[2 * p][1], bfr[2 * p + 1][0], bfr[2 * p + 1][1], addr);
            }
            #pragma unroll
            for (int mt = 0; mt < 4; mt++) {
                uint32_t af[4];
                uint32_t addr = abase +
                    (uint32_t)((wm * 64 + mt * 16 + r + (sel & 1) * 8) * LDT + k + (sel >> 1) * 8) * 2;
                ldm_x4(af[0], af[1], af[2], af[3], addr);
                #pragma unroll
                for (int nt = 0; nt < 4; nt++)
                    mma16816(acc[mt][nt], af, bfr[nt]);
            }
        }

        if (i + 1 < NIT) {
            // store prefetched tile to the other buffer (free since iter i-1) and sync
            const int nb = (i + 1) & 1;
            __nv_bfloat16* sa = &As[nb][lrow * LDT + lhalf * 16];
            __nv_bfloat16* sb = &Bs[nb][lrow * LDT + lhalf * 16];
            reinterpret_cast<uint4*>(sa)[0] = ar0;
            reinterpret_cast<uint4*>(sa)[1] = ar1;
            reinterpret_cast<uint4*>(sb)[0] = br0;
            reinterpret_cast<uint4*>(sb)[1] = br1;
            __syncthreads();
        }
    }

    // Epilogue: fragment layout c0,c1 -> (row=lane>>2, col=(lane&3)*2 +0/1); c2,c3 -> row+8
    #pragma unroll
    for (int mt = 0; mt < 4; mt++) {
        const int mg = row0 + wm * 64 + mt * 16 + (lane >> 2);
        #pragma unroll
        for (int nt = 0; nt < 4; nt++) {
            const int ng = col0 + wn * 32 + nt * 8 + (lane & 3) * 2;
            float s0 = 1.f, s1 = 1.f;
            if (SCALE_C) { s0 = cscale[b * E_ + ng]; s1 = cscale[b * E_ + ng + 1]; }
            const float bi0 = bias[ng], bi1 = bias[ng + 1];
            float v0 = acc[mt][nt][0] * s0 + bi0;
            float v1 = acc[mt][nt][1] * s1 + bi1;
            float v2 = acc[mt][nt][2] * s0 + bi0;
            float v3 = acc[mt][nt][3] * s1 + bi1;
            if (ADD_C) {
                v0 += addend[(size_t)mg * E_ + ng];
                v1 += addend[(size_t)mg * E_ + ng + 1];
                v2 += addend[(size_t)(mg + 8) * E_ + ng];
                v3 += addend[(size_t)(mg + 8) * E_ + ng + 1];
            }
            *reinterpret_cast<float2*>(C + (size_t)mg * E_ + ng)       = make_float2(v0, v1);
            *reinterpret_cast<float2*>(C + (size_t)(mg + 8) * E_ + ng) = make_float2(v2, v3);
        }
    }
}

// ---------------------------------------------------------------------------
// fp32 -> bf16 hi(/lo) split, optional per-(b,k) scale
// ---------------------------------------------------------------------------
template<bool LO, bool SCALED>
__global__ __launch_bounds__(256)
void split_kernel(const float* __restrict__ in, __nv_bfloat16* __restrict__ hi,
                  __nv_bfloat16* __restrict__ lo, const float* __restrict__ scale)
{
    const size_t i = (size_t)blockIdx.x * 256 + threadIdx.x;   // float4 index
    float4 v = reinterpret_cast<const float4*>(in)[i];
    if (SCALED) {
        const size_t e0 = i * 4;
        const int k  = (int)(e0 & (E_ - 1));
        const int bb = (int)(e0 >> 21);
        float4 s = *reinterpret_cast<const float4*>(scale + bb * E_ + k);
        v.x *= s.x; v.y *= s.y; v.z *= s.z; v.w *= s.w;
    }
    __nv_bfloat16 h0 = __float2bfloat16(v.x), h1 = __float2bfloat16(v.y);
    __nv_bfloat16 h2 = __float2bfloat16(v.z), h3 = __float2bfloat16(v.w);
    __nv_bfloat162* hp = reinterpret_cast<__nv_bfloat162*>(hi) + 2 * i;
    hp[0] = __nv_bfloat162(h0, h1); hp[1] = __nv_bfloat162(h2, h3);
    if (LO) {
        __nv_bfloat16 l0 = __float2bfloat16(v.x - __bfloat162float(h0));
        __nv_bfloat16 l1 = __float2bfloat16(v.y - __bfloat162float(h1));
        __nv_bfloat16 l2 = __float2bfloat16(v.z - __bfloat162float(h2));
        __nv_bfloat16 l3 = __float2bfloat16(v.w - __bfloat162float(h3));
        __nv_bfloat162* lp = reinterpret_cast<__nv_bfloat162*>(lo) + 2 * i;
        lp[0] = __nv_bfloat162(l0, l1); lp[1] = __nv_bfloat162(l2, l3);
    }
}

// W[k][n] (512x512) -> W^T hi(/lo) [n][k]
template<bool LO>
__global__ __launch_bounds__(256)
void wsplit_kernel(const float* __restrict__ W, __nv_bfloat16* __restrict__ hi,
                   __nv_bfloat16* __restrict__ lo)
{
    const int idx = blockIdx.x * 256 + threadIdx.x;   // = n*512 + k
    const int n = idx >> 9, k = idx & 511;
    const float v = W[k * E_ + n];
    const __nv_bfloat16 h = __float2bfloat16(v);
    hi[idx] = h;
    if (LO) lo[idx] = __float2bfloat16(v - __bfloat162float(h));
}

// ---------------------------------------------------------------------------
// scores[m,h] = dot(X[m,:], Wa[:,h]) + ba[h]
// ---------------------------------------------------------------------------
__global__ __launch_bounds__(256)
void scores_kernel(const float* __restrict__ X, const float* __restrict__ Wa,
                   const float* __restrict__ ba, float* __restrict__ S)
{
    __shared__ float wT[H_][E_];
    __shared__ float bsh[H_];
    const int tid = threadIdx.x;
    for (int i = tid; i < E_ * H_; i += 256) wT[i & (H_ - 1)][i >> 3] = Wa[i];
    if (tid < H_) bsh[tid] = ba[tid];
    __syncthreads();

    const int warp = tid >> 5, lane = tid & 31;
    const int m = blockIdx.x * 8 + warp;
    const float* xr = X + (size_t)m * E_;

    float s[H_] = {0.f, 0.f, 0.f, 0.f, 0.f, 0.f, 0.f, 0.f};
    for (int e = lane; e < E_; e += 32) {
        const float xv = xr[e];
        #pragma unroll
        for (int h = 0; h < H_; h++) s[h] = fmaf(xv, wT[h][e], s[h]);
    }
    #pragma unroll
    for (int off = 16; off; off >>= 1)
        #pragma unroll
        for (int h = 0; h < H_; h++) s[h] += __shfl_xor_sync(0xffffffffu, s[h], off);
    if (lane < H_) S[(size_t)m * H_ + lane] = s[lane] + bsh[lane];
}

// ---------------------------------------------------------------------------
// softmax weights per (b,h): w[bh*T+t] = softmax_t(mask(scores*0.125))
// ---------------------------------------------------------------------------
__global__ __launch_bounds__(256)
void softmax_kernel(const float* __restrict__ S, const unsigned char* __restrict__ mask,
                    float* __restrict__ w)
{
    const int bh = blockIdx.x;
    const int b = bh >> 3, h = bh & 7;
    __shared__ float buf[T_];
    __shared__ float red[256];
    const int tid = threadIdx.x;

    float mx = -INFINITY;
    for (int t = tid; t < T_; t += 256) {
        float s = S[((size_t)b * T_ + t) * H_ + h] * 0.125f;
        if (mask[b * T_ + t]) s = -INFINITY;
        buf[t] = s;
        mx = fmaxf(mx, s);
    }
    red[tid] = mx; __syncthreads();
    #pragma unroll
    for (int s2 = 128; s2 > 0; s2 >>= 1) {
        if (tid < s2) red[tid] = fmaxf(red[tid], red[tid + s2]);
        __syncthreads();
    }
    mx = red[0];
    __syncthreads();

    float sum = 0.f;
    for (int t = tid; t < T_; t += 256) {
        const float e = expf(buf[t] - mx);
        buf[t] = e;
        sum += e;
    }
    red[tid] = sum; __syncthreads();
    #pragma unroll
    for (int s2 = 128; s2 > 0; s2 >>= 1) {
        if (tid < s2) red[tid] += red[tid + s2];
        __syncthreads();
    }
    const float inv = 1.f / red[0];
    __syncthreads();
    for (int t = tid; t < T_; t += 256) w[(size_t)bh * T_ + t] = buf[t] * inv;
}

// Partial pooling: grid (8 chunks, 64 bh). partial[chunk][bh][d] = sum over 512 t.
__global__ __launch_bounds__(256)
void pool_partial_kernel(const float* __restrict__ w, const float* __restrict__ content,
                         float* __restrict__ partial)
{
    const int bh = blockIdx.y;
    const int b = bh >> 3, h = bh & 7;
    const int t0 = blockIdx.x * 512;
    const int tid = threadIdx.x;
    const int d = tid & 63, g = tid >> 6;
    __shared__ float red[256];

    const float* cp = content + (size_t)b * T_ * E_ + h * D_ + d;
    const float* wp = w + (size_t)bh * T_;
    float acc = 0.f;
    for (int t = t0 + g; t < t0 + 512; t += 4)
        acc = fmaf(wp[t], cp[(size_t)t * E_], acc);
    red[tid] = acc; __syncthreads();
    if (tid < 64)
        partial[((size_t)blockIdx.x * 64 + bh) * 64 + d] =
            red[tid] + red[tid + 64] + red[tid + 128] + red[tid + 192];
}

// Deterministic reduce: out[b*E + h*64 + d] = sum_c partial[c][bh][d]
__global__ __launch_bounds__(64)
void pool_reduce_kernel(const float* __restrict__ partial, float* __restrict__ out)
{
    const int bh = blockIdx.x;
    const int b = bh >> 3, h = bh & 7;
    const int d = threadIdx.x;
    float acc = 0.f;
    #pragma unroll
    for (int c = 0; c < 8; c++) acc += partial[((size_t)c * 64 + bh) * 64 + d];
    out[b * E_ + h * D_ + d] = acc;
}

// ---------------------------------------------------------------------------
// Launch sequence
// ---------------------------------------------------------------------------
extern "C" void kernel_launch(void* const* d_in, const int* in_sizes, int n_in,
                              void* d_out, int out_size)
{
    const float* x            = (const float*)d_in[0];
    const unsigned char* mask = (const unsigned char*)d_in[3];
    const float* Wq  = (const float*)d_in[4];
    const float* bq  = (const float*)d_in[5];
    const float* Waq = (const float*)d_in[6];
    const float* baq = (const float*)d_in[7];
    const float* Wk  = (const float*)d_in[8];
    const float* bk  = (const float*)d_in[9];
    const float* Wak = (const float*)d_in[10];
    const float* bak = (const float*)d_in[11];
    const float* Wo  = (const float*)d_in[12];
    const float* bo  = (const float*)d_in[13];
    float* out = (float*)d_out;

    float *q_, *kc_, *sc_, *w_, *pp_, *sq_, *sk_;
    __nv_bfloat16 *ah, *al, *wqh, *wql, *wkh, *woh;
    cudaGetSymbolAddress((void**)&q_,  g_query);
    cudaGetSymbolAddress((void**)&kc_, g_kc);
    cudaGetSymbolAddress((void**)&sc_, g_scores);
    cudaGetSymbolAddress((void**)&w_,  g_w);
    cudaGetSymbolAddress((void**)&pp_, g_partial);
    cudaGetSymbolAddress((void**)&sq_, g_scale_q);
    cudaGetSymbolAddress((void**)&sk_, g_scale_k);
    cudaGetSymbolAddress((void**)&ah,  g_ah);
    cudaGetSymbolAddress((void**)&al,  g_al);
    cudaGetSymbolAddress((void**)&wqh, g_wqh);
    cudaGetSymbolAddress((void**)&wql, g_wql);
    cudaGetSymbolAddress((void**)&wkh, g_wkh);
    cudaGetSymbolAddress((void**)&woh, g_woh);

    const dim3 gemmGrid(E_ / 128, M_ / 128);            // (4, 256)
    const int splitBlocks  = (M_ * E_ / 4) / 256;       // 16384
    const int wsplitBlocks = (E_ * E_) / 256;           // 1024
    const dim3 poolGrid(8, 64);

    // Conversions
    split_kernel<true, false><<<splitBlocks, 256>>>(x, ah, al, nullptr);
    wsplit_kernel<true ><<<wsplitBlocks, 256>>>(Wq, wqh, wql);
    wsplit_kernel<false><<<wsplitBlocks, 256>>>(Wk, wkh, nullptr);
    wsplit_kernel<false><<<wsplitBlocks, 256>>>(Wo, woh, nullptr);

    // 1) query = x @ Wq + bq   (3-term hi/lo split for precision)
    hmma_gemm<3, false, false><<<gemmGrid, 256>>>(ah, al, ah, wqh, wqh, wql,
                                                  bq, q_, nullptr, nullptr);
    // 2-3) q path
    scores_kernel<<<M_ / 8, 256>>>(q_, Waq, baq, sc_);
    softmax_kernel<<<B_ * H_, 256>>>(sc_, mask, w_);
    pool_partial_kernel<<<poolGrid, 256>>>(w_, q_, pp_);
    pool_reduce_kernel<<<B_ * H_, 64>>>(pp_, sq_);
    // 4) key_content = (x @ Wk + bk) * q_flat   (single bf16 pass)
    hmma_gemm<1, true, false><<<gemmGrid, 256>>>(ah, nullptr, nullptr, wkh, nullptr, nullptr,
                                                 bk, kc_, sq_, nullptr);
    // 5-6) k path
    scores_kernel<<<M_ / 8, 256>>>(kc_, Wak, bak, sc_);
    softmax_kernel<<<B_ * H_, 256>>>(sc_, mask, w_);
    pool_partial_kernel<<<poolGrid, 256>>>(w_, kc_, pp_);
    pool_reduce_kernel<<<B_ * H_, 64>>>(pp_, sk_);
    // 7) out = (query * k_flat) @ Wo + bo + query   (single bf16 pass)
    split_kernel<false, true><<<splitBlocks, 256>>>(q_, ah, nullptr, sk_);
    hmma_gemm<1, false, true><<<gemmGrid, 256>>>(ah, nullptr, nullptr, woh, nullptr, nullptr,
                                                 bo, out, nullptr, q_);
}

// round 5
// speedup vs baseline: 2.2467x; 1.1299x over previous
#include <cuda_runtime.h>
#include <cuda_fp16.h>
#include <cstdint>
#include <cmath>

// Problem constants
#define B_ 8
#define T_ 4096
#define E_ 512
#define H_ 8
#define D_ 64
#define M_ (B_*T_)   // 32768

// ---------------------------------------------------------------------------
// Scratch (__device__ globals per allocation-free rule)
// ---------------------------------------------------------------------------
__device__ float g_query[(size_t)M_ * E_];           // 64 MB
__device__ float g_kc[(size_t)M_ * E_];              // 64 MB
__device__ float g_scores[(size_t)M_ * H_];          // 1 MB
__device__ float g_w[B_ * H_ * T_];                  // softmax weights, 1 MB
__device__ float g_partial[8 * B_ * H_ * D_];        // pool partials
__device__ float g_scale_q[B_ * E_];
__device__ float g_scale_k[B_ * E_];
__device__ __half g_ah[(size_t)M_ * E_];             // 32 MB  A hi (fp16)
__device__ __half g_al[(size_t)M_ * E_];             // 32 MB  A lo (fp16)
__device__ __half g_wqh[E_ * E_];                    // W^T [N][K] fp16
__device__ __half g_wkh[E_ * E_];
__device__ __half g_woh[E_ * E_];

// ---------------------------------------------------------------------------
// HMMA helpers (PTX sm_80+, works on compute_103 virtual arch)
// ---------------------------------------------------------------------------
__device__ __forceinline__ uint32_t smem_u32(const void* p) {
    uint32_t a;
    asm("{ .reg .u64 t; cvta.to.shared.u64 t, %1; cvt.u32.u64 %0, t; }" : "=r"(a) : "l"(p));
    return a;
}
__device__ __forceinline__ void ldm_x4(uint32_t& r0, uint32_t& r1, uint32_t& r2, uint32_t& r3,
                                       uint32_t addr) {
    asm volatile("ldmatrix.sync.aligned.m8n8.x4.shared.b16 {%0,%1,%2,%3}, [%4];"
                 : "=r"(r0), "=r"(r1), "=r"(r2), "=r"(r3) : "r"(addr));
}
__device__ __forceinline__ void mma16816(float* c, const uint32_t* a, const uint32_t* b) {
    asm volatile(
        "mma.sync.aligned.m16n8k16.row.col.f32.f16.f16.f32 "
        "{%0,%1,%2,%3}, {%4,%5,%6,%7}, {%8,%9}, {%0,%1,%2,%3};"
        : "+f"(c[0]), "+f"(c[1]), "+f"(c[2]), "+f"(c[3])
        : "r"(a[0]), "r"(a[1]), "r"(a[2]), "r"(a[3]), "r"(b[0]), "r"(b[1]));
}

// ---------------------------------------------------------------------------
// HMMA GEMM: C[M,512] = sum_seg A_seg[M,512] @ Bt_seg^T + bias (+extras)
// Bt operands are pre-transposed [N][K] fp16 (K-major) -> mma row.col direct.
// Tile 128x128, BK=32, 8 warps (2x4), warp tile 64x32, double-buffered smem.
// ---------------------------------------------------------------------------
template<int NSEG, bool SCALE_C, bool ADD_C>
__global__ __launch_bounds__(256, 2)
void hmma_gemm(const __half* __restrict__ A0, const __half* __restrict__ A1,
               const __half* __restrict__ Bt0, const __half* __restrict__ Bt1,
               const float* __restrict__ bias, float* __restrict__ C,
               const float* __restrict__ cscale, const float* __restrict__ addend)
{
    constexpr int LDT = 40;  // padded smem stride in halves (80B -> conflict-free)
    __shared__ __align__(16) __half As[2][128 * LDT];
    __shared__ __align__(16) __half Bs[2][128 * LDT];

    const int tid  = threadIdx.x;
    const int wid  = tid >> 5;
    const int lane = tid & 31;
    const int wm   = wid & 1;          // 0..1 (M)
    const int wn   = wid >> 1;         // 0..3 (N)
    const int row0 = blockIdx.y * 128;
    const int col0 = blockIdx.x * 128;
    const int b    = row0 / T_;

    const __half* aseg[2] = {A0, A1};
    const __half* bseg[2] = {Bt0, Bt1};

    // tile loader mapping: thread -> (row, k-half)
    const int lrow  = tid & 127;
    const int lhalf = tid >> 7;        // 0/1 -> k offset 0/16

    float acc[4][4][4];
    #pragma unroll
    for (int i = 0; i < 4; i++)
        #pragma unroll
        for (int j = 0; j < 4; j++)
            #pragma unroll
            for (int u = 0; u < 4; u++) acc[i][j][u] = 0.f;

    constexpr int NIT = NSEG * 16;     // 512/32 iters per segment

    uint4 ar0, ar1, br0, br1;
    // preload iter 0
    {
        const __half* ga = aseg[0] + (size_t)(row0 + lrow) * E_ + lhalf * 16;
        const __half* gb = bseg[0] + (size_t)(col0 + lrow) * E_ + lhalf * 16;
        ar0 = reinterpret_cast<const uint4*>(ga)[0];
        ar1 = reinterpret_cast<const uint4*>(ga)[1];
        br0 = reinterpret_cast<const uint4*>(gb)[0];
        br1 = reinterpret_cast<const uint4*>(gb)[1];
        __half* sa = &As[0][lrow * LDT + lhalf * 16];
        __half* sb = &Bs[0][lrow * LDT + lhalf * 16];
        reinterpret_cast<uint4*>(sa)[0] = ar0;
        reinterpret_cast<uint4*>(sa)[1] = ar1;
        reinterpret_cast<uint4*>(sb)[0] = br0;
        reinterpret_cast<uint4*>(sb)[1] = br1;
    }
    __syncthreads();

    const int r   = lane & 7;
    const int sel = lane >> 3;

    for (int i = 0; i < NIT; i++) {
        const int buf = i & 1;
        if (i + 1 < NIT) {             // prefetch next tile into regs (LDG overlaps mma)
            const int seg = (i + 1) >> 4;
            const int k0  = ((i + 1) & 15) * 32;
            const __half* ga = aseg[seg] + (size_t)(row0 + lrow) * E_ + k0 + lhalf * 16;
            const __half* gb = bseg[seg] + (size_t)(col0 + lrow) * E_ + k0 + lhalf * 16;
            ar0 = reinterpret_cast<const uint4*>(ga)[0];
            ar1 = reinterpret_cast<const uint4*>(ga)[1];
            br0 = reinterpret_cast<const uint4*>(gb)[0];
            br1 = reinterpret_cast<const uint4*>(gb)[1];
        }

        const uint32_t abase = smem_u32(&As[buf][0]);
        const uint32_t bbase = smem_u32(&Bs[buf][0]);
        #pragma unroll
        for (int ks = 0; ks < 2; ks++) {
            const int k = ks * 16;
            uint32_t bfr[4][2];
            #pragma unroll
            for (int p = 0; p < 2; p++) {
                uint32_t addr = bbase +
                    (uint32_t)((wn * 32 + p * 16 + r + (sel >> 1) * 8) * LDT + k + (sel & 1) * 8) * 2;
                ldm_x4(bfr[2 * p][0], bfr[2 * p][1], bfr[2 * p + 1][0], bfr[2 * p + 1][1], addr);
            }
            #pragma unroll
            for (int mt = 0; mt < 4; mt++) {
                uint32_t af[4];
                uint32_t addr = abase +
                    (uint32_t)((wm * 64 + mt * 16 + r + (sel & 1) * 8) * LDT + k + (sel >> 1) * 8) * 2;
                ldm_x4(af[0], af[1], af[2], af[3], addr);
                #pragma unroll
                for (int nt = 0; nt < 4; nt++)
                    mma16816(acc[mt][nt], af, bfr[nt]);
            }
        }

        if (i + 1 < NIT) {
            const int nb = (i + 1) & 1;
            __half* sa = &As[nb][lrow * LDT + lhalf * 16];
            __half* sb = &Bs[nb][lrow * LDT + lhalf * 16];
            reinterpret_cast<uint4*>(sa)[0] = ar0;
            reinterpret_cast<uint4*>(sa)[1] = ar1;
            reinterpret_cast<uint4*>(sb)[0] = br0;
            reinterpret_cast<uint4*>(sb)[1] = br1;
            __syncthreads();
        }
    }

    // Epilogue
    #pragma unroll
    for (int mt = 0; mt < 4; mt++) {
        const int mg = row0 + wm * 64 + mt * 16 + (lane >> 2);
        #pragma unroll
        for (int nt = 0; nt < 4; nt++) {
            const int ng = col0 + wn * 32 + nt * 8 + (lane & 3) * 2;
            float s0 = 1.f, s1 = 1.f;
            if (SCALE_C) { s0 = cscale[b * E_ + ng]; s1 = cscale[b * E_ + ng + 1]; }
            const float bi0 = bias[ng], bi1 = bias[ng + 1];
            float v0 = acc[mt][nt][0] * s0 + bi0;
            float v1 = acc[mt][nt][1] * s1 + bi1;
            float v2 = acc[mt][nt][2] * s0 + bi0;
            float v3 = acc[mt][nt][3] * s1 + bi1;
            if (ADD_C) {
                v0 += addend[(size_t)mg * E_ + ng];
                v1 += addend[(size_t)mg * E_ + ng + 1];
                v2 += addend[(size_t)(mg + 8) * E_ + ng];
                v3 += addend[(size_t)(mg + 8) * E_ + ng + 1];
            }
            *reinterpret_cast<float2*>(C + (size_t)mg * E_ + ng)       = make_float2(v0, v1);
            *reinterpret_cast<float2*>(C + (size_t)(mg + 8) * E_ + ng) = make_float2(v2, v3);
        }
    }
}

// ---------------------------------------------------------------------------
// fp32 -> fp16 hi(/lo) split, optional per-(b,k) scale
// ---------------------------------------------------------------------------
template<bool LO, bool SCALED>
__global__ __launch_bounds__(256)
void split_kernel(const float* __restrict__ in, __half* __restrict__ hi,
                  __half* __restrict__ lo, const float* __restrict__ scale)
{
    const size_t i = (size_t)blockIdx.x * 256 + threadIdx.x;   // float4 index
    float4 v = reinterpret_cast<const float4*>(in)[i];
    if (SCALED) {
        const size_t e0 = i * 4;
        const int k  = (int)(e0 & (E_ - 1));
        const int bb = (int)(e0 >> 21);
        float4 s = *reinterpret_cast<const float4*>(scale + bb * E_ + k);
        v.x *= s.x; v.y *= s.y; v.z *= s.z; v.w *= s.w;
    }
    __half h0 = __float2half(v.x), h1 = __float2half(v.y);
    __half h2 = __float2half(v.z), h3 = __float2half(v.w);
    __half2* hp = reinterpret_cast<__half2*>(hi) + 2 * i;
    hp[0] = __half2(h0, h1); hp[1] = __half2(h2, h3);
    if (LO) {
        __half l0 = __float2half(v.x - __half2float(h0));
        __half l1 = __float2half(v.y - __half2float(h1));
        __half l2 = __float2half(v.z - __half2float(h2));
        __half l3 = __float2half(v.w - __half2float(h3));
        __half2* lp = reinterpret_cast<__half2*>(lo) + 2 * i;
        lp[0] = __half2(l0, l1); lp[1] = __half2(l2, l3);
    }
}

// W[k][n] (512x512) -> W^T hi [n][k] fp16
__global__ __launch_bounds__(256)
void wsplit_kernel(const float* __restrict__ W, __half* __restrict__ hi)
{
    const int idx = blockIdx.x * 256 + threadIdx.x;   // = n*512 + k
    const int n = idx >> 9, k = idx & 511;
    hi[idx] = __float2half(W[k * E_ + n]);
}

// ---------------------------------------------------------------------------
// scores[m,h] = dot(X[m,:], Wa[:,h]) + ba[h]
// ---------------------------------------------------------------------------
__global__ __launch_bounds__(256)
void scores_kernel(const float* __restrict__ X, const float* __restrict__ Wa,
                   const float* __restrict__ ba, float* __restrict__ S)
{
    __shared__ float wT[H_][E_];
    __shared__ float bsh[H_];
    const int tid = threadIdx.x;
    for (int i = tid; i < E_ * H_; i += 256) wT[i & (H_ - 1)][i >> 3] = Wa[i];
    if (tid < H_) bsh[tid] = ba[tid];
    __syncthreads();

    const int warp = tid >> 5, lane = tid & 31;
    const int m = blockIdx.x * 8 + warp;
    const float* xr = X + (size_t)m * E_;

    float s[H_] = {0.f, 0.f, 0.f, 0.f, 0.f, 0.f, 0.f, 0.f};
    for (int e = lane; e < E_; e += 32) {
        const float xv = xr[e];
        #pragma unroll
        for (int h = 0; h < H_; h++) s[h] = fmaf(xv, wT[h][e], s[h]);
    }
    #pragma unroll
    for (int off = 16; off; off >>= 1)
        #pragma unroll
        for (int h = 0; h < H_; h++) s[h] += __shfl_xor_sync(0xffffffffu, s[h], off);
    if (lane < H_) S[(size_t)m * H_ + lane] = s[lane] + bsh[lane];
}

// ---------------------------------------------------------------------------
// softmax weights per (b,h): w[bh*T+t] = softmax_t(mask(scores*0.125))
// ---------------------------------------------------------------------------
__global__ __launch_bounds__(256)
void softmax_kernel(const float* __restrict__ S, const unsigned char* __restrict__ mask,
                    float* __restrict__ w)
{
    const int bh = blockIdx.x;
    const int b = bh >> 3, h = bh & 7;
    __shared__ float buf[T_];
    __shared__ float red[256];
    const int tid = threadIdx.x;

    float mx = -INFINITY;
    for (int t = tid; t < T_; t += 256) {
        float s = S[((size_t)b * T_ + t) * H_ + h] * 0.125f;
        if (mask[b * T_ + t]) s = -INFINITY;
        buf[t] = s;
        mx = fmaxf(mx, s);
    }
    red[tid] = mx; __syncthreads();
    #pragma unroll
    for (int s2 = 128; s2 > 0; s2 >>= 1) {
        if (tid < s2) red[tid] = fmaxf(red[tid], red[tid + s2]);
        __syncthreads();
    }
    mx = red[0];
    __syncthreads();

    float sum = 0.f;
    for (int t = tid; t < T_; t += 256) {
        const float e = expf(buf[t] - mx);
        buf[t] = e;
        sum += e;
    }
    red[tid] = sum; __syncthreads();
    #pragma unroll
    for (int s2 = 128; s2 > 0; s2 >>= 1) {
        if (tid < s2) red[tid] += red[tid + s2];
        __syncthreads();
    }
    const float inv = 1.f / red[0];
    __syncthreads();
    for (int t = tid; t < T_; t += 256) w[(size_t)bh * T_ + t] = buf[t] * inv;
}

// Partial pooling: grid (8 chunks, 64 bh). partial[chunk][bh][d] = sum over 512 t.
__global__ __launch_bounds__(256)
void pool_partial_kernel(const float* __restrict__ w, const float* __restrict__ content,
                         float* __restrict__ partial)
{
    const int bh = blockIdx.y;
    const int b = bh >> 3, h = bh & 7;
    const int t0 = blockIdx.x * 512;
    const int tid = threadIdx.x;
    const int d = tid & 63, g = tid >> 6;
    __shared__ float red[256];

    const float* cp = content + (size_t)b * T_ * E_ + h * D_ + d;
    const float* wp = w + (size_t)bh * T_;
    float acc = 0.f;
    for (int t = t0 + g; t < t0 + 512; t += 4)
        acc = fmaf(wp[t], cp[(size_t)t * E_], acc);
    red[tid] = acc; __syncthreads();
    if (tid < 64)
        partial[((size_t)blockIdx.x * 64 + bh) * 64 + d] =
            red[tid] + red[tid + 64] + red[tid + 128] + red[tid + 192];
}

// Deterministic reduce: out[b*E + h*64 + d] = sum_c partial[c][bh][d]
__global__ __launch_bounds__(64)
void pool_reduce_kernel(const float* __restrict__ partial, float* __restrict__ out)
{
    const int bh = blockIdx.x;
    const int b = bh >> 3, h = bh & 7;
    const int d = threadIdx.x;
    float acc = 0.f;
    #pragma unroll
    for (int c = 0; c < 8; c++) acc += partial[((size_t)c * 64 + bh) * 64 + d];
    out[b * E_ + h * D_ + d] = acc;
}

// ---------------------------------------------------------------------------
// Launch sequence
// ---------------------------------------------------------------------------
extern "C" void kernel_launch(void* const* d_in, const int* in_sizes, int n_in,
                              void* d_out, int out_size)
{
    const float* x            = (const float*)d_in[0];
    const unsigned char* mask = (const unsigned char*)d_in[3];
    const float* Wq  = (const float*)d_in[4];
    const float* bq  = (const float*)d_in[5];
    const float* Waq = (const float*)d_in[6];
    const float* baq = (const float*)d_in[7];
    const float* Wk  = (const float*)d_in[8];
    const float* bk  = (const float*)d_in[9];
    const float* Wak = (const float*)d_in[10];
    const float* bak = (const float*)d_in[11];
    const float* Wo  = (const float*)d_in[12];
    const float* bo  = (const float*)d_in[13];
    float* out = (float*)d_out;

    float *q_, *kc_, *sc_, *w_, *pp_, *sq_, *sk_;
    __half *ah, *al, *wqh, *wkh, *woh;
    cudaGetSymbolAddress((void**)&q_,  g_query);
    cudaGetSymbolAddress((void**)&kc_, g_kc);
    cudaGetSymbolAddress((void**)&sc_, g_scores);
    cudaGetSymbolAddress((void**)&w_,  g_w);
    cudaGetSymbolAddress((void**)&pp_, g_partial);
    cudaGetSymbolAddress((void**)&sq_, g_scale_q);
    cudaGetSymbolAddress((void**)&sk_, g_scale_k);
    cudaGetSymbolAddress((void**)&ah,  g_ah);
    cudaGetSymbolAddress((void**)&al,  g_al);
    cudaGetSymbolAddress((void**)&wqh, g_wqh);
    cudaGetSymbolAddress((void**)&wkh, g_wkh);
    cudaGetSymbolAddress((void**)&woh, g_woh);

    const dim3 gemmGrid(E_ / 128, M_ / 128);            // (4, 256)
    const int splitBlocks  = (M_ * E_ / 4) / 256;       // 16384
    const int wsplitBlocks = (E_ * E_) / 256;           // 1024
    const dim3 poolGrid(8, 64);

    // Conversions
    split_kernel<true, false><<<splitBlocks, 256>>>(x, ah, al, nullptr);
    wsplit_kernel<<<wsplitBlocks, 256>>>(Wq, wqh);
    wsplit_kernel<<<wsplitBlocks, 256>>>(Wk, wkh);
    wsplit_kernel<<<wsplitBlocks, 256>>>(Wo, woh);

    // 1) query = x @ Wq + bq   (2-term fp16 split: Ah*Wh + Al*Wh)
    hmma_gemm<2, false, false><<<gemmGrid, 256>>>(ah, al, wqh, wqh,
                                                  bq, q_, nullptr, nullptr);
    // 2-3) q path
    scores_kernel<<<M_ / 8, 256>>>(q_, Waq, baq, sc_);
    softmax_kernel<<<B_ * H_, 256>>>(sc_, mask, w_);
    pool_partial_kernel<<<poolGrid, 256>>>(w_, q_, pp_);
    pool_reduce_kernel<<<B_ * H_, 64>>>(pp_, sq_);
    // 4) key_content = (x @ Wk + bk) * q_flat   (single fp16 pass)
    hmma_gemm<1, true, false><<<gemmGrid, 256>>>(ah, nullptr, wkh, nullptr,
                                                 bk, kc_, sq_, nullptr);
    // 5-6) k path
    scores_kernel<<<M_ / 8, 256>>>(kc_, Wak, bak, sc_);
    softmax_kernel<<<B_ * H_, 256>>>(sc_, mask, w_);
    pool_partial_kernel<<<poolGrid, 256>>>(w_, kc_, pp_);
    pool_reduce_kernel<<<B_ * H_, 64>>>(pp_, sk_);
    // 7) out = (query * k_flat) @ Wo + bo + query   (single fp16 pass)
    split_kernel<false, true><<<splitBlocks, 256>>>(q_, ah, nullptr, sk_);
    hmma_gemm<1, false, true><<<gemmGrid, 256>>>(ah, nullptr, woh, nullptr,
                                                 bo, out, nullptr, q_);
}

// round 6
// speedup vs baseline: 2.3782x; 1.0585x over previous
#include <cuda_runtime.h>
#include <cuda_fp16.h>
#include <cstdint>
#include <cmath>

// Problem constants
#define B_ 8
#define T_ 4096
#define E_ 512
#define H_ 8
#define D_ 64
#define M_ (B_*T_)   // 32768

// ---------------------------------------------------------------------------
// Scratch (__device__ globals per allocation-free rule)
// ---------------------------------------------------------------------------
__device__ float g_scores[(size_t)M_ * H_];          // 1 MB
__device__ float g_w[B_ * H_ * T_];                  // softmax weights, 1 MB
__device__ float g_partial[16 * B_ * H_ * E_];       // pool partials, 2 MB
__device__ float g_qf[B_ * E_];                      // q_flat
__device__ float g_kf[B_ * E_];                      // k_flat
__device__ float g_Cq[E_ * H_];                      // Wq@Waq
__device__ float g_cq[H_];
__device__ float g_Ck[B_ * E_ * H_];                 // per-batch Wk@diag(qf)@Wak
__device__ float g_ck[B_ * H_];
__device__ float g_cb[B_ * E_];                      // final bias per batch
__device__ __half g_ah[(size_t)M_ * E_];             // 32 MB  x hi (fp16)
__device__ __half g_al[(size_t)M_ * E_];             // 32 MB  x lo (fp16)
__device__ __half g_mt[B_ * E_ * E_];                // 4 MB   M^T per batch, fp16

// ---------------------------------------------------------------------------
// HMMA helpers
// ---------------------------------------------------------------------------
__device__ __forceinline__ uint32_t smem_u32(const void* p) {
    uint32_t a;
    asm("{ .reg .u64 t; cvta.to.shared.u64 t, %1; cvt.u32.u64 %0, t; }" : "=r"(a) : "l"(p));
    return a;
}
__device__ __forceinline__ void ldm_x4(uint32_t& r0, uint32_t& r1, uint32_t& r2, uint32_t& r3,
                                       uint32_t addr) {
    asm volatile("ldmatrix.sync.aligned.m8n8.x4.shared.b16 {%0,%1,%2,%3}, [%4];"
                 : "=r"(r0), "=r"(r1), "=r"(r2), "=r"(r3) : "r"(addr));
}
__device__ __forceinline__ void mma16816(float* c, const uint32_t* a, const uint32_t* b) {
    asm volatile(
        "mma.sync.aligned.m16n8k16.row.col.f32.f16.f16.f32 "
        "{%0,%1,%2,%3}, {%4,%5,%6,%7}, {%8,%9}, {%0,%1,%2,%3};"
        : "+f"(c[0]), "+f"(c[1]), "+f"(c[2]), "+f"(c[3])
        : "r"(a[0]), "r"(a[1]), "r"(a[2]), "r"(a[3]), "r"(b[0]), "r"(b[1]));
}

// ---------------------------------------------------------------------------
// Final HMMA GEMM: out[m,n] = sum_seg A_seg[m,:] @ Bt_b[n,:] + bias_b[n]
// Bt is per-batch [N][K] fp16 K-major. Tile 128x128, BK=32, 8 warps.
// ---------------------------------------------------------------------------
template<int NSEG>
__global__ __launch_bounds__(256, 2)
void hmma_gemm(const __half* __restrict__ A0, const __half* __restrict__ A1,
               const __half* __restrict__ Bt,
               const float* __restrict__ bias, float* __restrict__ C)
{
    constexpr int LDT = 40;
    __shared__ __align__(16) __half As[2][128 * LDT];
    __shared__ __align__(16) __half Bs[2][128 * LDT];

    const int tid  = threadIdx.x;
    const int wid  = tid >> 5;
    const int lane = tid & 31;
    const int wm   = wid & 1;
    const int wn   = wid >> 1;
    const int row0 = blockIdx.y * 128;
    const int col0 = blockIdx.x * 128;
    const int b    = row0 / T_;

    const __half* aseg[2] = {A0, A1};
    const __half* Btb = Bt + (size_t)b * E_ * E_;
    const float* bias_b = bias + b * E_;

    const int lrow  = tid & 127;
    const int lhalf = tid >> 7;

    float acc[4][4][4];
    #pragma unroll
    for (int i = 0; i < 4; i++)
        #pragma unroll
        for (int j = 0; j < 4; j++)
            #pragma unroll
            for (int u = 0; u < 4; u++) acc[i][j][u] = 0.f;

    constexpr int NIT = NSEG * 16;

    uint4 ar0, ar1, br0, br1;
    {
        const __half* ga = aseg[0] + (size_t)(row0 + lrow) * E_ + lhalf * 16;
        const __half* gb = Btb + (size_t)(col0 + lrow) * E_ + lhalf * 16;
        ar0 = reinterpret_cast<const uint4*>(ga)[0];
        ar1 = reinterpret_cast<const uint4*>(ga)[1];
        br0 = reinterpret_cast<const uint4*>(gb)[0];
        br1 = reinterpret_cast<const uint4*>(gb)[1];
        __half* sa = &As[0][lrow * LDT + lhalf * 16];
        __half* sb = &Bs[0][lrow * LDT + lhalf * 16];
        reinterpret_cast<uint4*>(sa)[0] = ar0;
        reinterpret_cast<uint4*>(sa)[1] = ar1;
        reinterpret_cast<uint4*>(sb)[0] = br0;
        reinterpret_cast<uint4*>(sb)[1] = br1;
    }
    __syncthreads();

    const int r   = lane & 7;
    const int sel = lane >> 3;

    for (int i = 0; i < NIT; i++) {
        const int buf = i & 1;
        if (i + 1 < NIT) {
            const int seg = (i + 1) >> 4;
            const int k0  = ((i + 1) & 15) * 32;
            const __half* ga = aseg[seg] + (size_t)(row0 + lrow) * E_ + k0 + lhalf * 16;
            const __half* gb = Btb + (size_t)(col0 + lrow) * E_ + ((i + 1) & 15) * 32 + lhalf * 16;
            ar0 = reinterpret_cast<const uint4*>(ga)[0];
            ar1 = reinterpret_cast<const uint4*>(ga)[1];
            br0 = reinterpret_cast<const uint4*>(gb)[0];
            br1 = reinterpret_cast<const uint4*>(gb)[1];
        }

        const uint32_t abase = smem_u32(&As[buf][0]);
        const uint32_t bbase = smem_u32(&Bs[buf][0]);
        #pragma unroll
        for (int ks = 0; ks < 2; ks++) {
            const int k = ks * 16;
            uint32_t bfr[4][2];
            #pragma unroll
            for (int p = 0; p < 2; p++) {
                uint32_t addr = bbase +
                    (uint32_t)((wn * 32 + p * 16 + r + (sel >> 1) * 8) * LDT + k + (sel & 1) * 8) * 2;
                ldm_x4(bfr[2 * p][0], bfr[2 * p][1], bfr[2 * p + 1][0], bfr[2 * p + 1][1], addr);
            }
            #pragma unroll
            for (int mt = 0; mt < 4; mt++) {
                uint32_t af[4];
                uint32_t addr = abase +
                    (uint32_t)((wm * 64 + mt * 16 + r + (sel & 1) * 8) * LDT + k + (sel >> 1) * 8) * 2;
                ldm_x4(af[0], af[1], af[2], af[3], addr);
                #pragma unroll
                for (int nt = 0; nt < 4; nt++)
                    mma16816(acc[mt][nt], af, bfr[nt]);
            }
        }

        if (i + 1 < NIT) {
            const int nb = (i + 1) & 1;
            __half* sa = &As[nb][lrow * LDT + lhalf * 16];
            __half* sb = &Bs[nb][lrow * LDT + lhalf * 16];
            reinterpret_cast<uint4*>(sa)[0] = ar0;
            reinterpret_cast<uint4*>(sa)[1] = ar1;
            reinterpret_cast<uint4*>(sb)[0] = br0;
            reinterpret_cast<uint4*>(sb)[1] = br1;
            __syncthreads();
        }
    }

    #pragma unroll
    for (int mt = 0; mt < 4; mt++) {
        const int mg = row0 + wm * 64 + mt * 16 + (lane >> 2);
        #pragma unroll
        for (int nt = 0; nt < 4; nt++) {
            const int ng = col0 + wn * 32 + nt * 8 + (lane & 3) * 2;
            const float bi0 = bias_b[ng], bi1 = bias_b[ng + 1];
            *reinterpret_cast<float2*>(C + (size_t)mg * E_ + ng) =
                make_float2(acc[mt][nt][0] + bi0, acc[mt][nt][1] + bi1);
            *reinterpret_cast<float2*>(C + (size_t)(mg + 8) * E_ + ng) =
                make_float2(acc[mt][nt][2] + bi0, acc[mt][nt][3] + bi1);
        }
    }
}

// ---------------------------------------------------------------------------
// C[bb][e1][h] = sum_e2 W[e1,e2] * s[e2] * Wa[e2,h]   (s = scale[bb,:] or 1)
// cv[bb][h]    = sum_e2 bvec[e2] * s[e2] * Wa[e2,h] + ba[h]
// ---------------------------------------------------------------------------
template<bool SCALED>
__global__ __launch_bounds__(256)
void cmat_kernel(const float* __restrict__ W, const float* __restrict__ Wa,
                 const float* __restrict__ bvec, const float* __restrict__ ba,
                 const float* __restrict__ scale,
                 float* __restrict__ C, float* __restrict__ cv)
{
    const int bb = blockIdx.y;
    __shared__ float s[E_][H_];
    const int tid = threadIdx.x;
    for (int i = tid; i < E_ * H_; i += 256) {
        const int e2 = i >> 3, h = i & 7;
        const float sc = SCALED ? scale[bb * E_ + e2] : 1.f;
        s[e2][h] = sc * Wa[i];
    }
    __syncthreads();
    const int e1 = blockIdx.x * 32 + (tid >> 3);
    const int h  = tid & 7;
    const float* wr = W + (size_t)e1 * E_;
    float acc = 0.f;
    for (int e2 = 0; e2 < E_; e2++) acc = fmaf(wr[e2], s[e2][h], acc);
    C[((size_t)bb * E_ + e1) * H_ + h] = acc;
    if (blockIdx.x == 0 && tid < H_) {
        float a = 0.f;
        for (int e2 = 0; e2 < E_; e2++) a = fmaf(bvec[e2], s[e2][tid], a);
        cv[bb * H_ + tid] = a + ba[tid];
    }
}

// ---------------------------------------------------------------------------
// Fused: split x -> fp16 hi/lo AND q_scores[m,h] = x[m,:]@Cq[:,h] + cq[h]
// One warp per row.
// ---------------------------------------------------------------------------
__global__ __launch_bounds__(256)
void split_scores_kernel(const float* __restrict__ x, __half* __restrict__ ah,
                         __half* __restrict__ al,
                         const float* __restrict__ Cq, const float* __restrict__ cq,
                         float* __restrict__ S)
{
    __shared__ float wT[H_][E_];
    __shared__ float bsh[H_];
    const int tid = threadIdx.x;
    for (int i = tid; i < E_ * H_; i += 256) wT[i & 7][i >> 3] = Cq[i];
    if (tid < H_) bsh[tid] = cq[tid];
    __syncthreads();

    const int warp = tid >> 5, lane = tid & 31;
    const int m = blockIdx.x * 8 + warp;
    const float4* xr = reinterpret_cast<const float4*>(x + (size_t)m * E_);

    float s[H_] = {0.f, 0.f, 0.f, 0.f, 0.f, 0.f, 0.f, 0.f};
    #pragma unroll
    for (int c = 0; c < 4; c++) {
        const int fi = c * 32 + lane;          // float4 index 0..127
        const float4 v = xr[fi];
        const int e = fi * 4;
        #pragma unroll
        for (int h = 0; h < H_; h++)
            s[h] += v.x * wT[h][e] + v.y * wT[h][e + 1] + v.z * wT[h][e + 2] + v.w * wT[h][e + 3];
        const __half h0 = __float2half(v.x), h1 = __float2half(v.y);
        const __half h2 = __float2half(v.z), h3 = __float2half(v.w);
        __half2* hp = reinterpret_cast<__half2*>(ah + (size_t)m * E_ + e);
        hp[0] = __half2(h0, h1); hp[1] = __half2(h2, h3);
        __half2* lp = reinterpret_cast<__half2*>(al + (size_t)m * E_ + e);
        lp[0] = __half2(__float2half(v.x - __half2float(h0)),
                        __float2half(v.y - __half2float(h1)));
        lp[1] = __half2(__float2half(v.z - __half2float(h2)),
                        __float2half(v.w - __half2float(h3)));
    }
    #pragma unroll
    for (int off = 16; off; off >>= 1)
        #pragma unroll
        for (int h = 0; h < H_; h++) s[h] += __shfl_xor_sync(0xffffffffu, s[h], off);
    if (lane < H_) S[(size_t)m * H_ + lane] = s[lane] + bsh[lane];
}

// Same but scores-only with per-batch C (k_scores)
__global__ __launch_bounds__(256)
void scores_pb_kernel(const float* __restrict__ x, const float* __restrict__ C,
                      const float* __restrict__ cv, float* __restrict__ S)
{
    const int b = blockIdx.x >> 9;           // (blockIdx.x*8)/4096
    __shared__ float wT[H_][E_];
    __shared__ float bsh[H_];
    const int tid = threadIdx.x;
    const float* Cb = C + (size_t)b * E_ * H_;
    for (int i = tid; i < E_ * H_; i += 256) wT[i & 7][i >> 3] = Cb[i];
    if (tid < H_) bsh[tid] = cv[b * H_ + tid];
    __syncthreads();

    const int warp = tid >> 5, lane = tid & 31;
    const int m = blockIdx.x * 8 + warp;
    const float4* xr = reinterpret_cast<const float4*>(x + (size_t)m * E_);

    float s[H_] = {0.f, 0.f, 0.f, 0.f, 0.f, 0.f, 0.f, 0.f};
    #pragma unroll
    for (int c = 0; c < 4; c++) {
        const int fi = c * 32 + lane;
        const float4 v = xr[fi];
        const int e = fi * 4;
        #pragma unroll
        for (int h = 0; h < H_; h++)
            s[h] += v.x * wT[h][e] + v.y * wT[h][e + 1] + v.z * wT[h][e + 2] + v.w * wT[h][e + 3];
    }
    #pragma unroll
    for (int off = 16; off; off >>= 1)
        #pragma unroll
        for (int h = 0; h < H_; h++) s[h] += __shfl_xor_sync(0xffffffffu, s[h], off);
    if (lane < H_) S[(size_t)m * H_ + lane] = s[lane] + bsh[lane];
}

// ---------------------------------------------------------------------------
// softmax weights per (b,h)
// ---------------------------------------------------------------------------
__global__ __launch_bounds__(256)
void softmax_kernel(const float* __restrict__ S, const unsigned char* __restrict__ mask,
                    float* __restrict__ w)
{
    const int bh = blockIdx.x;
    const int b = bh >> 3, h = bh & 7;
    __shared__ float buf[T_];
    __shared__ float red[256];
    const int tid = threadIdx.x;

    float mx = -INFINITY;
    for (int t = tid; t < T_; t += 256) {
        float s = S[((size_t)b * T_ + t) * H_ + h] * 0.125f;
        if (mask[b * T_ + t]) s = -INFINITY;
        buf[t] = s;
        mx = fmaxf(mx, s);
    }
    red[tid] = mx; __syncthreads();
    #pragma unroll
    for (int s2 = 128; s2 > 0; s2 >>= 1) {
        if (tid < s2) red[tid] = fmaxf(red[tid], red[tid + s2]);
        __syncthreads();
    }
    mx = red[0];
    __syncthreads();

    float sum = 0.f;
    for (int t = tid; t < T_; t += 256) {
        const float e = expf(buf[t] - mx);
        buf[t] = e;
        sum += e;
    }
    red[tid] = sum; __syncthreads();
    #pragma unroll
    for (int s2 = 128; s2 > 0; s2 >>= 1) {
        if (tid < s2) red[tid] += red[tid + s2];
        __syncthreads();
    }
    const float inv = 1.f / red[0];
    __syncthreads();
    for (int t = tid; t < T_; t += 256) w[(size_t)bh * T_ + t] = buf[t] * inv;
}

// ---------------------------------------------------------------------------
// pool x with all 8 head-weights at once: partial[chunk][b][h][e] over 256 t
// ---------------------------------------------------------------------------
__global__ __launch_bounds__(256)
void pool_x_kernel(const float* __restrict__ w, const float* __restrict__ x,
                   float* __restrict__ partial)
{
    const int chunk = blockIdx.x, b = blockIdx.y;
    __shared__ float ws[H_][256];
    const int tid = threadIdx.x;
    #pragma unroll
    for (int h = 0; h < H_; h++)
        ws[h][tid] = w[(size_t)(b * 8 + h) * T_ + chunk * 256 + tid];
    __syncthreads();

    float acc[H_][2];
    #pragma unroll
    for (int h = 0; h < H_; h++) { acc[h][0] = 0.f; acc[h][1] = 0.f; }

    const float* xp = x + (size_t)b * T_ * E_ + (size_t)chunk * 256 * E_;
    for (int tt = 0; tt < 256; tt++) {
        const float2 v = *reinterpret_cast<const float2*>(xp + (size_t)tt * E_ + tid * 2);
        #pragma unroll
        for (int h = 0; h < H_; h++) {
            acc[h][0] = fmaf(ws[h][tt], v.x, acc[h][0]);
            acc[h][1] = fmaf(ws[h][tt], v.y, acc[h][1]);
        }
    }
    #pragma unroll
    for (int h = 0; h < H_; h++) {
        float* pp = partial + (((size_t)chunk * 8 + b) * 8 + h) * E_ + tid * 2;
        pp[0] = acc[h][0]; pp[1] = acc[h][1];
    }
}

// ---------------------------------------------------------------------------
// flat: out[b, h*64+d] = (sum_c partial[c][b][h][:]) @ W[:, h*64+d] + bvec  (*qf)
// ---------------------------------------------------------------------------
template<bool MULQF>
__global__ __launch_bounds__(256)
void flat_kernel(const float* __restrict__ partial, const float* __restrict__ W,
                 const float* __restrict__ bvec, const float* __restrict__ qf_in,
                 float* __restrict__ out)
{
    const int b = blockIdx.x, h = blockIdx.y;
    __shared__ float px[E_];
    __shared__ float red[256];
    const int tid = threadIdx.x;
    for (int e = tid; e < E_; e += 256) {
        float a = 0.f;
        #pragma unroll
        for (int c = 0; c < 16; c++) a += partial[(((size_t)c * 8 + b) * 8 + h) * E_ + e];
        px[e] = a;
    }
    __syncthreads();
    const int d = tid & 63, q = tid >> 6;
    float acc = 0.f;
    for (int k = q * 128; k < q * 128 + 128; k++)
        acc = fmaf(px[k], W[(size_t)k * E_ + h * D_ + d], acc);
    red[tid] = acc; __syncthreads();
    if (tid < 64) {
        float v = red[tid] + red[tid + 64] + red[tid + 128] + red[tid + 192] + bvec[h * D_ + d];
        if (MULQF) v *= qf_in[b * E_ + h * D_ + d];
        out[b * E_ + h * D_ + d] = v;
    }
}

// ---------------------------------------------------------------------------
// buildM: mt[b][n][e1] = fp16( Wq[e1,n] + sum_e2 Wq[e1,e2]*kf[b,e2]*Wo[e2,n] )
// 64x64 tiles, K=512 over e2.
// ---------------------------------------------------------------------------
__global__ __launch_bounds__(256)
void buildM_kernel(const float* __restrict__ Wq, const float* __restrict__ Wo,
                   const float* __restrict__ kf, __half* __restrict__ mt)
{
    const int b  = blockIdx.z;
    const int n0 = blockIdx.x * 64, e0 = blockIdx.y * 64;
    __shared__ float wo_s[16][64];
    __shared__ float wq_s[64][17];
    const int tid = threadIdx.x;
    const int tn = (tid >> 4) << 2;
    const int te = (tid & 15) << 2;
    float acc[4][4];
    #pragma unroll
    for (int i = 0; i < 4; i++)
        #pragma unroll
        for (int j = 0; j < 4; j++) acc[i][j] = 0.f;

    for (int k0 = 0; k0 < E_; k0 += 16) {
        for (int i = tid; i < 1024; i += 256) {
            const int kk = i >> 6, nn = i & 63;
            wo_s[kk][nn] = Wo[(size_t)(k0 + kk) * E_ + n0 + nn] * kf[b * E_ + k0 + kk];
        }
        for (int i = tid; i < 1024; i += 256) {
            const int ee = i >> 4, kk = i & 15;
            wq_s[ee][kk] = Wq[(size_t)(e0 + ee) * E_ + k0 + kk];
        }
        __syncthreads();
        #pragma unroll
        for (int kk = 0; kk < 16; kk++) {
            float av[4], bv[4];
            #pragma unroll
            for (int i = 0; i < 4; i++) av[i] = wo_s[kk][tn + i];
            #pragma unroll
            for (int j = 0; j < 4; j++) bv[j] = wq_s[te + j][kk];
            #pragma unroll
            for (int i = 0; i < 4; i++)
                #pragma unroll
                for (int j = 0; j < 4; j++) acc[i][j] = fmaf(av[i], bv[j], acc[i][j]);
        }
        __syncthreads();
    }
    #pragma unroll
    for (int i = 0; i < 4; i++) {
        __half hv[4];
        #pragma unroll
        for (int j = 0; j < 4; j++)
            hv[j] = __float2half(acc[i][j] + Wq[(size_t)(e0 + te + j) * E_ + n0 + tn + i]);
        *reinterpret_cast<uint2*>(mt + (size_t)b * E_ * E_ + (size_t)(n0 + tn + i) * E_ + e0 + te) =
            *reinterpret_cast<uint2*>(hv);
    }
}

// cb[b][n] = sum_e bq[e]*kf[b,e]*Wo[e,n] + bo[n] + bq[n]
__global__ __launch_bounds__(128)
void cbias_kernel(const float* __restrict__ Wo, const float* __restrict__ bq,
                  const float* __restrict__ bo, const float* __restrict__ kf,
                  float* __restrict__ cb)
{
    const int b = blockIdx.y;
    const int n = blockIdx.x * 128 + threadIdx.x;
    float a = 0.f;
    for (int e = 0; e < E_; e++) a = fmaf(bq[e] * kf[b * E_ + e], Wo[(size_t)e * E_ + n], a);
    cb[b * E_ + n] = a + bo[n] + bq[n];
}

// ---------------------------------------------------------------------------
// Launch sequence
// ---------------------------------------------------------------------------
extern "C" void kernel_launch(void* const* d_in, const int* in_sizes, int n_in,
                              void* d_out, int out_size)
{
    const float* x            = (const float*)d_in[0];
    const unsigned char* mask = (const unsigned char*)d_in[3];
    const float* Wq  = (const float*)d_in[4];
    const float* bq  = (const float*)d_in[5];
    const float* Waq = (const float*)d_in[6];
    const float* baq = (const float*)d_in[7];
    const float* Wk  = (const float*)d_in[8];
    const float* bk  = (const float*)d_in[9];
    const float* Wak = (const float*)d_in[10];
    const float* bak = (const float*)d_in[11];
    const float* Wo  = (const float*)d_in[12];
    const float* bo  = (const float*)d_in[13];
    float* out = (float*)d_out;

    float *sc_, *w_, *pp_, *qf_, *kf_, *Cq_, *cq_, *Ck_, *ck_, *cb_;
    __half *ah, *al, *mt;
    cudaGetSymbolAddress((void**)&sc_, g_scores);
    cudaGetSymbolAddress((void**)&w_,  g_w);
    cudaGetSymbolAddress((void**)&pp_, g_partial);
    cudaGetSymbolAddress((void**)&qf_, g_qf);
    cudaGetSymbolAddress((void**)&kf_, g_kf);
    cudaGetSymbolAddress((void**)&Cq_, g_Cq);
    cudaGetSymbolAddress((void**)&cq_, g_cq);
    cudaGetSymbolAddress((void**)&Ck_, g_Ck);
    cudaGetSymbolAddress((void**)&ck_, g_ck);
    cudaGetSymbolAddress((void**)&cb_, g_cb);
    cudaGetSymbolAddress((void**)&ah,  g_ah);
    cudaGetSymbolAddress((void**)&al,  g_al);
    cudaGetSymbolAddress((void**)&mt,  g_mt);

    // 1) Cq = Wq@Waq (+ bias fold); fused split of x + q_scores
    cmat_kernel<false><<<dim3(16, 1), 256>>>(Wq, Waq, bq, baq, nullptr, Cq_, cq_);
    split_scores_kernel<<<M_ / 8, 256>>>(x, ah, al, Cq_, cq_, sc_);
    // 2) q softmax + pool x + q_flat
    softmax_kernel<<<B_ * H_, 256>>>(sc_, mask, w_);
    pool_x_kernel<<<dim3(16, B_), 256>>>(w_, x, pp_);
    flat_kernel<false><<<dim3(B_, H_), 256>>>(pp_, Wq, bq, nullptr, qf_);
    // 3) per-batch Ck; k_scores from x
    cmat_kernel<true><<<dim3(16, B_), 256>>>(Wk, Wak, bk, bak, qf_, Ck_, ck_);
    scores_pb_kernel<<<M_ / 8, 256>>>(x, Ck_, ck_, sc_);
    // 4) k softmax + pool x + k_flat
    softmax_kernel<<<B_ * H_, 256>>>(sc_, mask, w_);
    pool_x_kernel<<<dim3(16, B_), 256>>>(w_, x, pp_);
    flat_kernel<true><<<dim3(B_, H_), 256>>>(pp_, Wk, bk, qf_, kf_);
    // 5) per-batch M^T (fp16) + bias; final GEMM out = x @ M_b + cb_b
    buildM_kernel<<<dim3(8, 8, B_), 256>>>(Wq, Wo, kf_, mt);
    cbias_kernel<<<dim3(4, B_), 128>>>(Wo, bq, bo, kf_, cb_);
    hmma_gemm<2><<<dim3(E_ / 128, M_ / 128), 256>>>(ah, al, mt, cb_, out);
}

// round 7
// speedup vs baseline: 3.0270x; 1.2728x over previous
#include <cuda_runtime.h>
#include <cuda_fp16.h>
#include <cstdint>
#include <cmath>

// Problem constants
#define B_ 8
#define T_ 4096
#define E_ 512
#define H_ 8
#define D_ 64
#define M_ (B_*T_)   // 32768

#define NCHUNK 64    // pool chunks

// ---------------------------------------------------------------------------
// Scratch (__device__ globals per allocation-free rule)
// ---------------------------------------------------------------------------
__device__ float g_scores[(size_t)M_ * H_];          // 1 MB
__device__ float g_w[B_ * H_ * T_];                  // softmax weights, 1 MB
__device__ float g_partial[NCHUNK * B_ * H_ * E_];   // pool partials, 8 MB
__device__ float g_qf[B_ * E_];                      // q_flat
__device__ float g_kf[B_ * E_];                      // k_flat
__device__ float g_Cq[E_ * H_];                      // Wq@Waq
__device__ float g_cq[H_];
__device__ float g_Ck[B_ * E_ * H_];                 // per-batch Wk@diag(qf)@Wak
__device__ float g_ck[B_ * H_];
__device__ float g_cb[B_ * E_];                      // final bias per batch
__device__ __half g_ah[(size_t)M_ * E_];             // 32 MB  x hi (fp16)
__device__ __half g_al[(size_t)M_ * E_];             // 32 MB  x lo (fp16)
__device__ __half g_mt[B_ * E_ * E_];                // 4 MB   M^T per batch, fp16
__device__ __half g_wakt[B_ * E_ * E_];              // 4 MB   Wo^T*kf per batch, fp16
__device__ __half g_wqh[E_ * E_];                    // 0.5 MB Wq fp16 (row-major)

// ---------------------------------------------------------------------------
// HMMA helpers
// ---------------------------------------------------------------------------
__device__ __forceinline__ uint32_t smem_u32(const void* p) {
    uint32_t a;
    asm("{ .reg .u64 t; cvta.to.shared.u64 t, %1; cvt.u32.u64 %0, t; }" : "=r"(a) : "l"(p));
    return a;
}
__device__ __forceinline__ void ldm_x4(uint32_t& r0, uint32_t& r1, uint32_t& r2, uint32_t& r3,
                                       uint32_t addr) {
    asm volatile("ldmatrix.sync.aligned.m8n8.x4.shared.b16 {%0,%1,%2,%3}, [%4];"
                 : "=r"(r0), "=r"(r1), "=r"(r2), "=r"(r3) : "r"(addr));
}
__device__ __forceinline__ void mma16816(float* c, const uint32_t* a, const uint32_t* b) {
    asm volatile(
        "mma.sync.aligned.m16n8k16.row.col.f32.f16.f16.f32 "
        "{%0,%1,%2,%3}, {%4,%5,%6,%7}, {%8,%9}, {%0,%1,%2,%3};"
        : "+f"(c[0]), "+f"(c[1]), "+f"(c[2]), "+f"(c[3])
        : "r"(a[0]), "r"(a[1]), "r"(a[2]), "r"(a[3]), "r"(b[0]), "r"(b[1]));
}

// ---------------------------------------------------------------------------
// Final HMMA GEMM: out[m,n] = sum_seg A_seg[m,:] @ Bt_b[n,:] + bias_b[n]
// ---------------------------------------------------------------------------
template<int NSEG>
__global__ __launch_bounds__(256, 2)
void hmma_gemm(const __half* __restrict__ A0, const __half* __restrict__ A1,
               const __half* __restrict__ Bt,
               const float* __restrict__ bias, float* __restrict__ C)
{
    constexpr int LDT = 40;
    __shared__ __align__(16) __half As[2][128 * LDT];
    __shared__ __align__(16) __half Bs[2][128 * LDT];

    const int tid  = threadIdx.x;
    const int wid  = tid >> 5;
    const int lane = tid & 31;
    const int wm   = wid & 1;
    const int wn   = wid >> 1;
    const int row0 = blockIdx.y * 128;
    const int col0 = blockIdx.x * 128;
    const int b    = row0 / T_;

    const __half* aseg[2] = {A0, A1};
    const __half* Btb = Bt + (size_t)b * E_ * E_;
    const float* bias_b = bias + b * E_;

    const int lrow  = tid & 127;
    const int lhalf = tid >> 7;

    float acc[4][4][4];
    #pragma unroll
    for (int i = 0; i < 4; i++)
        #pragma unroll
        for (int j = 0; j < 4; j++)
            #pragma unroll
            for (int u = 0; u < 4; u++) acc[i][j][u] = 0.f;

    constexpr int NIT = NSEG * 16;

    uint4 ar0, ar1, br0, br1;
    {
        const __half* ga = aseg[0] + (size_t)(row0 + lrow) * E_ + lhalf * 16;
        const __half* gb = Btb + (size_t)(col0 + lrow) * E_ + lhalf * 16;
        ar0 = reinterpret_cast<const uint4*>(ga)[0];
        ar1 = reinterpret_cast<const uint4*>(ga)[1];
        br0 = reinterpret_cast<const uint4*>(gb)[0];
        br1 = reinterpret_cast<const uint4*>(gb)[1];
        __half* sa = &As[0][lrow * LDT + lhalf * 16];
        __half* sb = &Bs[0][lrow * LDT + lhalf * 16];
        reinterpret_cast<uint4*>(sa)[0] = ar0;
        reinterpret_cast<uint4*>(sa)[1] = ar1;
        reinterpret_cast<uint4*>(sb)[0] = br0;
        reinterpret_cast<uint4*>(sb)[1] = br1;
    }
    __syncthreads();

    const int r   = lane & 7;
    const int sel = lane >> 3;

    for (int i = 0; i < NIT; i++) {
        const int buf = i & 1;
        if (i + 1 < NIT) {
            const int seg = (i + 1) >> 4;
            const int k0  = ((i + 1) & 15) * 32;
            const __half* ga = aseg[seg] + (size_t)(row0 + lrow) * E_ + k0 + lhalf * 16;
            const __half* gb = Btb + (size_t)(col0 + lrow) * E_ + k0 + lhalf * 16;
            ar0 = reinterpret_cast<const uint4*>(ga)[0];
            ar1 = reinterpret_cast<const uint4*>(ga)[1];
            br0 = reinterpret_cast<const uint4*>(gb)[0];
            br1 = reinterpret_cast<const uint4*>(gb)[1];
        }

        const uint32_t abase = smem_u32(&As[buf][0]);
        const uint32_t bbase = smem_u32(&Bs[buf][0]);
        #pragma unroll
        for (int ks = 0; ks < 2; ks++) {
            const int k = ks * 16;
            uint32_t bfr[4][2];
            #pragma unroll
            for (int p = 0; p < 2; p++) {
                uint32_t addr = bbase +
                    (uint32_t)((wn * 32 + p * 16 + r + (sel >> 1) * 8) * LDT + k + (sel & 1) * 8) * 2;
                ldm_x4(bfr[2 * p][0], bfr[2 * p][1], bfr[2 * p + 1][0], bfr[2 * p + 1][1], addr);
            }
            #pragma unroll
            for (int mt = 0; mt < 4; mt++) {
                uint32_t af[4];
                uint32_t addr = abase +
                    (uint32_t)((wm * 64 + mt * 16 + r + (sel & 1) * 8) * LDT + k + (sel >> 1) * 8) * 2;
                ldm_x4(af[0], af[1], af[2], af[3], addr);
                #pragma unroll
                for (int nt = 0; nt < 4; nt++)
                    mma16816(acc[mt][nt], af, bfr[nt]);
            }
        }

        if (i + 1 < NIT) {
            const int nb = (i + 1) & 1;
            __half* sa = &As[nb][lrow * LDT + lhalf * 16];
            __half* sb = &Bs[nb][lrow * LDT + lhalf * 16];
            reinterpret_cast<uint4*>(sa)[0] = ar0;
            reinterpret_cast<uint4*>(sa)[1] = ar1;
            reinterpret_cast<uint4*>(sb)[0] = br0;
            reinterpret_cast<uint4*>(sb)[1] = br1;
            __syncthreads();
        }
    }

    #pragma unroll
    for (int mt = 0; mt < 4; mt++) {
        const int mg = row0 + wm * 64 + mt * 16 + (lane >> 2);
        #pragma unroll
        for (int nt = 0; nt < 4; nt++) {
            const int ng = col0 + wn * 32 + nt * 8 + (lane & 3) * 2;
            const float bi0 = bias_b[ng], bi1 = bias_b[ng + 1];
            *reinterpret_cast<float2*>(C + (size_t)mg * E_ + ng) =
                make_float2(acc[mt][nt][0] + bi0, acc[mt][nt][1] + bi1);
            *reinterpret_cast<float2*>(C + (size_t)(mg + 8) * E_ + ng) =
                make_float2(acc[mt][nt][2] + bi0, acc[mt][nt][3] + bi1);
        }
    }
}

// ---------------------------------------------------------------------------
// buildM HMMA: mt[m=b*512+n][e1] = fp16( sum_e2 wakt[m][e2]*wqh[e1][e2] + Wq[e1][n] )
// A = wakt (4096 x 512), Bt = wqh (shared across batches). Grid (4, 32).
// ---------------------------------------------------------------------------
__global__ __launch_bounds__(256, 2)
void hmma_buildM(const __half* __restrict__ A0, const __half* __restrict__ Bt,
                 const float* __restrict__ Wq, __half* __restrict__ Cmt)
{
    constexpr int LDT = 40;
    __shared__ __align__(16) __half As[2][128 * LDT];
    __shared__ __align__(16) __half Bs[2][128 * LDT];

    const int tid  = threadIdx.x;
    const int wid  = tid >> 5;
    const int lane = tid & 31;
    const int wm   = wid & 1;
    const int wn   = wid >> 1;
    const int row0 = blockIdx.y * 128;
    const int col0 = blockIdx.x * 128;

    const int lrow  = tid & 127;
    const int lhalf = tid >> 7;

    float acc[4][4][4];
    #pragma unroll
    for (int i = 0; i < 4; i++)
        #pragma unroll
        for (int j = 0; j < 4; j++)
            #pragma unroll
            for (int u = 0; u < 4; u++) acc[i][j][u] = 0.f;

    uint4 ar0, ar1, br0, br1;
    {
        const __half* ga = A0 + (size_t)(row0 + lrow) * E_ + lhalf * 16;
        const __half* gb = Bt + (size_t)(col0 + lrow) * E_ + lhalf * 16;
        ar0 = reinterpret_cast<const uint4*>(ga)[0];
        ar1 = reinterpret_cast<const uint4*>(ga)[1];
        br0 = reinterpret_cast<const uint4*>(gb)[0];
        br1 = reinterpret_cast<const uint4*>(gb)[1];
        __half* sa = &As[0][lrow * LDT + lhalf * 16];
        __half* sb = &Bs[0][lrow * LDT + lhalf * 16];
        reinterpret_cast<uint4*>(sa)[0] = ar0;
        reinterpret_cast<uint4*>(sa)[1] = ar1;
        reinterpret_cast<uint4*>(sb)[0] = br0;
        reinterpret_cast<uint4*>(sb)[1] = br1;
    }
    __syncthreads();

    const int r   = lane & 7;
    const int sel = lane >> 3;

    for (int i = 0; i < 16; i++) {
        const int buf = i & 1;
        if (i + 1 < 16) {
            const int k0 = (i + 1) * 32;
            const __half* ga = A0 + (size_t)(row0 + lrow) * E_ + k0 + lhalf * 16;
            const __half* gb = Bt + (size_t)(col0 + lrow) * E_ + k0 + lhalf * 16;
            ar0 = reinterpret_cast<const uint4*>(ga)[0];
            ar1 = reinterpret_cast<const uint4*>(ga)[1];
            br0 = reinterpret_cast<const uint4*>(gb)[0];
            br1 = reinterpret_cast<const uint4*>(gb)[1];
        }

        const uint32_t abase = smem_u32(&As[buf][0]);
        const uint32_t bbase = smem_u32(&Bs[buf][0]);
        #pragma unroll
        for (int ks = 0; ks < 2; ks++) {
            const int k = ks * 16;
            uint32_t bfr[4][2];
            #pragma unroll
            for (int p = 0; p < 2; p++) {
                uint32_t addr = bbase +
                    (uint32_t)((wn * 32 + p * 16 + r + (sel >> 1) * 8) * LDT + k + (sel & 1) * 8) * 2;
                ldm_x4(bfr[2 * p][0], bfr[2 * p][1], bfr[2 * p + 1][0], bfr[2 * p + 1][1], addr);
            }
            #pragma unroll
            for (int mt = 0; mt < 4; mt++) {
                uint32_t af[4];
                uint32_t addr = abase +
                    (uint32_t)((wm * 64 + mt * 16 + r + (sel & 1) * 8) * LDT + k + (sel >> 1) * 8) * 2;
                ldm_x4(af[0], af[1], af[2], af[3], addr);
                #pragma unroll
                for (int nt = 0; nt < 4; nt++)
                    mma16816(acc[mt][nt], af, bfr[nt]);
            }
        }

        if (i + 1 < 16) {
            const int nb = (i + 1) & 1;
            __half* sa = &As[nb][lrow * LDT + lhalf * 16];
            __half* sb = &Bs[nb][lrow * LDT + lhalf * 16];
            reinterpret_cast<uint4*>(sa)[0] = ar0;
            reinterpret_cast<uint4*>(sa)[1] = ar1;
            reinterpret_cast<uint4*>(sb)[0] = br0;
            reinterpret_cast<uint4*>(sb)[1] = br1;
            __syncthreads();
        }
    }

    // Epilogue: add Wq^T (Wq[e1][n], scattered fp32 reads, L2-resident) and store fp16
    #pragma unroll
    for (int mt = 0; mt < 4; mt++) {
        const int mg = row0 + wm * 64 + mt * 16 + (lane >> 2);
        const int n  = mg & 511;   // n within batch
        #pragma unroll
        for (int nt = 0; nt < 4; nt++) {
            const int ng = col0 + wn * 32 + nt * 8 + (lane & 3) * 2;   // e1
            float v0 = acc[mt][nt][0] + Wq[(size_t)ng * E_ + n];
            float v1 = acc[mt][nt][1] + Wq[(size_t)(ng + 1) * E_ + n];
            float v2 = acc[mt][nt][2] + Wq[(size_t)ng * E_ + n + 8];
            float v3 = acc[mt][nt][3] + Wq[(size_t)(ng + 1) * E_ + n + 8];
            *reinterpret_cast<__half2*>(Cmt + (size_t)mg * E_ + ng) =
                __half2(__float2half(v0), __float2half(v1));
            *reinterpret_cast<__half2*>(Cmt + (size_t)(mg + 8) * E_ + ng) =
                __half2(__float2half(v2), __float2half(v3));
        }
    }
}

// ---------------------------------------------------------------------------
// wakt[b*512+n][e2] = fp16( Wo[e2][n] * kf[b][e2] )  — tiled transpose
// grid (E/32, E/32, B), 256 threads
// ---------------------------------------------------------------------------
__global__ __launch_bounds__(256)
void woTkf_kernel(const float* __restrict__ Wo, const float* __restrict__ kf,
                  __half* __restrict__ wakt)
{
    __shared__ float t[32][33];
    const int n0 = blockIdx.x * 32, e20 = blockIdx.y * 32, b = blockIdx.z;
    const int tx = threadIdx.x & 31, ty = threadIdx.x >> 5;
    #pragma unroll
    for (int j = 0; j < 4; j++) {
        const int e2 = e20 + ty * 4 + j;
        t[ty * 4 + j][tx] = Wo[(size_t)e2 * E_ + n0 + tx] * kf[b * E_ + e2];
    }
    __syncthreads();
    #pragma unroll
    for (int j = 0; j < 4; j++) {
        const int n = n0 + ty * 4 + j;
        wakt[((size_t)b * E_ + n) * E_ + e20 + tx] = __float2half(t[tx][ty * 4 + j]);
    }
}

// wqh = fp16(Wq), row-major (k-major over e2)
__global__ __launch_bounds__(256)
void wq_conv_kernel(const float* __restrict__ Wq, __half* __restrict__ wqh)
{
    const int i = blockIdx.x * 256 + threadIdx.x;
    const float4 v = reinterpret_cast<const float4*>(Wq)[i];
    __half2* hp = reinterpret_cast<__half2*>(wqh) + 2 * i;
    hp[0] = __half2(__float2half(v.x), __float2half(v.y));
    hp[1] = __half2(__float2half(v.z), __float2half(v.w));
}

// ---------------------------------------------------------------------------
// C[bb][e1][h] = sum_e2 W[e1,e2] * s[e2] * Wa[e2,h]
// ---------------------------------------------------------------------------
template<bool SCALED>
__global__ __launch_bounds__(256)
void cmat_kernel(const float* __restrict__ W, const float* __restrict__ Wa,
                 const float* __restrict__ bvec, const float* __restrict__ ba,
                 const float* __restrict__ scale,
                 float* __restrict__ C, float* __restrict__ cv)
{
    const int bb = blockIdx.y;
    __shared__ float s[E_][H_];
    const int tid = threadIdx.x;
    for (int i = tid; i < E_ * H_; i += 256) {
        const int e2 = i >> 3, h = i & 7;
        const float sc = SCALED ? scale[bb * E_ + e2] : 1.f;
        s[e2][h] = sc * Wa[i];
    }
    __syncthreads();
    const int e1 = blockIdx.x * 32 + (tid >> 3);
    const int h  = tid & 7;
    const float* wr = W + (size_t)e1 * E_;
    float acc = 0.f;
    for (int e2 = 0; e2 < E_; e2++) acc = fmaf(wr[e2], s[e2][h], acc);
    C[((size_t)bb * E_ + e1) * H_ + h] = acc;
    if (blockIdx.x == 0 && tid < H_) {
        float a = 0.f;
        for (int e2 = 0; e2 < E_; e2++) a = fmaf(bvec[e2], s[e2][tid], a);
        cv[bb * H_ + tid] = a + ba[tid];
    }
}

// ---------------------------------------------------------------------------
// Fused: split x -> fp16 hi/lo AND q_scores = x@Cq + cq
// ---------------------------------------------------------------------------
__global__ __launch_bounds__(256)
void split_scores_kernel(const float* __restrict__ x, __half* __restrict__ ah,
                         __half* __restrict__ al,
                         const float* __restrict__ Cq, const float* __restrict__ cq,
                         float* __restrict__ S)
{
    __shared__ float wT[H_][E_];
    __shared__ float bsh[H_];
    const int tid = threadIdx.x;
    for (int i = tid; i < E_ * H_; i += 256) wT[i & 7][i >> 3] = Cq[i];
    if (tid < H_) bsh[tid] = cq[tid];
    __syncthreads();

    const int warp = tid >> 5, lane = tid & 31;
    const int m = blockIdx.x * 8 + warp;
    const float4* xr = reinterpret_cast<const float4*>(x + (size_t)m * E_);

    float s[H_] = {0.f, 0.f, 0.f, 0.f, 0.f, 0.f, 0.f, 0.f};
    #pragma unroll
    for (int c = 0; c < 4; c++) {
        const int fi = c * 32 + lane;
        const float4 v = xr[fi];
        const int e = fi * 4;
        #pragma unroll
        for (int h = 0; h < H_; h++)
            s[h] += v.x * wT[h][e] + v.y * wT[h][e + 1] + v.z * wT[h][e + 2] + v.w * wT[h][e + 3];
        const __half h0 = __float2half(v.x), h1 = __float2half(v.y);
        const __half h2 = __float2half(v.z), h3 = __float2half(v.w);
        __half2* hp = reinterpret_cast<__half2*>(ah + (size_t)m * E_ + e);
        hp[0] = __half2(h0, h1); hp[1] = __half2(h2, h3);
        __half2* lp = reinterpret_cast<__half2*>(al + (size_t)m * E_ + e);
        lp[0] = __half2(__float2half(v.x - __half2float(h0)),
                        __float2half(v.y - __half2float(h1)));
        lp[1] = __half2(__float2half(v.z - __half2float(h2)),
                        __float2half(v.w - __half2float(h3)));
    }
    #pragma unroll
    for (int off = 16; off; off >>= 1)
        #pragma unroll
        for (int h = 0; h < H_; h++) s[h] += __shfl_xor_sync(0xffffffffu, s[h], off);
    if (lane < H_) S[(size_t)m * H_ + lane] = s[lane] + bsh[lane];
}

// k_scores with per-batch C
__global__ __launch_bounds__(256)
void scores_pb_kernel(const float* __restrict__ x, const float* __restrict__ C,
                      const float* __restrict__ cv, float* __restrict__ S)
{
    const int b = blockIdx.x >> 9;
    __shared__ float wT[H_][E_];
    __shared__ float bsh[H_];
    const int tid = threadIdx.x;
    const float* Cb = C + (size_t)b * E_ * H_;
    for (int i = tid; i < E_ * H_; i += 256) wT[i & 7][i >> 3] = Cb[i];
    if (tid < H_) bsh[tid] = cv[b * H_ + tid];
    __syncthreads();

    const int warp = tid >> 5, lane = tid & 31;
    const int m = blockIdx.x * 8 + warp;
    const float4* xr = reinterpret_cast<const float4*>(x + (size_t)m * E_);

    float s[H_] = {0.f, 0.f, 0.f, 0.f, 0.f, 0.f, 0.f, 0.f};
    #pragma unroll
    for (int c = 0; c < 4; c++) {
        const int fi = c * 32 + lane;
        const float4 v = xr[fi];
        const int e = fi * 4;
        #pragma unroll
        for (int h = 0; h < H_; h++)
            s[h] += v.x * wT[h][e] + v.y * wT[h][e + 1] + v.z * wT[h][e + 2] + v.w * wT[h][e + 3];
    }
    #pragma unroll
    for (int off = 16; off; off >>= 1)
        #pragma unroll
        for (int h = 0; h < H_; h++) s[h] += __shfl_xor_sync(0xffffffffu, s[h], off);
    if (lane < H_) S[(size_t)m * H_ + lane] = s[lane] + bsh[lane];
}

// ---------------------------------------------------------------------------
// softmax weights per (b,h)
// ---------------------------------------------------------------------------
__global__ __launch_bounds__(256)
void softmax_kernel(const float* __restrict__ S, const unsigned char* __restrict__ mask,
                    float* __restrict__ w)
{
    const int bh = blockIdx.x;
    const int b = bh >> 3, h = bh & 7;
    __shared__ float buf[T_];
    __shared__ float red[256];
    const int tid = threadIdx.x;

    float mx = -INFINITY;
    for (int t = tid; t < T_; t += 256) {
        float s = S[((size_t)b * T_ + t) * H_ + h] * 0.125f;
        if (mask[b * T_ + t]) s = -INFINITY;
        buf[t] = s;
        mx = fmaxf(mx, s);
    }
    red[tid] = mx; __syncthreads();
    #pragma unroll
    for (int s2 = 128; s2 > 0; s2 >>= 1) {
        if (tid < s2) red[tid] = fmaxf(red[tid], red[tid + s2]);
        __syncthreads();
    }
    mx = red[0];
    __syncthreads();

    float sum = 0.f;
    for (int t = tid; t < T_; t += 256) {
        const float e = expf(buf[t] - mx);
        buf[t] = e;
        sum += e;
    }
    red[tid] = sum; __syncthreads();
    #pragma unroll
    for (int s2 = 128; s2 > 0; s2 >>= 1) {
        if (tid < s2) red[tid] += red[tid + s2];
        __syncthreads();
    }
    const float inv = 1.f / red[0];
    __syncthreads();
    for (int t = tid; t < T_; t += 256) w[(size_t)bh * T_ + t] = buf[t] * inv;
}

// ---------------------------------------------------------------------------
// pool x with all 8 head-weights: partial[chunk][b][h][e], 64 t per chunk
// ---------------------------------------------------------------------------
__global__ __launch_bounds__(256)
void pool_x_kernel(const float* __restrict__ w, const float* __restrict__ x,
                   float* __restrict__ partial)
{
    const int chunk = blockIdx.x, b = blockIdx.y;
    __shared__ float ws[H_][64];
    const int tid = threadIdx.x;
    for (int i = tid; i < H_ * 64; i += 256)
        ws[i >> 6][i & 63] = w[(size_t)(b * 8 + (i >> 6)) * T_ + chunk * 64 + (i & 63)];
    __syncthreads();

    float acc[H_][2];
    #pragma unroll
    for (int h = 0; h < H_; h++) { acc[h][0] = 0.f; acc[h][1] = 0.f; }

    const float* xp = x + (size_t)b * T_ * E_ + (size_t)chunk * 64 * E_;
    for (int tt = 0; tt < 64; tt++) {
        const float2 v = *reinterpret_cast<const float2*>(xp + (size_t)tt * E_ + tid * 2);
        #pragma unroll
        for (int h = 0; h < H_; h++) {
            acc[h][0] = fmaf(ws[h][tt], v.x, acc[h][0]);
            acc[h][1] = fmaf(ws[h][tt], v.y, acc[h][1]);
        }
    }
    #pragma unroll
    for (int h = 0; h < H_; h++) {
        float* pp = partial + (((size_t)chunk * 8 + b) * 8 + h) * E_ + tid * 2;
        pp[0] = acc[h][0]; pp[1] = acc[h][1];
    }
}

// ---------------------------------------------------------------------------
// flat: out[b, h*64+d] = (sum_c partial[c][b][h][:]) @ W[:, h*64+d] + bvec  (*qf)
// ---------------------------------------------------------------------------
template<bool MULQF>
__global__ __launch_bounds__(256)
void flat_kernel(const float* __restrict__ partial, const float* __restrict__ W,
                 const float* __restrict__ bvec, const float* __restrict__ qf_in,
                 float* __restrict__ out)
{
    const int b = blockIdx.x, h = blockIdx.y;
    __shared__ float px[E_];
    __shared__ float red[256];
    const int tid = threadIdx.x;
    for (int e = tid; e < E_; e += 256) {
        float a = 0.f;
        #pragma unroll
        for (int c = 0; c < NCHUNK; c++) a += partial[(((size_t)c * 8 + b) * 8 + h) * E_ + e];
        px[e] = a;
    }
    __syncthreads();
    const int d = tid & 63, q = tid >> 6;
    float acc = 0.f;
    for (int k = q * 128; k < q * 128 + 128; k++)
        acc = fmaf(px[k], W[(size_t)k * E_ + h * D_ + d], acc);
    red[tid] = acc; __syncthreads();
    if (tid < 64) {
        float v = red[tid] + red[tid + 64] + red[tid + 128] + red[tid + 192] + bvec[h * D_ + d];
        if (MULQF) v *= qf_in[b * E_ + h * D_ + d];
        out[b * E_ + h * D_ + d] = v;
    }
}

// cb[b][n] = sum_e bq[e]*kf[b,e]*Wo[e,n] + bo[n] + bq[n]
__global__ __launch_bounds__(128)
void cbias_kernel(const float* __restrict__ Wo, const float* __restrict__ bq,
                  const float* __restrict__ bo, const float* __restrict__ kf,
                  float* __restrict__ cb)
{
    const int b = blockIdx.y;
    const int n = blockIdx.x * 128 + threadIdx.x;
    float a = 0.f;
    for (int e = 0; e < E_; e++) a = fmaf(bq[e] * kf[b * E_ + e], Wo[(size_t)e * E_ + n], a);
    cb[b * E_ + n] = a + bo[n] + bq[n];
}

// ---------------------------------------------------------------------------
// Launch sequence
// ---------------------------------------------------------------------------
extern "C" void kernel_launch(void* const* d_in, const int* in_sizes, int n_in,
                              void* d_out, int out_size)
{
    const float* x            = (const float*)d_in[0];
    const unsigned char* mask = (const unsigned char*)d_in[3];
    const float* Wq  = (const float*)d_in[4];
    const float* bq  = (const float*)d_in[5];
    const float* Waq = (const float*)d_in[6];
    const float* baq = (const float*)d_in[7];
    const float* Wk  = (const float*)d_in[8];
    const float* bk  = (const float*)d_in[9];
    const float* Wak = (const float*)d_in[10];
    const float* bak = (const float*)d_in[11];
    const float* Wo  = (const float*)d_in[12];
    const float* bo  = (const float*)d_in[13];
    float* out = (float*)d_out;

    float *sc_, *w_, *pp_, *qf_, *kf_, *Cq_, *cq_, *Ck_, *ck_, *cb_;
    __half *ah, *al, *mt, *wakt, *wqh;
    cudaGetSymbolAddress((void**)&sc_, g_scores);
    cudaGetSymbolAddress((void**)&w_,  g_w);
    cudaGetSymbolAddress((void**)&pp_, g_partial);
    cudaGetSymbolAddress((void**)&qf_, g_qf);
    cudaGetSymbolAddress((void**)&kf_, g_kf);
    cudaGetSymbolAddress((void**)&Cq_, g_Cq);
    cudaGetSymbolAddress((void**)&cq_, g_cq);
    cudaGetSymbolAddress((void**)&Ck_, g_Ck);
    cudaGetSymbolAddress((void**)&ck_, g_ck);
    cudaGetSymbolAddress((void**)&cb_, g_cb);
    cudaGetSymbolAddress((void**)&ah,  g_ah);
    cudaGetSymbolAddress((void**)&al,  g_al);
    cudaGetSymbolAddress((void**)&mt,  g_mt);
    cudaGetSymbolAddress((void**)&wakt, g_wakt);
    cudaGetSymbolAddress((void**)&wqh, g_wqh);

    // 1) Cq = Wq@Waq; fused split of x + q_scores; Wq fp16 convert (for buildM)
    cmat_kernel<false><<<dim3(16, 1), 256>>>(Wq, Waq, bq, baq, nullptr, Cq_, cq_);
    wq_conv_kernel<<<E_ * E_ / 1024, 256>>>(Wq, wqh);
    split_scores_kernel<<<M_ / 8, 256>>>(x, ah, al, Cq_, cq_, sc_);
    // 2) q softmax + pool x + q_flat
    softmax_kernel<<<B_ * H_, 256>>>(sc_, mask, w_);
    pool_x_kernel<<<dim3(NCHUNK, B_), 256>>>(w_, x, pp_);
    flat_kernel<false><<<dim3(B_, H_), 256>>>(pp_, Wq, bq, nullptr, qf_);
    // 3) per-batch Ck; k_scores from x
    cmat_kernel<true><<<dim3(16, B_), 256>>>(Wk, Wak, bk, bak, qf_, Ck_, ck_);
    scores_pb_kernel<<<M_ / 8, 256>>>(x, Ck_, ck_, sc_);
    // 4) k softmax + pool x + k_flat
    softmax_kernel<<<B_ * H_, 256>>>(sc_, mask, w_);
    pool_x_kernel<<<dim3(NCHUNK, B_), 256>>>(w_, x, pp_);
    flat_kernel<true><<<dim3(B_, H_), 256>>>(pp_, Wk, bk, qf_, kf_);
    // 5) M^T via tensor cores: wakt = Wo^T*kf (fp16), mt = wakt@wqh^T + Wq^T
    woTkf_kernel<<<dim3(E_ / 32, E_ / 32, B_), 256>>>(Wo, kf_, wakt);
    cbias_kernel<<<dim3(4, B_), 128>>>(Wo, bq, bo, kf_, cb_);
    hmma_buildM<<<dim3(E_ / 128, B_ * E_ / 128), 256>>>(wakt, wqh, Wq, mt);
    // 6) final GEMM: out = x @ M_b + cb_b   (2-term fp16 split)
    hmma_gemm<2><<<dim3(E_ / 128, M_ / 128), 256>>>(ah, al, mt, cb_, out);
}

// round 8
// speedup vs baseline: 3.1151x; 1.0291x over previous
#include <cuda_runtime.h>
#include <cuda_fp16.h>
#include <cstdint>
#include <cmath>

// Problem constants
#define B_ 8
#define T_ 4096
#define E_ 512
#define H_ 8
#define D_ 64
#define M_ (B_*T_)   // 32768

#define NCHUNK 64    // pool chunks

// ---------------------------------------------------------------------------
// Scratch (__device__ globals per allocation-free rule)
// ---------------------------------------------------------------------------
__device__ float g_scores[(size_t)M_ * H_];          // 1 MB
__device__ float g_w[B_ * H_ * T_];                  // softmax weights, 1 MB
__device__ float g_partial[NCHUNK * B_ * H_ * E_];   // pool partials, 8 MB
__device__ float g_qf[B_ * E_];                      // q_flat
__device__ float g_kf[B_ * E_];                      // k_flat
__device__ float g_Cq[E_ * H_];                      // Wq@Waq
__device__ float g_cq[H_];
__device__ float g_Ck[B_ * E_ * H_];                 // per-batch Wk@diag(qf)@Wak
__device__ float g_ck[B_ * H_];
__device__ float g_cb[B_ * E_];                      // final bias per batch
__device__ __half g_ah[(size_t)M_ * E_];             // 32 MB  x hi (fp16)
__device__ __half g_al[(size_t)M_ * E_];             // 32 MB  x lo (fp16)
__device__ __half g_mt[B_ * E_ * E_];                // 4 MB   M^T per batch, fp16
__device__ __half g_wakt[B_ * E_ * E_];              // 4 MB   Wo^T*kf per batch, fp16
__device__ __half g_wqh[E_ * E_];                    // 0.5 MB Wq fp16 (row-major)

// ---------------------------------------------------------------------------
// HMMA helpers
// ---------------------------------------------------------------------------
__device__ __forceinline__ uint32_t smem_u32(const void* p) {
    uint32_t a;
    asm("{ .reg .u64 t; cvta.to.shared.u64 t, %1; cvt.u32.u64 %0, t; }" : "=r"(a) : "l"(p));
    return a;
}
__device__ __forceinline__ void ldm_x4(uint32_t& r0, uint32_t& r1, uint32_t& r2, uint32_t& r3,
                                       uint32_t addr) {
    asm volatile("ldmatrix.sync.aligned.m8n8.x4.shared.b16 {%0,%1,%2,%3}, [%4];"
                 : "=r"(r0), "=r"(r1), "=r"(r2), "=r"(r3) : "r"(addr));
}
__device__ __forceinline__ void mma16816(float* c, const uint32_t* a, const uint32_t* b) {
    asm volatile(
        "mma.sync.aligned.m16n8k16.row.col.f32.f16.f16.f32 "
        "{%0,%1,%2,%3}, {%4,%5,%6,%7}, {%8,%9}, {%0,%1,%2,%3};"
        : "+f"(c[0]), "+f"(c[1]), "+f"(c[2]), "+f"(c[3])
        : "r"(a[0]), "r"(a[1]), "r"(a[2]), "r"(a[3]), "r"(b[0]), "r"(b[1]));
}

// ---------------------------------------------------------------------------
// Final HMMA GEMM: out[m,n] = sum_seg A_seg[m,:] @ Bt_b[n,:] + bias_b[n]
// ---------------------------------------------------------------------------
template<int NSEG>
__global__ __launch_bounds__(256, 2)
void hmma_gemm(const __half* __restrict__ A0, const __half* __restrict__ A1,
               const __half* __restrict__ Bt,
               const float* __restrict__ bias, float* __restrict__ C)
{
    constexpr int LDT = 40;
    __shared__ __align__(16) __half As[2][128 * LDT];
    __shared__ __align__(16) __half Bs[2][128 * LDT];

    const int tid  = threadIdx.x;
    const int wid  = tid >> 5;
    const int lane = tid & 31;
    const int wm   = wid & 1;
    const int wn   = wid >> 1;
    const int row0 = blockIdx.y * 128;
    const int col0 = blockIdx.x * 128;
    const int b    = row0 / T_;

    const __half* aseg[2] = {A0, A1};
    const __half* Btb = Bt + (size_t)b * E_ * E_;
    const float* bias_b = bias + b * E_;

    const int lrow  = tid & 127;
    const int lhalf = tid >> 7;

    float acc[4][4][4];
    #pragma unroll
    for (int i = 0; i < 4; i++)
        #pragma unroll
        for (int j = 0; j < 4; j++)
            #pragma unroll
            for (int u = 0; u < 4; u++) acc[i][j][u] = 0.f;

    constexpr int NIT = NSEG * 16;

    uint4 ar0, ar1, br0, br1;
    {
        const __half* ga = aseg[0] + (size_t)(row0 + lrow) * E_ + lhalf * 16;
        const __half* gb = Btb + (size_t)(col0 + lrow) * E_ + lhalf * 16;
        ar0 = reinterpret_cast<const uint4*>(ga)[0];
        ar1 = reinterpret_cast<const uint4*>(ga)[1];
        br0 = reinterpret_cast<const uint4*>(gb)[0];
        br1 = reinterpret_cast<const uint4*>(gb)[1];
        __half* sa = &As[0][lrow * LDT + lhalf * 16];
        __half* sb = &Bs[0][lrow * LDT + lhalf * 16];
        reinterpret_cast<uint4*>(sa)[0] = ar0;
        reinterpret_cast<uint4*>(sa)[1] = ar1;
        reinterpret_cast<uint4*>(sb)[0] = br0;
        reinterpret_cast<uint4*>(sb)[1] = br1;
    }
    __syncthreads();

    const int r   = lane & 7;
    const int sel = lane >> 3;

    for (int i = 0; i < NIT; i++) {
        const int buf = i & 1;
        if (i + 1 < NIT) {
            const int seg = (i + 1) >> 4;
            const int k0  = ((i + 1) & 15) * 32;
            const __half* ga = aseg[seg] + (size_t)(row0 + lrow) * E_ + k0 + lhalf * 16;
            const __half* gb = Btb + (size_t)(col0 + lrow) * E_ + k0 + lhalf * 16;
            ar0 = reinterpret_cast<const uint4*>(ga)[0];
            ar1 = reinterpret_cast<const uint4*>(ga)[1];
            br0 = reinterpret_cast<const uint4*>(gb)[0];
            br1 = reinterpret_cast<const uint4*>(gb)[1];
        }

        const uint32_t abase = smem_u32(&As[buf][0]);
        const uint32_t bbase = smem_u32(&Bs[buf][0]);
        #pragma unroll
        for (int ks = 0; ks < 2; ks++) {
            const int k = ks * 16;
            uint32_t bfr[4][2];
            #pragma unroll
            for (int p = 0; p < 2; p++) {
                uint32_t addr = bbase +
                    (uint32_t)((wn * 32 + p * 16 + r + (sel >> 1) * 8) * LDT + k + (sel & 1) * 8) * 2;
                ldm_x4(bfr[2 * p][0], bfr[2 * p][1], bfr[2 * p + 1][0], bfr[2 * p + 1][1], addr);
            }
            #pragma unroll
            for (int mt = 0; mt < 4; mt++) {
                uint32_t af[4];
                uint32_t addr = abase +
                    (uint32_t)((wm * 64 + mt * 16 + r + (sel & 1) * 8) * LDT + k + (sel >> 1) * 8) * 2;
                ldm_x4(af[0], af[1], af[2], af[3], addr);
                #pragma unroll
                for (int nt = 0; nt < 4; nt++)
                    mma16816(acc[mt][nt], af, bfr[nt]);
            }
        }

        if (i + 1 < NIT) {
            const int nb = (i + 1) & 1;
            __half* sa = &As[nb][lrow * LDT + lhalf * 16];
            __half* sb = &Bs[nb][lrow * LDT + lhalf * 16];
            reinterpret_cast<uint4*>(sa)[0] = ar0;
            reinterpret_cast<uint4*>(sa)[1] = ar1;
            reinterpret_cast<uint4*>(sb)[0] = br0;
            reinterpret_cast<uint4*>(sb)[1] = br1;
            __syncthreads();
        }
    }

    #pragma unroll
    for (int mt = 0; mt < 4; mt++) {
        const int mg = row0 + wm * 64 + mt * 16 + (lane >> 2);
        #pragma unroll
        for (int nt = 0; nt < 4; nt++) {
            const int ng = col0 + wn * 32 + nt * 8 + (lane & 3) * 2;
            const float bi0 = bias_b[ng], bi1 = bias_b[ng + 1];
            *reinterpret_cast<float2*>(C + (size_t)mg * E_ + ng) =
                make_float2(acc[mt][nt][0] + bi0, acc[mt][nt][1] + bi1);
            *reinterpret_cast<float2*>(C + (size_t)(mg + 8) * E_ + ng) =
                make_float2(acc[mt][nt][2] + bi0, acc[mt][nt][3] + bi1);
        }
    }
}

// ---------------------------------------------------------------------------
// buildM HMMA: mt[m=b*512+n][e1] = fp16( sum_e2 wakt[m][e2]*wqh[e1][e2] + Wq[e1][n] )
// ---------------------------------------------------------------------------
__global__ __launch_bounds__(256, 2)
void hmma_buildM(const __half* __restrict__ A0, const __half* __restrict__ Bt,
                 const float* __restrict__ Wq, __half* __restrict__ Cmt)
{
    constexpr int LDT = 40;
    __shared__ __align__(16) __half As[2][128 * LDT];
    __shared__ __align__(16) __half Bs[2][128 * LDT];

    const int tid  = threadIdx.x;
    const int wid  = tid >> 5;
    const int lane = tid & 31;
    const int wm   = wid & 1;
    const int wn   = wid >> 1;
    const int row0 = blockIdx.y * 128;
    const int col0 = blockIdx.x * 128;

    const int lrow  = tid & 127;
    const int lhalf = tid >> 7;

    float acc[4][4][4];
    #pragma unroll
    for (int i = 0; i < 4; i++)
        #pragma unroll
        for (int j = 0; j < 4; j++)
            #pragma unroll
            for (int u = 0; u < 4; u++) acc[i][j][u] = 0.f;

    uint4 ar0, ar1, br0, br1;
    {
        const __half* ga = A0 + (size_t)(row0 + lrow) * E_ + lhalf * 16;
        const __half* gb = Bt + (size_t)(col0 + lrow) * E_ + lhalf * 16;
        ar0 = reinterpret_cast<const uint4*>(ga)[0];
        ar1 = reinterpret_cast<const uint4*>(ga)[1];
        br0 = reinterpret_cast<const uint4*>(gb)[0];
        br1 = reinterpret_cast<const uint4*>(gb)[1];
        __half* sa = &As[0][lrow * LDT + lhalf * 16];
        __half* sb = &Bs[0][lrow * LDT + lhalf * 16];
        reinterpret_cast<uint4*>(sa)[0] = ar0;
        reinterpret_cast<uint4*>(sa)[1] = ar1;
        reinterpret_cast<uint4*>(sb)[0] = br0;
        reinterpret_cast<uint4*>(sb)[1] = br1;
    }
    __syncthreads();

    const int r   = lane & 7;
    const int sel = lane >> 3;

    for (int i = 0; i < 16; i++) {
        const int buf = i & 1;
        if (i + 1 < 16) {
            const int k0 = (i + 1) * 32;
            const __half* ga = A0 + (size_t)(row0 + lrow) * E_ + k0 + lhalf * 16;
            const __half* gb = Bt + (size_t)(col0 + lrow) * E_ + k0 + lhalf * 16;
            ar0 = reinterpret_cast<const uint4*>(ga)[0];
            ar1 = reinterpret_cast<const uint4*>(ga)[1];
            br0 = reinterpret_cast<const uint4*>(gb)[0];
            br1 = reinterpret_cast<const uint4*>(gb)[1];
        }

        const uint32_t abase = smem_u32(&As[buf][0]);
        const uint32_t bbase = smem_u32(&Bs[buf][0]);
        #pragma unroll
        for (int ks = 0; ks < 2; ks++) {
            const int k = ks * 16;
            uint32_t bfr[4][2];
            #pragma unroll
            for (int p = 0; p < 2; p++) {
                uint32_t addr = bbase +
                    (uint32_t)((wn * 32 + p * 16 + r + (sel >> 1) * 8) * LDT + k + (sel & 1) * 8) * 2;
                ldm_x4(bfr[2 * p][0], bfr[2 * p][1], bfr[2 * p + 1][0], bfr[2 * p + 1][1], addr);
            }
            #pragma unroll
            for (int mt = 0; mt < 4; mt++) {
                uint32_t af[4];
                uint32_t addr = abase +
                    (uint32_t)((wm * 64 + mt * 16 + r + (sel & 1) * 8) * LDT + k + (sel >> 1) * 8) * 2;
                ldm_x4(af[0], af[1], af[2], af[3], addr);
                #pragma unroll
                for (int nt = 0; nt < 4; nt++)
                    mma16816(acc[mt][nt], af, bfr[nt]);
            }
        }

        if (i + 1 < 16) {
            const int nb = (i + 1) & 1;
            __half* sa = &As[nb][lrow * LDT + lhalf * 16];
            __half* sb = &Bs[nb][lrow * LDT + lhalf * 16];
            reinterpret_cast<uint4*>(sa)[0] = ar0;
            reinterpret_cast<uint4*>(sa)[1] = ar1;
            reinterpret_cast<uint4*>(sb)[0] = br0;
            reinterpret_cast<uint4*>(sb)[1] = br1;
            __syncthreads();
        }
    }

    #pragma unroll
    for (int mt = 0; mt < 4; mt++) {
        const int mg = row0 + wm * 64 + mt * 16 + (lane >> 2);
        const int n  = mg & 511;
        #pragma unroll
        for (int nt = 0; nt < 4; nt++) {
            const int ng = col0 + wn * 32 + nt * 8 + (lane & 3) * 2;
            float v0 = acc[mt][nt][0] + Wq[(size_t)ng * E_ + n];
            float v1 = acc[mt][nt][1] + Wq[(size_t)(ng + 1) * E_ + n];
            float v2 = acc[mt][nt][2] + Wq[(size_t)ng * E_ + n + 8];
            float v3 = acc[mt][nt][3] + Wq[(size_t)(ng + 1) * E_ + n + 8];
            *reinterpret_cast<__half2*>(Cmt + (size_t)mg * E_ + ng) =
                __half2(__float2half(v0), __float2half(v1));
            *reinterpret_cast<__half2*>(Cmt + (size_t)(mg + 8) * E_ + ng) =
                __half2(__float2half(v2), __float2half(v3));
        }
    }
}

// ---------------------------------------------------------------------------
// wakt[b*512+n][e2] = fp16( Wo[e2][n] * kf[b][e2] )
// ---------------------------------------------------------------------------
__global__ __launch_bounds__(256)
void woTkf_kernel(const float* __restrict__ Wo, const float* __restrict__ kf,
                  __half* __restrict__ wakt)
{
    __shared__ float t[32][33];
    const int n0 = blockIdx.x * 32, e20 = blockIdx.y * 32, b = blockIdx.z;
    const int tx = threadIdx.x & 31, ty = threadIdx.x >> 5;
    #pragma unroll
    for (int j = 0; j < 4; j++) {
        const int e2 = e20 + ty * 4 + j;
        t[ty * 4 + j][tx] = Wo[(size_t)e2 * E_ + n0 + tx] * kf[b * E_ + e2];
    }
    __syncthreads();
    #pragma unroll
    for (int j = 0; j < 4; j++) {
        const int n = n0 + ty * 4 + j;
        wakt[((size_t)b * E_ + n) * E_ + e20 + tx] = __float2half(t[tx][ty * 4 + j]);
    }
}

__global__ __launch_bounds__(256)
void wq_conv_kernel(const float* __restrict__ Wq, __half* __restrict__ wqh)
{
    const int i = blockIdx.x * 256 + threadIdx.x;
    const float4 v = reinterpret_cast<const float4*>(Wq)[i];
    __half2* hp = reinterpret_cast<__half2*>(wqh) + 2 * i;
    hp[0] = __half2(__float2half(v.x), __float2half(v.y));
    hp[1] = __half2(__float2half(v.z), __float2half(v.w));
}

// ---------------------------------------------------------------------------
// C[bb][e1][h] = sum_e2 W[e1,e2] * s[e2] * Wa[e2,h]
// ---------------------------------------------------------------------------
template<bool SCALED>
__global__ __launch_bounds__(256)
void cmat_kernel(const float* __restrict__ W, const float* __restrict__ Wa,
                 const float* __restrict__ bvec, const float* __restrict__ ba,
                 const float* __restrict__ scale,
                 float* __restrict__ C, float* __restrict__ cv)
{
    const int bb = blockIdx.y;
    __shared__ float s[E_][H_];
    const int tid = threadIdx.x;
    for (int i = tid; i < E_ * H_; i += 256) {
        const int e2 = i >> 3, h = i & 7;
        const float sc = SCALED ? scale[bb * E_ + e2] : 1.f;
        s[e2][h] = sc * Wa[i];
    }
    __syncthreads();
    const int e1 = blockIdx.x * 32 + (tid >> 3);
    const int h  = tid & 7;
    const float* wr = W + (size_t)e1 * E_;
    float acc = 0.f;
    for (int e2 = 0; e2 < E_; e2++) acc = fmaf(wr[e2], s[e2][h], acc);
    C[((size_t)bb * E_ + e1) * H_ + h] = acc;
    if (blockIdx.x == 0 && tid < H_) {
        float a = 0.f;
        for (int e2 = 0; e2 < E_; e2++) a = fmaf(bvec[e2], s[e2][tid], a);
        cv[bb * H_ + tid] = a + ba[tid];
    }
}

// ---------------------------------------------------------------------------
// Fused: split x -> fp16 hi/lo AND q_scores = x@Cq + cq
// ---------------------------------------------------------------------------
__global__ __launch_bounds__(256)
void split_scores_kernel(const float* __restrict__ x, __half* __restrict__ ah,
                         __half* __restrict__ al,
                         const float* __restrict__ Cq, const float* __restrict__ cq,
                         float* __restrict__ S)
{
    __shared__ float wT[H_][E_];
    __shared__ float bsh[H_];
    const int tid = threadIdx.x;
    for (int i = tid; i < E_ * H_; i += 256) wT[i & 7][i >> 3] = Cq[i];
    if (tid < H_) bsh[tid] = cq[tid];
    __syncthreads();

    const int warp = tid >> 5, lane = tid & 31;
    const int m = blockIdx.x * 8 + warp;
    const float4* xr = reinterpret_cast<const float4*>(x + (size_t)m * E_);

    float s[H_] = {0.f, 0.f, 0.f, 0.f, 0.f, 0.f, 0.f, 0.f};
    #pragma unroll
    for (int c = 0; c < 4; c++) {
        const int fi = c * 32 + lane;
        const float4 v = xr[fi];
        const int e = fi * 4;
        #pragma unroll
        for (int h = 0; h < H_; h++)
            s[h] += v.x * wT[h][e] + v.y * wT[h][e + 1] + v.z * wT[h][e + 2] + v.w * wT[h][e + 3];
        const __half h0 = __float2half(v.x), h1 = __float2half(v.y);
        const __half h2 = __float2half(v.z), h3 = __float2half(v.w);
        __half2* hp = reinterpret_cast<__half2*>(ah + (size_t)m * E_ + e);
        hp[0] = __half2(h0, h1); hp[1] = __half2(h2, h3);
        __half2* lp = reinterpret_cast<__half2*>(al + (size_t)m * E_ + e);
        lp[0] = __half2(__float2half(v.x - __half2float(h0)),
                        __float2half(v.y - __half2float(h1)));
        lp[1] = __half2(__float2half(v.z - __half2float(h2)),
                        __float2half(v.w - __half2float(h3)));
    }
    #pragma unroll
    for (int off = 16; off; off >>= 1)
        #pragma unroll
        for (int h = 0; h < H_; h++) s[h] += __shfl_xor_sync(0xffffffffu, s[h], off);
    if (lane < H_) S[(size_t)m * H_ + lane] = s[lane] + bsh[lane];
}

// k_scores with per-batch C, reading fp16 x (aux path; error ~1e-3 of scores,
// which reaches the output only via the ~1e-3-relative correction term)
__global__ __launch_bounds__(256)
void scores_pb_kernel(const __half* __restrict__ xh, const float* __restrict__ C,
                      const float* __restrict__ cv, float* __restrict__ S)
{
    const int b = blockIdx.x >> 9;
    __shared__ float wT[H_][E_];
    __shared__ float bsh[H_];
    const int tid = threadIdx.x;
    const float* Cb = C + (size_t)b * E_ * H_;
    for (int i = tid; i < E_ * H_; i += 256) wT[i & 7][i >> 3] = Cb[i];
    if (tid < H_) bsh[tid] = cv[b * H_ + tid];
    __syncthreads();

    const int warp = tid >> 5, lane = tid & 31;
    const int m = blockIdx.x * 8 + warp;
    const uint4* xr = reinterpret_cast<const uint4*>(xh + (size_t)m * E_);  // 64 x uint4

    float s[H_] = {0.f, 0.f, 0.f, 0.f, 0.f, 0.f, 0.f, 0.f};
    #pragma unroll
    for (int c = 0; c < 2; c++) {
        const int fi = c * 32 + lane;
        const uint4 raw = xr[fi];
        const int e = fi * 8;
        const __half2* p = reinterpret_cast<const __half2*>(&raw);
        #pragma unroll
        for (int j = 0; j < 4; j++) {
            const float2 f = __half22float2(p[j]);
            #pragma unroll
            for (int h = 0; h < H_; h++)
                s[h] += f.x * wT[h][e + 2 * j] + f.y * wT[h][e + 2 * j + 1];
        }
    }
    #pragma unroll
    for (int off = 16; off; off >>= 1)
        #pragma unroll
        for (int h = 0; h < H_; h++) s[h] += __shfl_xor_sync(0xffffffffu, s[h], off);
    if (lane < H_) S[(size_t)m * H_ + lane] = s[lane] + bsh[lane];
}

// ---------------------------------------------------------------------------
// softmax weights per (b,h) — 1024 threads for latency hiding
// ---------------------------------------------------------------------------
__global__ __launch_bounds__(1024)
void softmax_kernel(const float* __restrict__ S, const unsigned char* __restrict__ mask,
                    float* __restrict__ w)
{
    const int bh = blockIdx.x;
    const int b = bh >> 3, h = bh & 7;
    __shared__ float buf[T_];
    __shared__ float red[1024];
    const int tid = threadIdx.x;

    float mx = -INFINITY;
    #pragma unroll
    for (int c = 0; c < 4; c++) {
        const int t = c * 1024 + tid;
        float s = S[((size_t)b * T_ + t) * H_ + h] * 0.125f;
        if (mask[b * T_ + t]) s = -INFINITY;
        buf[t] = s;
        mx = fmaxf(mx, s);
    }
    red[tid] = mx; __syncthreads();
    #pragma unroll
    for (int s2 = 512; s2 > 0; s2 >>= 1) {
        if (tid < s2) red[tid] = fmaxf(red[tid], red[tid + s2]);
        __syncthreads();
    }
    mx = red[0];
    __syncthreads();

    float sum = 0.f;
    #pragma unroll
    for (int c = 0; c < 4; c++) {
        const int t = c * 1024 + tid;
        const float e = expf(buf[t] - mx);
        buf[t] = e;
        sum += e;
    }
    red[tid] = sum; __syncthreads();
    #pragma unroll
    for (int s2 = 512; s2 > 0; s2 >>= 1) {
        if (tid < s2) red[tid] += red[tid + s2];
        __syncthreads();
    }
    const float inv = 1.f / red[0];
    __syncthreads();
    #pragma unroll
    for (int c = 0; c < 4; c++) {
        const int t = c * 1024 + tid;
        w[(size_t)bh * T_ + t] = buf[t] * inv;
    }
}

// ---------------------------------------------------------------------------
// pool fp16 x with all 8 head-weights: partial[chunk][b][h][e], 64 t per chunk
// ---------------------------------------------------------------------------
__global__ __launch_bounds__(256)
void pool_x_kernel(const float* __restrict__ w, const __half* __restrict__ xh,
                   float* __restrict__ partial)
{
    const int chunk = blockIdx.x, b = blockIdx.y;
    __shared__ float ws[H_][64];
    const int tid = threadIdx.x;
    for (int i = tid; i < H_ * 64; i += 256)
        ws[i >> 6][i & 63] = w[(size_t)(b * 8 + (i >> 6)) * T_ + chunk * 64 + (i & 63)];
    __syncthreads();

    float acc[H_][2];
    #pragma unroll
    for (int h = 0; h < H_; h++) { acc[h][0] = 0.f; acc[h][1] = 0.f; }

    const __half* xp = xh + (size_t)b * T_ * E_ + (size_t)chunk * 64 * E_;
    for (int tt = 0; tt < 64; tt++) {
        const __half2 hv = *reinterpret_cast<const __half2*>(xp + (size_t)tt * E_ + tid * 2);
        const float2 v = __half22float2(hv);
        #pragma unroll
        for (int h = 0; h < H_; h++) {
            acc[h][0] = fmaf(ws[h][tt], v.x, acc[h][0]);
            acc[h][1] = fmaf(ws[h][tt], v.y, acc[h][1]);
        }
    }
    #pragma unroll
    for (int h = 0; h < H_; h++) {
        float* pp = partial + (((size_t)chunk * 8 + b) * 8 + h) * E_ + tid * 2;
        pp[0] = acc[h][0]; pp[1] = acc[h][1];
    }
}

// ---------------------------------------------------------------------------
// flat: out[b, h*64+d] = (sum_c partial[c][b][h][:]) @ W[:, h*64+d] + bvec  (*qf)
// ---------------------------------------------------------------------------
template<bool MULQF>
__global__ __launch_bounds__(256)
void flat_kernel(const float* __restrict__ partial, const float* __restrict__ W,
                 const float* __restrict__ bvec, const float* __restrict__ qf_in,
                 float* __restrict__ out)
{
    const int b = blockIdx.x, h = blockIdx.y;
    __shared__ float px[E_];
    __shared__ float red[256];
    const int tid = threadIdx.x;
    for (int e = tid; e < E_; e += 256) {
        float a = 0.f;
        #pragma unroll
        for (int c = 0; c < NCHUNK; c++) a += partial[(((size_t)c * 8 + b) * 8 + h) * E_ + e];
        px[e] = a;
    }
    __syncthreads();
    const int d = tid & 63, q = tid >> 6;
    float acc = 0.f;
    for (int k = q * 128; k < q * 128 + 128; k++)
        acc = fmaf(px[k], W[(size_t)k * E_ + h * D_ + d], acc);
    red[tid] = acc; __syncthreads();
    if (tid < 64) {
        float v = red[tid] + red[tid + 64] + red[tid + 128] + red[tid + 192] + bvec[h * D_ + d];
        if (MULQF) v *= qf_in[b * E_ + h * D_ + d];
        out[b * E_ + h * D_ + d] = v;
    }
}

// cb[b][n] = sum_e bq[e]*kf[b,e]*Wo[e,n] + bo[n] + bq[n]
__global__ __launch_bounds__(128)
void cbias_kernel(const float* __restrict__ Wo, const float* __restrict__ bq,
                  const float* __restrict__ bo, const float* __restrict__ kf,
                  float* __restrict__ cb)
{
    const int b = blockIdx.y;
    const int n = blockIdx.x * 128 + threadIdx.x;
    float a = 0.f;
    for (int e = 0; e < E_; e++) a = fmaf(bq[e] * kf[b * E_ + e], Wo[(size_t)e * E_ + n], a);
    cb[b * E_ + n] = a + bo[n] + bq[n];
}

// ---------------------------------------------------------------------------
// Launch sequence
// ---------------------------------------------------------------------------
extern "C" void kernel_launch(void* const* d_in, const int* in_sizes, int n_in,
                              void* d_out, int out_size)
{
    const float* x            = (const float*)d_in[0];
    const unsigned char* mask = (const unsigned char*)d_in[3];
    const float* Wq  = (const float*)d_in[4];
    const float* bq  = (const float*)d_in[5];
    const float* Waq = (const float*)d_in[6];
    const float* baq = (const float*)d_in[7];
    const float* Wk  = (const float*)d_in[8];
    const float* bk  = (const float*)d_in[9];
    const float* Wak = (const float*)d_in[10];
    const float* bak = (const float*)d_in[11];
    const float* Wo  = (const float*)d_in[12];
    const float* bo  = (const float*)d_in[13];
    float* out = (float*)d_out;

    float *sc_, *w_, *pp_, *qf_, *kf_, *Cq_, *cq_, *Ck_, *ck_, *cb_;
    __half *ah, *al, *mt, *wakt, *wqh;
    cudaGetSymbolAddress((void**)&sc_, g_scores);
    cudaGetSymbolAddress((void**)&w_,  g_w);
    cudaGetSymbolAddress((void**)&pp_, g_partial);
    cudaGetSymbolAddress((void**)&qf_, g_qf);
    cudaGetSymbolAddress((void**)&kf_, g_kf);
    cudaGetSymbolAddress((void**)&Cq_, g_Cq);
    cudaGetSymbolAddress((void**)&cq_, g_cq);
    cudaGetSymbolAddress((void**)&Ck_, g_Ck);
    cudaGetSymbolAddress((void**)&ck_, g_ck);
    cudaGetSymbolAddress((void**)&cb_, g_cb);
    cudaGetSymbolAddress((void**)&ah,  g_ah);
    cudaGetSymbolAddress((void**)&al,  g_al);
    cudaGetSymbolAddress((void**)&mt,  g_mt);
    cudaGetSymbolAddress((void**)&wakt, g_wakt);
    cudaGetSymbolAddress((void**)&wqh, g_wqh);

    // 1) Cq = Wq@Waq; fused split of x + q_scores; Wq fp16 convert
    cmat_kernel<false><<<dim3(16, 1), 256>>>(Wq, Waq, bq, baq, nullptr, Cq_, cq_);
    wq_conv_kernel<<<E_ * E_ / 1024, 256>>>(Wq, wqh);
    split_scores_kernel<<<M_ / 8, 256>>>(x, ah, al, Cq_, cq_, sc_);
    // 2) q softmax + pool (fp16 x) + q_flat
    softmax_kernel<<<B_ * H_, 1024>>>(sc_, mask, w_);
    pool_x_kernel<<<dim3(NCHUNK, B_), 256>>>(w_, ah, pp_);
    flat_kernel<false><<<dim3(B_, H_), 256>>>(pp_, Wq, bq, nullptr, qf_);
    // 3) per-batch Ck; k_scores from fp16 x
    cmat_kernel<true><<<dim3(16, B_), 256>>>(Wk, Wak, bk, bak, qf_, Ck_, ck_);
    scores_pb_kernel<<<M_ / 8, 256>>>(ah, Ck_, ck_, sc_);
    // 4) k softmax + pool (fp16 x) + k_flat
    softmax_kernel<<<B_ * H_, 1024>>>(sc_, mask, w_);
    pool_x_kernel<<<dim3(NCHUNK, B_), 256>>>(w_, ah, pp_);
    flat_kernel<true><<<dim3(B_, H_), 256>>>(pp_, Wk, bk, qf_, kf_);
    // 5) M^T via tensor cores
    woTkf_kernel<<<dim3(E_ / 32, E_ / 32, B_), 256>>>(Wo, kf_, wakt);
    cbias_kernel<<<dim3(4, B_), 128>>>(Wo, bq, bo, kf_, cb_);
    hmma_buildM<<<dim3(E_ / 128, B_ * E_ / 128), 256>>>(wakt, wqh, Wq, mt);
    // 6) final GEMM: out = x @ M_b + cb_b   (2-term fp16 split)
    hmma_gemm<2><<<dim3(E_ / 128, M_ / 128), 256>>>(ah, al, mt, cb_, out);
}

// round 9
// speedup vs baseline: 3.9503x; 1.2681x over previous
#include <cuda_runtime.h>
#include <cuda_fp16.h>
#include <cstdint>
#include <cmath>

// Problem constants
#define B_ 8
#define T_ 4096
#define E_ 512
#define H_ 8
#define D_ 64
#define M_ (B_*T_)   // 32768

#define NCHUNK 64    // pool chunks

// ---------------------------------------------------------------------------
// Scratch (__device__ globals per allocation-free rule)
// ---------------------------------------------------------------------------
__device__ float g_scores[(size_t)M_ * H_];          // 1 MB
__device__ float g_w[B_ * H_ * T_];                  // softmax weights, 1 MB
__device__ float g_partial[NCHUNK * B_ * H_ * E_];   // pool partials, 8 MB
__device__ float g_qf[B_ * E_];                      // q_flat
__device__ float g_kf[B_ * E_];                      // k_flat
__device__ float g_Cq[E_ * H_];                      // Wq@Waq
__device__ float g_cq[H_];
__device__ float g_Ck[B_ * E_ * H_];                 // per-batch Wk@diag(qf)@Wak
__device__ float g_ck[B_ * H_];
__device__ float g_cb[B_ * E_];                      // final bias per batch
__device__ __half g_ah[(size_t)M_ * E_];             // 32 MB  x hi (fp16)
__device__ __half g_al[(size_t)M_ * E_];             // 32 MB  x lo (fp16)
__device__ __half g_mt[B_ * E_ * E_];                // 4 MB   M^T per batch, fp16
__device__ __half g_wakt[B_ * E_ * E_];              // 4 MB   Wo^T*kf per batch, fp16
__device__ __half g_wqh[E_ * E_];                    // 0.5 MB Wq fp16 (row-major)

// ---------------------------------------------------------------------------
// HMMA / async helpers
// ---------------------------------------------------------------------------
__device__ __forceinline__ uint32_t smem_u32(const void* p) {
    uint32_t a;
    asm("{ .reg .u64 t; cvta.to.shared.u64 t, %1; cvt.u32.u64 %0, t; }" : "=r"(a) : "l"(p));
    return a;
}
__device__ __forceinline__ void ldm_x4(uint32_t& r0, uint32_t& r1, uint32_t& r2, uint32_t& r3,
                                       uint32_t addr) {
    asm volatile("ldmatrix.sync.aligned.m8n8.x4.shared.b16 {%0,%1,%2,%3}, [%4];"
                 : "=r"(r0), "=r"(r1), "=r"(r2), "=r"(r3) : "r"(addr));
}
__device__ __forceinline__ void mma16816(float* c, const uint32_t* a, const uint32_t* b) {
    asm volatile(
        "mma.sync.aligned.m16n8k16.row.col.f32.f16.f16.f32 "
        "{%0,%1,%2,%3}, {%4,%5,%6,%7}, {%8,%9}, {%0,%1,%2,%3};"
        : "+f"(c[0]), "+f"(c[1]), "+f"(c[2]), "+f"(c[3])
        : "r"(a[0]), "r"(a[1]), "r"(a[2]), "r"(a[3]), "r"(b[0]), "r"(b[1]));
}
__device__ __forceinline__ void cp16(uint32_t saddr, const void* gaddr) {
    asm volatile("cp.async.cg.shared.global [%0], [%1], 16;" :: "r"(saddr), "l"(gaddr));
}
#define CP_COMMIT() asm volatile("cp.async.commit_group;" ::: "memory")
#define CP_WAIT(n)  asm volatile("cp.async.wait_group %0;" :: "n"(n) : "memory")

// ---------------------------------------------------------------------------
// Final HMMA GEMM, fused 2-segment (Ah+Al share B), cp.async 3-stage pipeline.
// out[m,n] = (Ah+Al)[m,:] @ Bt_b[n,:] + bias_b[n]
// Tile 128x128, BK=32, 16 K-steps, 8 warps (2x4).
// ---------------------------------------------------------------------------
#define LDT    40                 // padded smem row stride in halves
#define TILEH  (128 * LDT)        // tile size in halves (5120)
#define STAGEH (3 * TILEH)        // Ah, Al, B per stage
#define NSTAGE 3
#define GEMM_SMEM (NSTAGE * STAGEH * 2)   // bytes = 92160

__global__ __launch_bounds__(256, 2)
void hmma_gemm_fused(const __half* __restrict__ A0, const __half* __restrict__ A1,
                     const __half* __restrict__ Bt,
                     const float* __restrict__ bias, float* __restrict__ C)
{
    extern __shared__ __half smem[];

    const int tid  = threadIdx.x;
    const int wid  = tid >> 5;
    const int lane = tid & 31;
    const int wm   = wid & 1;
    const int wn   = wid >> 1;
    const int row0 = blockIdx.y * 128;
    const int col0 = blockIdx.x * 128;
    const int b    = row0 / T_;

    const __half* Btb = Bt + (size_t)b * E_ * E_;
    const float* bias_b = bias + b * E_;

    // cp.async loader mapping: per tile 512 x 16B chunks; thread does c=tid, tid+256
    // chunk c: row = c>>2, kgroup = c&3 (8 halves each)
    const int r0c = tid >> 2,           kg0 = tid & 3;
    const int r1c = (tid + 256) >> 2,   kg1 = (tid + 256) & 3;
    const uint32_t sbase = smem_u32(smem);

    float acc[4][4][4];
    #pragma unroll
    for (int i = 0; i < 4; i++)
        #pragma unroll
        for (int j = 0; j < 4; j++)
            #pragma unroll
            for (int u = 0; u < 4; u++) acc[i][j][u] = 0.f;

    // issue one pipeline stage (k0 = s*32)
    auto issue = [&](int s) {
        const int k0 = s * 32;
        const uint32_t st = sbase + (uint32_t)((s % NSTAGE) * STAGEH) * 2;
        const uint32_t o0 = (uint32_t)(r0c * LDT + kg0 * 8) * 2;
        const uint32_t o1 = (uint32_t)(r1c * LDT + kg1 * 8) * 2;
        cp16(st + o0,               A0  + (size_t)(row0 + r0c) * E_ + k0 + kg0 * 8);
        cp16(st + o1,               A0  + (size_t)(row0 + r1c) * E_ + k0 + kg1 * 8);
        cp16(st + TILEH * 2 + o0,   A1  + (size_t)(row0 + r0c) * E_ + k0 + kg0 * 8);
        cp16(st + TILEH * 2 + o1,   A1  + (size_t)(row0 + r1c) * E_ + k0 + kg1 * 8);
        cp16(st + TILEH * 4 + o0,   Btb + (size_t)(col0 + r0c) * E_ + k0 + kg0 * 8);
        cp16(st + TILEH * 4 + o1,   Btb + (size_t)(col0 + r1c) * E_ + k0 + kg1 * 8);
        CP_COMMIT();
    };

    issue(0);
    issue(1);

    const int r   = lane & 7;
    const int sel = lane >> 3;

    for (int i = 0; i < 16; i++) {
        CP_WAIT(1);            // stage i resident
        __syncthreads();       // all threads see it; prior compute done

        if (i + 2 < 16) issue(i + 2);

        const uint32_t st = sbase + (uint32_t)((i % NSTAGE) * STAGEH) * 2;
        const uint32_t ah_base = st;
        const uint32_t al_base = st + TILEH * 2;
        const uint32_t b_base  = st + TILEH * 4;

        #pragma unroll
        for (int ks = 0; ks < 2; ks++) {
            const int k = ks * 16;
            uint32_t bfr[4][2];
            #pragma unroll
            for (int p = 0; p < 2; p++) {
                uint32_t addr = b_base +
                    (uint32_t)((wn * 32 + p * 16 + r + (sel >> 1) * 8) * LDT + k + (sel & 1) * 8) * 2;
                ldm_x4(bfr[2 * p][0], bfr[2 * p][1], bfr[2 * p + 1][0], bfr[2 * p + 1][1], addr);
            }
            const uint32_t a_off =
                (uint32_t)((wm * 64 + r + (sel & 1) * 8) * LDT + k + (sel >> 1) * 8) * 2;
            #pragma unroll
            for (int seg = 0; seg < 2; seg++) {
                const uint32_t abase2 = (seg == 0 ? ah_base : al_base) + a_off;
                #pragma unroll
                for (int mt = 0; mt < 4; mt++) {
                    uint32_t af[4];
                    ldm_x4(af[0], af[1], af[2], af[3], abase2 + (uint32_t)(mt * 16 * LDT) * 2);
                    #pragma unroll
                    for (int nt = 0; nt < 4; nt++)
                        mma16816(acc[mt][nt], af, bfr[nt]);
                }
            }
        }
        __syncthreads();       // compute done before stage buffer reuse
    }

    #pragma unroll
    for (int mt = 0; mt < 4; mt++) {
        const int mg = row0 + wm * 64 + mt * 16 + (lane >> 2);
        #pragma unroll
        for (int nt = 0; nt < 4; nt++) {
            const int ng = col0 + wn * 32 + nt * 8 + (lane & 3) * 2;
            const float bi0 = bias_b[ng], bi1 = bias_b[ng + 1];
            *reinterpret_cast<float2*>(C + (size_t)mg * E_ + ng) =
                make_float2(acc[mt][nt][0] + bi0, acc[mt][nt][1] + bi1);
            *reinterpret_cast<float2*>(C + (size_t)(mg + 8) * E_ + ng) =
                make_float2(acc[mt][nt][2] + bi0, acc[mt][nt][3] + bi1);
        }
    }
}

// ---------------------------------------------------------------------------
// buildM HMMA: mt[m=b*512+n][e1] = fp16( sum_e2 wakt[m][e2]*wqh[e1][e2] + Wq[e1][n] )
// ---------------------------------------------------------------------------
__global__ __launch_bounds__(256, 2)
void hmma_buildM(const __half* __restrict__ A0, const __half* __restrict__ Bt,
                 const float* __restrict__ Wq, __half* __restrict__ Cmt)
{
    __shared__ __align__(16) __half As[2][128 * LDT];
    __shared__ __align__(16) __half Bs[2][128 * LDT];

    const int tid  = threadIdx.x;
    const int wid  = tid >> 5;
    const int lane = tid & 31;
    const int wm   = wid & 1;
    const int wn   = wid >> 1;
    const int row0 = blockIdx.y * 128;
    const int col0 = blockIdx.x * 128;

    const int lrow  = tid & 127;
    const int lhalf = tid >> 7;

    float acc[4][4][4];
    #pragma unroll
    for (int i = 0; i < 4; i++)
        #pragma unroll
        for (int j = 0; j < 4; j++)
            #pragma unroll
            for (int u = 0; u < 4; u++) acc[i][j][u] = 0.f;

    uint4 ar0, ar1, br0, br1;
    {
        const __half* ga = A0 + (size_t)(row0 + lrow) * E_ + lhalf * 16;
        const __half* gb = Bt + (size_t)(col0 + lrow) * E_ + lhalf * 16;
        ar0 = reinterpret_cast<const uint4*>(ga)[0];
        ar1 = reinterpret_cast<const uint4*>(ga)[1];
        br0 = reinterpret_cast<const uint4*>(gb)[0];
        br1 = reinterpret_cast<const uint4*>(gb)[1];
        __half* sa = &As[0][lrow * LDT + lhalf * 16];
        __half* sb = &Bs[0][lrow * LDT + lhalf * 16];
        reinterpret_cast<uint4*>(sa)[0] = ar0;
        reinterpret_cast<uint4*>(sa)[1] = ar1;
        reinterpret_cast<uint4*>(sb)[0] = br0;
        reinterpret_cast<uint4*>(sb)[1] = br1;
    }
    __syncthreads();

    const int r   = lane & 7;
    const int sel = lane >> 3;

    for (int i = 0; i < 16; i++) {
        const int buf = i & 1;
        if (i + 1 < 16) {
            const int k0 = (i + 1) * 32;
            const __half* ga = A0 + (size_t)(row0 + lrow) * E_ + k0 + lhalf * 16;
            const __half* gb = Bt + (size_t)(col0 + lrow) * E_ + k0 + lhalf * 16;
            ar0 = reinterpret_cast<const uint4*>(ga)[0];
            ar1 = reinterpret_cast<const uint4*>(ga)[1];
            br0 = reinterpret_cast<const uint4*>(gb)[0];
            br1 = reinterpret_cast<const uint4*>(gb)[1];
        }

        const uint32_t abase = smem_u32(&As[buf][0]);
        const uint32_t bbase = smem_u32(&Bs[buf][0]);
        #pragma unroll
        for (int ks = 0; ks < 2; ks++) {
            const int k = ks * 16;
            uint32_t bfr[4][2];
            #pragma unroll
            for (int p = 0; p < 2; p++) {
                uint32_t addr = bbase +
                    (uint32_t)((wn * 32 + p * 16 + r + (sel >> 1) * 8) * LDT + k + (sel & 1) * 8) * 2;
                ldm_x4(bfr[2 * p][0], bfr[2 * p][1], bfr[2 * p + 1][0], bfr[2 * p + 1][1], addr);
            }
            #pragma unroll
            for (int mt = 0; mt < 4; mt++) {
                uint32_t af[4];
                uint32_t addr = abase +
                    (uint32_t)((wm * 64 + mt * 16 + r + (sel & 1) * 8) * LDT + k + (sel >> 1) * 8) * 2;
                ldm_x4(af[0], af[1], af[2], af[3], addr);
                #pragma unroll
                for (int nt = 0; nt < 4; nt++)
                    mma16816(acc[mt][nt], af, bfr[nt]);
            }
        }

        if (i + 1 < 16) {
            const int nb = (i + 1) & 1;
            __half* sa = &As[nb][lrow * LDT + lhalf * 16];
            __half* sb = &Bs[nb][lrow * LDT + lhalf * 16];
            reinterpret_cast<uint4*>(sa)[0] = ar0;
            reinterpret_cast<uint4*>(sa)[1] = ar1;
            reinterpret_cast<uint4*>(sb)[0] = br0;
            reinterpret_cast<uint4*>(sb)[1] = br1;
            __syncthreads();
        }
    }

    #pragma unroll
    for (int mt = 0; mt < 4; mt++) {
        const int mg = row0 + wm * 64 + mt * 16 + (lane >> 2);
        const int n  = mg & 511;
        #pragma unroll
        for (int nt = 0; nt < 4; nt++) {
            const int ng = col0 + wn * 32 + nt * 8 + (lane & 3) * 2;
            float v0 = acc[mt][nt][0] + Wq[(size_t)ng * E_ + n];
            float v1 = acc[mt][nt][1] + Wq[(size_t)(ng + 1) * E_ + n];
            float v2 = acc[mt][nt][2] + Wq[(size_t)ng * E_ + n + 8];
            float v3 = acc[mt][nt][3] + Wq[(size_t)(ng + 1) * E_ + n + 8];
            *reinterpret_cast<__half2*>(Cmt + (size_t)mg * E_ + ng) =
                __half2(__float2half(v0), __float2half(v1));
            *reinterpret_cast<__half2*>(Cmt + (size_t)(mg + 8) * E_ + ng) =
                __half2(__float2half(v2), __float2half(v3));
        }
    }
}

// ---------------------------------------------------------------------------
// wakt[b*512+n][e2] = fp16( Wo[e2][n] * kf[b][e2] )
// ---------------------------------------------------------------------------
__global__ __launch_bounds__(256)
void woTkf_kernel(const float* __restrict__ Wo, const float* __restrict__ kf,
                  __half* __restrict__ wakt)
{
    __shared__ float t[32][33];
    const int n0 = blockIdx.x * 32, e20 = blockIdx.y * 32, b = blockIdx.z;
    const int tx = threadIdx.x & 31, ty = threadIdx.x >> 5;
    #pragma unroll
    for (int j = 0; j < 4; j++) {
        const int e2 = e20 + ty * 4 + j;
        t[ty * 4 + j][tx] = Wo[(size_t)e2 * E_ + n0 + tx] * kf[b * E_ + e2];
    }
    __syncthreads();
    #pragma unroll
    for (int j = 0; j < 4; j++) {
        const int n = n0 + ty * 4 + j;
        wakt[((size_t)b * E_ + n) * E_ + e20 + tx] = __float2half(t[tx][ty * 4 + j]);
    }
}

__global__ __launch_bounds__(256)
void wq_conv_kernel(const float* __restrict__ Wq, __half* __restrict__ wqh)
{
    const int i = blockIdx.x * 256 + threadIdx.x;
    const float4 v = reinterpret_cast<const float4*>(Wq)[i];
    __half2* hp = reinterpret_cast<__half2*>(wqh) + 2 * i;
    hp[0] = __half2(__float2half(v.x), __float2half(v.y));
    hp[1] = __half2(__float2half(v.z), __float2half(v.w));
}

// ---------------------------------------------------------------------------
// C[bb][e1][h] = sum_e2 W[e1,e2] * s[e2] * Wa[e2,h]
// ---------------------------------------------------------------------------
template<bool SCALED>
__global__ __launch_bounds__(256)
void cmat_kernel(const float* __restrict__ W, const float* __restrict__ Wa,
                 const float* __restrict__ bvec, const float* __restrict__ ba,
                 const float* __restrict__ scale,
                 float* __restrict__ C, float* __restrict__ cv)
{
    const int bb = blockIdx.y;
    __shared__ float s[E_][H_];
    const int tid = threadIdx.x;
    for (int i = tid; i < E_ * H_; i += 256) {
        const int e2 = i >> 3, h = i & 7;
        const float sc = SCALED ? scale[bb * E_ + e2] : 1.f;
        s[e2][h] = sc * Wa[i];
    }
    __syncthreads();
    const int e1 = blockIdx.x * 32 + (tid >> 3);
    const int h  = tid & 7;
    const float* wr = W + (size_t)e1 * E_;
    float acc = 0.f;
    for (int e2 = 0; e2 < E_; e2++) acc = fmaf(wr[e2], s[e2][h], acc);
    C[((size_t)bb * E_ + e1) * H_ + h] = acc;
    if (blockIdx.x == 0 && tid < H_) {
        float a = 0.f;
        for (int e2 = 0; e2 < E_; e2++) a = fmaf(bvec[e2], s[e2][tid], a);
        cv[bb * H_ + tid] = a + ba[tid];
    }
}

// ---------------------------------------------------------------------------
// Fused: split x -> fp16 hi/lo AND q_scores = x@Cq + cq
// ---------------------------------------------------------------------------
__global__ __launch_bounds__(256)
void split_scores_kernel(const float* __restrict__ x, __half* __restrict__ ah,
                         __half* __restrict__ al,
                         const float* __restrict__ Cq, const float* __restrict__ cq,
                         float* __restrict__ S)
{
    __shared__ float wT[H_][E_];
    __shared__ float bsh[H_];
    const int tid = threadIdx.x;
    for (int i = tid; i < E_ * H_; i += 256) wT[i & 7][i >> 3] = Cq[i];
    if (tid < H_) bsh[tid] = cq[tid];
    __syncthreads();

    const int warp = tid >> 5, lane = tid & 31;
    const int m = blockIdx.x * 8 + warp;
    const float4* xr = reinterpret_cast<const float4*>(x + (size_t)m * E_);

    float s[H_] = {0.f, 0.f, 0.f, 0.f, 0.f, 0.f, 0.f, 0.f};
    #pragma unroll
    for (int c = 0; c < 4; c++) {
        const int fi = c * 32 + lane;
        const float4 v = xr[fi];
        const int e = fi * 4;
        #pragma unroll
        for (int h = 0; h < H_; h++)
            s[h] += v.x * wT[h][e] + v.y * wT[h][e + 1] + v.z * wT[h][e + 2] + v.w * wT[h][e + 3];
        const __half h0 = __float2half(v.x), h1 = __float2half(v.y);
        const __half h2 = __float2half(v.z), h3 = __float2half(v.w);
        __half2* hp = reinterpret_cast<__half2*>(ah + (size_t)m * E_ + e);
        hp[0] = __half2(h0, h1); hp[1] = __half2(h2, h3);
        __half2* lp = reinterpret_cast<__half2*>(al + (size_t)m * E_ + e);
        lp[0] = __half2(__float2half(v.x - __half2float(h0)),
                        __float2half(v.y - __half2float(h1)));
        lp[1] = __half2(__float2half(v.z - __half2float(h2)),
                        __float2half(v.w - __half2float(h3)));
    }
    #pragma unroll
    for (int off = 16; off; off >>= 1)
        #pragma unroll
        for (int h = 0; h < H_; h++) s[h] += __shfl_xor_sync(0xffffffffu, s[h], off);
    if (lane < H_) S[(size_t)m * H_ + lane] = s[lane] + bsh[lane];
}

// k_scores with per-batch C, reading fp16 x
__global__ __launch_bounds__(256)
void scores_pb_kernel(const __half* __restrict__ xh, const float* __restrict__ C,
                      const float* __restrict__ cv, float* __restrict__ S)
{
    const int b = blockIdx.x >> 9;
    __shared__ float wT[H_][E_];
    __shared__ float bsh[H_];
    const int tid = threadIdx.x;
    const float* Cb = C + (size_t)b * E_ * H_;
    for (int i = tid; i < E_ * H_; i += 256) wT[i & 7][i >> 3] = Cb[i];
    if (tid < H_) bsh[tid] = cv[b * H_ + tid];
    __syncthreads();

    const int warp = tid >> 5, lane = tid & 31;
    const int m = blockIdx.x * 8 + warp;
    const uint4* xr = reinterpret_cast<const uint4*>(xh + (size_t)m * E_);

    float s[H_] = {0.f, 0.f, 0.f, 0.f, 0.f, 0.f, 0.f, 0.f};
    #pragma unroll
    for (int c = 0; c < 2; c++) {
        const int fi = c * 32 + lane;
        const uint4 raw = xr[fi];
        const int e = fi * 8;
        const __half2* p = reinterpret_cast<const __half2*>(&raw);
        #pragma unroll
        for (int j = 0; j < 4; j++) {
            const float2 f = __half22float2(p[j]);
            #pragma unroll
            for (int h = 0; h < H_; h++)
                s[h] += f.x * wT[h][e + 2 * j] + f.y * wT[h][e + 2 * j + 1];
        }
    }
    #pragma unroll
    for (int off = 16; off; off >>= 1)
        #pragma unroll
        for (int h = 0; h < H_; h++) s[h] += __shfl_xor_sync(0xffffffffu, s[h], off);
    if (lane < H_) S[(size_t)m * H_ + lane] = s[lane] + bsh[lane];
}

// ---------------------------------------------------------------------------
// softmax weights per (b,h) — 1024 threads
// ---------------------------------------------------------------------------
__global__ __launch_bounds__(1024)
void softmax_kernel(const float* __restrict__ S, const unsigned char* __restrict__ mask,
                    float* __restrict__ w)
{
    const int bh = blockIdx.x;
    const int b = bh >> 3, h = bh & 7;
    __shared__ float buf[T_];
    __shared__ float red[1024];
    const int tid = threadIdx.x;

    float mx = -INFINITY;
    #pragma unroll
    for (int c = 0; c < 4; c++) {
        const int t = c * 1024 + tid;
        float s = S[((size_t)b * T_ + t) * H_ + h] * 0.125f;
        if (mask[b * T_ + t]) s = -INFINITY;
        buf[t] = s;
        mx = fmaxf(mx, s);
    }
    red[tid] = mx; __syncthreads();
    #pragma unroll
    for (int s2 = 512; s2 > 0; s2 >>= 1) {
        if (tid < s2) red[tid] = fmaxf(red[tid], red[tid + s2]);
        __syncthreads();
    }
    mx = red[0];
    __syncthreads();

    float sum = 0.f;
    #pragma unroll
    for (int c = 0; c < 4; c++) {
        const int t = c * 1024 + tid;
        const float e = expf(buf[t] - mx);
        buf[t] = e;
        sum += e;
    }
    red[tid] = sum; __syncthreads();
    #pragma unroll
    for (int s2 = 512; s2 > 0; s2 >>= 1) {
        if (tid < s2) red[tid] += red[tid + s2];
        __syncthreads();
    }
    const float inv = 1.f / red[0];
    __syncthreads();
    #pragma unroll
    for (int c = 0; c < 4; c++) {
        const int t = c * 1024 + tid;
        w[(size_t)bh * T_ + t] = buf[t] * inv;
    }
}

// ---------------------------------------------------------------------------
// pool fp16 x with all 8 head-weights: partial[chunk][b][h][e], 64 t per chunk
// ---------------------------------------------------------------------------
__global__ __launch_bounds__(256)
void pool_x_kernel(const float* __restrict__ w, const __half* __restrict__ xh,
                   float* __restrict__ partial)
{
    const int chunk = blockIdx.x, b = blockIdx.y;
    __shared__ float ws[H_][64];
    const int tid = threadIdx.x;
    for (int i = tid; i < H_ * 64; i += 256)
        ws[i >> 6][i & 63] = w[(size_t)(b * 8 + (i >> 6)) * T_ + chunk * 64 + (i & 63)];
    __syncthreads();

    float acc[H_][2];
    #pragma unroll
    for (int h = 0; h < H_; h++) { acc[h][0] = 0.f; acc[h][1] = 0.f; }

    const __half* xp = xh + (size_t)b * T_ * E_ + (size_t)chunk * 64 * E_;
    for (int tt = 0; tt < 64; tt++) {
        const __half2 hv = *reinterpret_cast<const __half2*>(xp + (size_t)tt * E_ + tid * 2);
        const float2 v = __half22float2(hv);
        #pragma unroll
        for (int h = 0; h < H_; h++) {
            acc[h][0] = fmaf(ws[h][tt], v.x, acc[h][0]);
            acc[h][1] = fmaf(ws[h][tt], v.y, acc[h][1]);
        }
    }
    #pragma unroll
    for (int h = 0; h < H_; h++) {
        float* pp = partial + (((size_t)chunk * 8 + b) * 8 + h) * E_ + tid * 2;
        pp[0] = acc[h][0]; pp[1] = acc[h][1];
    }
}

// ---------------------------------------------------------------------------
// flat: out[b, h*64+d] = (sum_c partial[c][b][h][:]) @ W[:, h*64+d] + bvec  (*qf)
// ---------------------------------------------------------------------------
template<bool MULQF>
__global__ __launch_bounds__(256)
void flat_kernel(const float* __restrict__ partial, const float* __restrict__ W,
                 const float* __restrict__ bvec, const float* __restrict__ qf_in,
                 float* __restrict__ out)
{
    const int b = blockIdx.x, h = blockIdx.y;
    __shared__ float px[E_];
    __shared__ float red[256];
    const int tid = threadIdx.x;
    for (int e = tid; e < E_; e += 256) {
        float a = 0.f;
        #pragma unroll
        for (int c = 0; c < NCHUNK; c++) a += partial[(((size_t)c * 8 + b) * 8 + h) * E_ + e];
        px[e] = a;
    }
    __syncthreads();
    const int d = tid & 63, q = tid >> 6;
    float acc = 0.f;
    for (int k = q * 128; k < q * 128 + 128; k++)
        acc = fmaf(px[k], W[(size_t)k * E_ + h * D_ + d], acc);
    red[tid] = acc; __syncthreads();
    if (tid < 64) {
        float v = red[tid] + red[tid + 64] + red[tid + 128] + red[tid + 192] + bvec[h * D_ + d];
        if (MULQF) v *= qf_in[b * E_ + h * D_ + d];
        out[b * E_ + h * D_ + d] = v;
    }
}

// cb[b][n] = sum_e bq[e]*kf[b,e]*Wo[e,n] + bo[n] + bq[n]
__global__ __launch_bounds__(128)
void cbias_kernel(const float* __restrict__ Wo, const float* __restrict__ bq,
                  const float* __restrict__ bo, const float* __restrict__ kf,
                  float* __restrict__ cb)
{
    const int b = blockIdx.y;
    const int n = blockIdx.x * 128 + threadIdx.x;
    float a = 0.f;
    for (int e = 0; e < E_; e++) a = fmaf(bq[e] * kf[b * E_ + e], Wo[(size_t)e * E_ + n], a);
    cb[b * E_ + n] = a + bo[n] + bq[n];
}

// ---------------------------------------------------------------------------
// Launch sequence
// ---------------------------------------------------------------------------
extern "C" void kernel_launch(void* const* d_in, const int* in_sizes, int n_in,
                              void* d_out, int out_size)
{
    const float* x            = (const float*)d_in[0];
    const unsigned char* mask = (const unsigned char*)d_in[3];
    const float* Wq  = (const float*)d_in[4];
    const float* bq  = (const float*)d_in[5];
    const float* Waq = (const float*)d_in[6];
    const float* baq = (const float*)d_in[7];
    const float* Wk  = (const float*)d_in[8];
    const float* bk  = (const float*)d_in[9];
    const float* Wak = (const float*)d_in[10];
    const float* bak = (const float*)d_in[11];
    const float* Wo  = (const float*)d_in[12];
    const float* bo  = (const float*)d_in[13];
    float* out = (float*)d_out;

    float *sc_, *w_, *pp_, *qf_, *kf_, *Cq_, *cq_, *Ck_, *ck_, *cb_;
    __half *ah, *al, *mt, *wakt, *wqh;
    cudaGetSymbolAddress((void**)&sc_, g_scores);
    cudaGetSymbolAddress((void**)&w_,  g_w);
    cudaGetSymbolAddress((void**)&pp_, g_partial);
    cudaGetSymbolAddress((void**)&qf_, g_qf);
    cudaGetSymbolAddress((void**)&kf_, g_kf);
    cudaGetSymbolAddress((void**)&Cq_, g_Cq);
    cudaGetSymbolAddress((void**)&cq_, g_cq);
    cudaGetSymbolAddress((void**)&Ck_, g_Ck);
    cudaGetSymbolAddress((void**)&ck_, g_ck);
    cudaGetSymbolAddress((void**)&cb_, g_cb);
    cudaGetSymbolAddress((void**)&ah,  g_ah);
    cudaGetSymbolAddress((void**)&al,  g_al);
    cudaGetSymbolAddress((void**)&mt,  g_mt);
    cudaGetSymbolAddress((void**)&wakt, g_wakt);
    cudaGetSymbolAddress((void**)&wqh, g_wqh);

    cudaFuncSetAttribute(hmma_gemm_fused, cudaFuncAttributeMaxDynamicSharedMemorySize, GEMM_SMEM);

    // 1) Cq = Wq@Waq; fused split of x + q_scores; Wq fp16 convert
    cmat_kernel<false><<<dim3(16, 1), 256>>>(Wq, Waq, bq, baq, nullptr, Cq_, cq_);
    wq_conv_kernel<<<E_ * E_ / 1024, 256>>>(Wq, wqh);
    split_scores_kernel<<<M_ / 8, 256>>>(x, ah, al, Cq_, cq_, sc_);
    // 2) q softmax + pool (fp16 x) + q_flat
    softmax_kernel<<<B_ * H_, 1024>>>(sc_, mask, w_);
    pool_x_kernel<<<dim3(NCHUNK, B_), 256>>>(w_, ah, pp_);
    flat_kernel<false><<<dim3(B_, H_), 256>>>(pp_, Wq, bq, nullptr, qf_);
    // 3) per-batch Ck; k_scores from fp16 x
    cmat_kernel<true><<<dim3(16, B_), 256>>>(Wk, Wak, bk, bak, qf_, Ck_, ck_);
    scores_pb_kernel<<<M_ / 8, 256>>>(ah, Ck_, ck_, sc_);
    // 4) k softmax + pool (fp16 x) + k_flat
    softmax_kernel<<<B_ * H_, 1024>>>(sc_, mask, w_);
    pool_x_kernel<<<dim3(NCHUNK, B_), 256>>>(w_, ah, pp_);
    flat_kernel<true><<<dim3(B_, H_), 256>>>(pp_, Wk, bk, qf_, kf_);
    // 5) M^T via tensor cores
    woTkf_kernel<<<dim3(E_ / 32, E_ / 32, B_), 256>>>(Wo, kf_, wakt);
    cbias_kernel<<<dim3(4, B_), 128>>>(Wo, bq, bo, kf_, cb_);
    hmma_buildM<<<dim3(E_ / 128, B_ * E_ / 128), 256>>>(wakt, wqh, Wq, mt);
    // 6) final GEMM: out = (Ah+Al) @ M_b + cb_b   (fused segments, cp.async pipeline)
    hmma_gemm_fused<<<dim3(E_ / 128, M_ / 128), 256, GEMM_SMEM>>>(ah, al, mt, cb_, out);
}

// round 10
// speedup vs baseline: 3.9719x; 1.0055x over previous
#include <cuda_runtime.h>
#include <cuda_fp16.h>
#include <cstdint>
#include <cmath>

// Problem constants
#define B_ 8
#define T_ 4096
#define E_ 512
#define H_ 8
#define D_ 64
#define M_ (B_*T_)   // 32768

#define NCHUNK 64    // pool chunks

// ---------------------------------------------------------------------------
// Scratch (__device__ globals per allocation-free rule)
// ---------------------------------------------------------------------------
__device__ float g_scores[(size_t)M_ * H_];          // 1 MB
__device__ float g_w[B_ * H_ * T_];                  // softmax weights, 1 MB
__device__ float g_partial[NCHUNK * B_ * H_ * E_];   // pool partials, 8 MB
__device__ float g_qf[B_ * E_];                      // q_flat
__device__ float g_kf[B_ * E_];                      // k_flat
__device__ float g_Cq[E_ * H_];                      // Wq@Waq
__device__ float g_cq[H_];
__device__ float g_Ck[B_ * E_ * H_];                 // per-batch Wk@diag(qf)@Wak
__device__ float g_ck[B_ * H_];
__device__ float g_cb[B_ * E_];                      // final bias per batch
__device__ __half g_ah[(size_t)M_ * E_];             // 32 MB  x hi (fp16)
__device__ __half g_al[(size_t)M_ * E_];             // 32 MB  x lo (fp16)
__device__ __half g_mt[B_ * E_ * E_];                // 4 MB   M^T per batch, fp16
__device__ __half g_wakt[B_ * E_ * E_];              // 4 MB   Wo^T*kf per batch, fp16
__device__ __half g_wqh[E_ * E_];                    // 0.5 MB Wq fp16 (row-major)

// ---------------------------------------------------------------------------
// HMMA / async helpers
// ---------------------------------------------------------------------------
__device__ __forceinline__ uint32_t smem_u32(const void* p) {
    uint32_t a;
    asm("{ .reg .u64 t; cvta.to.shared.u64 t, %1; cvt.u32.u64 %0, t; }" : "=r"(a) : "l"(p));
    return a;
}
__device__ __forceinline__ void ldm_x4(uint32_t& r0, uint32_t& r1, uint32_t& r2, uint32_t& r3,
                                       uint32_t addr) {
    asm volatile("ldmatrix.sync.aligned.m8n8.x4.shared.b16 {%0,%1,%2,%3}, [%4];"
                 : "=r"(r0), "=r"(r1), "=r"(r2), "=r"(r3) : "r"(addr));
}
__device__ __forceinline__ void mma16816(float* c, const uint32_t* a, const uint32_t* b) {
    asm volatile(
        "mma.sync.aligned.m16n8k16.row.col.f32.f16.f16.f32 "
        "{%0,%1,%2,%3}, {%4,%5,%6,%7}, {%8,%9}, {%0,%1,%2,%3};"
        : "+f"(c[0]), "+f"(c[1]), "+f"(c[2]), "+f"(c[3])
        : "r"(a[0]), "r"(a[1]), "r"(a[2]), "r"(a[3]), "r"(b[0]), "r"(b[1]));
}
__device__ __forceinline__ void cp16(uint32_t saddr, const void* gaddr) {
    asm volatile("cp.async.cg.shared.global [%0], [%1], 16;" :: "r"(saddr), "l"(gaddr));
}
#define CP_COMMIT() asm volatile("cp.async.commit_group;" ::: "memory")
#define CP_WAIT(n)  asm volatile("cp.async.wait_group %0;" :: "n"(n) : "memory")

// ---------------------------------------------------------------------------
// Final HMMA GEMM, fused 2-segment (Ah+Al share B), cp.async 3-stage pipeline.
// out[m,n] = (Ah+Al)[m,:] @ Bt_b[n,:] + bias_b[n]
// Tile 128x128, BK=32, 16 K-steps, 8 warps (2x4).
// ---------------------------------------------------------------------------
#define LDT    40                 // padded smem row stride in halves
#define TILEH  (128 * LDT)        // tile size in halves (5120)
#define STAGEH (3 * TILEH)        // Ah, Al, B per stage
#define NSTAGE 3
#define GEMM_SMEM (NSTAGE * STAGEH * 2)   // bytes = 92160

__global__ __launch_bounds__(256, 2)
void hmma_gemm_fused(const __half* __restrict__ A0, const __half* __restrict__ A1,
                     const __half* __restrict__ Bt,
                     const float* __restrict__ bias, float* __restrict__ C)
{
    extern __shared__ __half smem[];

    const int tid  = threadIdx.x;
    const int wid  = tid >> 5;
    const int lane = tid & 31;
    const int wm   = wid & 1;
    const int wn   = wid >> 1;
    const int row0 = blockIdx.y * 128;
    const int col0 = blockIdx.x * 128;
    const int b    = row0 / T_;

    const __half* Btb = Bt + (size_t)b * E_ * E_;
    const float* bias_b = bias + b * E_;

    // cp.async loader mapping: per tile 512 x 16B chunks; thread does c=tid, tid+256
    // chunk c: row = c>>2, kgroup = c&3 (8 halves each)
    const int r0c = tid >> 2,           kg0 = tid & 3;
    const int r1c = (tid + 256) >> 2,   kg1 = (tid + 256) & 3;
    const uint32_t sbase = smem_u32(smem);

    float acc[4][4][4];
    #pragma unroll
    for (int i = 0; i < 4; i++)
        #pragma unroll
        for (int j = 0; j < 4; j++)
            #pragma unroll
            for (int u = 0; u < 4; u++) acc[i][j][u] = 0.f;

    // issue one pipeline stage (k0 = s*32)
    auto issue = [&](int s) {
        const int k0 = s * 32;
        const uint32_t st = sbase + (uint32_t)((s % NSTAGE) * STAGEH) * 2;
        const uint32_t o0 = (uint32_t)(r0c * LDT + kg0 * 8) * 2;
        const uint32_t o1 = (uint32_t)(r1c * LDT + kg1 * 8) * 2;
        cp16(st + o0,               A0  + (size_t)(row0 + r0c) * E_ + k0 + kg0 * 8);
        cp16(st + o1,               A0  + (size_t)(row0 + r1c) * E_ + k0 + kg1 * 8);
        cp16(st + TILEH * 2 + o0,   A1  + (size_t)(row0 + r0c) * E_ + k0 + kg0 * 8);
        cp16(st + TILEH * 2 + o1,   A1  + (size_t)(row0 + r1c) * E_ + k0 + kg1 * 8);
        cp16(st + TILEH * 4 + o0,   Btb + (size_t)(col0 + r0c) * E_ + k0 + kg0 * 8);
        cp16(st + TILEH * 4 + o1,   Btb + (size_t)(col0 + r1c) * E_ + k0 + kg1 * 8);
        CP_COMMIT();
    };

    issue(0);
    issue(1);

    const int r   = lane & 7;
    const int sel = lane >> 3;

    for (int i = 0; i < 16; i++) {
        CP_WAIT(1);            // stage i resident
        __syncthreads();       // all threads see it; prior compute done

        if (i + 2 < 16) issue(i + 2);

        const uint32_t st = sbase + (uint32_t)((i % NSTAGE) * STAGEH) * 2;
        const uint32_t ah_base = st;
        const uint32_t al_base = st + TILEH * 2;
        const uint32_t b_base  = st + TILEH * 4;

        #pragma unroll
        for (int ks = 0; ks < 2; ks++) {
            const int k = ks * 16;
            uint32_t bfr[4][2];
            #pragma unroll
            for (int p = 0; p < 2; p++) {
                uint32_t addr = b_base +
                    (uint32_t)((wn * 32 + p * 16 + r + (sel >> 1) * 8) * LDT + k + (sel & 1) * 8) * 2;
                ldm_x4(bfr[2 * p][0], bfr[2 * p][1], bfr[2 * p + 1][0], bfr[2 * p + 1][1], addr);
            }
            const uint32_t a_off =
                (uint32_t)((wm * 64 + r + (sel & 1) * 8) * LDT + k + (sel >> 1) * 8) * 2;
            #pragma unroll
            for (int seg = 0; seg < 2; seg++) {
                const uint32_t abase2 = (seg == 0 ? ah_base : al_base) + a_off;
                #pragma unroll
                for (int mt = 0; mt < 4; mt++) {
                    uint32_t af[4];
                    ldm_x4(af[0], af[1], af[2], af[3], abase2 + (uint32_t)(mt * 16 * LDT) * 2);
                    #pragma unroll
                    for (int nt = 0; nt < 4; nt++)
                        mma16816(acc[mt][nt], af, bfr[nt]);
                }
            }
        }
        __syncthreads();       // compute done before stage buffer reuse
    }

    #pragma unroll
    for (int mt = 0; mt < 4; mt++) {
        const int mg = row0 + wm * 64 + mt * 16 + (lane >> 2);
        #pragma unroll
        for (int nt = 0; nt < 4; nt++) {
            const int ng = col0 + wn * 32 + nt * 8 + (lane & 3) * 2;
            const float bi0 = bias_b[ng], bi1 = bias_b[ng + 1];
            *reinterpret_cast<float2*>(C + (size_t)mg * E_ + ng) =
                make_float2(acc[mt][nt][0] + bi0, acc[mt][nt][1] + bi1);
            *reinterpret_cast<float2*>(C + (size_t)(mg + 8) * E_ + ng) =
                make_float2(acc[mt][nt][2] + bi0, acc[mt][nt][3] + bi1);
        }
    }
}

// ---------------------------------------------------------------------------
// buildM HMMA: mt[m=b*512+n][e1] = fp16( sum_e2 wakt[m][e2]*wqh[e1][e2] + Wq[e1][n] )
// ---------------------------------------------------------------------------
__global__ __launch_bounds__(256, 2)
void hmma_buildM(const __half* __restrict__ A0, const __half* __restrict__ Bt,
                 const float* __restrict__ Wq, __half* __restrict__ Cmt)
{
    __shared__ __align__(16) __half As[2][128 * LDT];
    __shared__ __align__(16) __half Bs[2][128 * LDT];

    const int tid  = threadIdx.x;
    const int wid  = tid >> 5;
    const int lane = tid & 31;
    const int wm   = wid & 1;
    const int wn   = wid >> 1;
    const int row0 = blockIdx.y * 128;
    const int col0 = blockIdx.x * 128;

    const int lrow  = tid & 127;
    const int lhalf = tid >> 7;

    float acc[4][4][4];
    #pragma unroll
    for (int i = 0; i < 4; i++)
        #pragma unroll
        for (int j = 0; j < 4; j++)
            #pragma unroll
            for (int u = 0; u < 4; u++) acc[i][j][u] = 0.f;

    uint4 ar0, ar1, br0, br1;
    {
        const __half* ga = A0 + (size_t)(row0 + lrow) * E_ + lhalf * 16;
        const __half* gb = Bt + (size_t)(col0 + lrow) * E_ + lhalf * 16;
        ar0 = reinterpret_cast<const uint4*>(ga)[0];
        ar1 = reinterpret_cast<const uint4*>(ga)[1];
        br0 = reinterpret_cast<const uint4*>(gb)[0];
        br1 = reinterpret_cast<const uint4*>(gb)[1];
        __half* sa = &As[0][lrow * LDT + lhalf * 16];
        __half* sb = &Bs[0][lrow * LDT + lhalf * 16];
        reinterpret_cast<uint4*>(sa)[0] = ar0;
        reinterpret_cast<uint4*>(sa)[1] = ar1;
        reinterpret_cast<uint4*>(sb)[0] = br0;
        reinterpret_cast<uint4*>(sb)[1] = br1;
    }
    __syncthreads();

    const int r   = lane & 7;
    const int sel = lane >> 3;

    for (int i = 0; i < 16; i++) {
        const int buf = i & 1;
        if (i + 1 < 16) {
            const int k0 = (i + 1) * 32;
            const __half* ga = A0 + (size_t)(row0 + lrow) * E_ + k0 + lhalf * 16;
            const __half* gb = Bt + (size_t)(col0 + lrow) * E_ + k0 + lhalf * 16;
            ar0 = reinterpret_cast<const uint4*>(ga)[0];
            ar1 = reinterpret_cast<const uint4*>(ga)[1];
            br0 = reinterpret_cast<const uint4*>(gb)[0];
            br1 = reinterpret_cast<const uint4*>(gb)[1];
        }

        const uint32_t abase = smem_u32(&As[buf][0]);
        const uint32_t bbase = smem_u32(&Bs[buf][0]);
        #pragma unroll
        for (int ks = 0; ks < 2; ks++) {
            const int k = ks * 16;
            uint32_t bfr[4][2];
            #pragma unroll
            for (int p = 0; p < 2; p++) {
                uint32_t addr = bbase +
                    (uint32_t)((wn * 32 + p * 16 + r + (sel >> 1) * 8) * LDT + k + (sel & 1) * 8) * 2;
                ldm_x4(bfr[2 * p][0], bfr[2 * p][1], bfr[2 * p + 1][0], bfr[2 * p + 1][1], addr);
            }
            #pragma unroll
            for (int mt = 0; mt < 4; mt++) {
                uint32_t af[4];
                uint32_t addr = abase +
                    (uint32_t)((wm * 64 + mt * 16 + r + (sel & 1) * 8) * LDT + k + (sel >> 1) * 8) * 2;
                ldm_x4(af[0], af[1], af[2], af[3], addr);
                #pragma unroll
                for (int nt = 0; nt < 4; nt++)
                    mma16816(acc[mt][nt], af, bfr[nt]);
            }
        }

        if (i + 1 < 16) {
            const int nb = (i + 1) & 1;
            __half* sa = &As[nb][lrow * LDT + lhalf * 16];
            __half* sb = &Bs[nb][lrow * LDT + lhalf * 16];
            reinterpret_cast<uint4*>(sa)[0] = ar0;
            reinterpret_cast<uint4*>(sa)[1] = ar1;
            reinterpret_cast<uint4*>(sb)[0] = br0;
            reinterpret_cast<uint4*>(sb)[1] = br1;
            __syncthreads();
        }
    }

    #pragma unroll
    for (int mt = 0; mt < 4; mt++) {
        const int mg = row0 + wm * 64 + mt * 16 + (lane >> 2);
        const int n  = mg & 511;
        #pragma unroll
        for (int nt = 0; nt < 4; nt++) {
            const int ng = col0 + wn * 32 + nt * 8 + (lane & 3) * 2;
            float v0 = acc[mt][nt][0] + Wq[(size_t)ng * E_ + n];
            float v1 = acc[mt][nt][1] + Wq[(size_t)(ng + 1) * E_ + n];
            float v2 = acc[mt][nt][2] + Wq[(size_t)ng * E_ + n + 8];
            float v3 = acc[mt][nt][3] + Wq[(size_t)(ng + 1) * E_ + n + 8];
            *reinterpret_cast<__half2*>(Cmt + (size_t)mg * E_ + ng) =
                __half2(__float2half(v0), __float2half(v1));
            *reinterpret_cast<__half2*>(Cmt + (size_t)(mg + 8) * E_ + ng) =
                __half2(__float2half(v2), __float2half(v3));
        }
    }
}

// ---------------------------------------------------------------------------
// wakt[b*512+n][e2] = fp16( Wo[e2][n] * kf[b][e2] )
// ---------------------------------------------------------------------------
__global__ __launch_bounds__(256)
void woTkf_kernel(const float* __restrict__ Wo, const float* __restrict__ kf,
                  __half* __restrict__ wakt)
{
    __shared__ float t[32][33];
    const int n0 = blockIdx.x * 32, e20 = blockIdx.y * 32, b = blockIdx.z;
    const int tx = threadIdx.x & 31, ty = threadIdx.x >> 5;
    #pragma unroll
    for (int j = 0; j < 4; j++) {
        const int e2 = e20 + ty * 4 + j;
        t[ty * 4 + j][tx] = Wo[(size_t)e2 * E_ + n0 + tx] * kf[b * E_ + e2];
    }
    __syncthreads();
    #pragma unroll
    for (int j = 0; j < 4; j++) {
        const int n = n0 + ty * 4 + j;
        wakt[((size_t)b * E_ + n) * E_ + e20 + tx] = __float2half(t[tx][ty * 4 + j]);
    }
}

__global__ __launch_bounds__(256)
void wq_conv_kernel(const float* __restrict__ Wq, __half* __restrict__ wqh)
{
    const int i = blockIdx.x * 256 + threadIdx.x;
    const float4 v = reinterpret_cast<const float4*>(Wq)[i];
    __half2* hp = reinterpret_cast<__half2*>(wqh) + 2 * i;
    hp[0] = __half2(__float2half(v.x), __float2half(v.y));
    hp[1] = __half2(__float2half(v.z), __float2half(v.w));
}

// ---------------------------------------------------------------------------
// C[bb][e1][h] = sum_e2 W[e1,e2] * s[e2] * Wa[e2,h]
// ---------------------------------------------------------------------------
template<bool SCALED>
__global__ __launch_bounds__(256)
void cmat_kernel(const float* __restrict__ W, const float* __restrict__ Wa,
                 const float* __restrict__ bvec, const float* __restrict__ ba,
                 const float* __restrict__ scale,
                 float* __restrict__ C, float* __restrict__ cv)
{
    const int bb = blockIdx.y;
    __shared__ float s[E_][H_];
    const int tid = threadIdx.x;
    for (int i = tid; i < E_ * H_; i += 256) {
        const int e2 = i >> 3, h = i & 7;
        const float sc = SCALED ? scale[bb * E_ + e2] : 1.f;
        s[e2][h] = sc * Wa[i];
    }
    __syncthreads();
    const int e1 = blockIdx.x * 32 + (tid >> 3);
    const int h  = tid & 7;
    const float* wr = W + (size_t)e1 * E_;
    float acc = 0.f;
    for (int e2 = 0; e2 < E_; e2++) acc = fmaf(wr[e2], s[e2][h], acc);
    C[((size_t)bb * E_ + e1) * H_ + h] = acc;
    if (blockIdx.x == 0 && tid < H_) {
        float a = 0.f;
        for (int e2 = 0; e2 < E_; e2++) a = fmaf(bvec[e2], s[e2][tid], a);
        cv[bb * H_ + tid] = a + ba[tid];
    }
}

// ---------------------------------------------------------------------------
// Fused: split x -> fp16 hi/lo AND q_scores = x@Cq + cq
// ---------------------------------------------------------------------------
__global__ __launch_bounds__(256)
void split_scores_kernel(const float* __restrict__ x, __half* __restrict__ ah,
                         __half* __restrict__ al,
                         const float* __restrict__ Cq, const float* __restrict__ cq,
                         float* __restrict__ S)
{
    __shared__ float wT[H_][E_];
    __shared__ float bsh[H_];
    const int tid = threadIdx.x;
    for (int i = tid; i < E_ * H_; i += 256) wT[i & 7][i >> 3] = Cq[i];
    if (tid < H_) bsh[tid] = cq[tid];
    __syncthreads();

    const int warp = tid >> 5, lane = tid & 31;
    const int m = blockIdx.x * 8 + warp;
    const float4* xr = reinterpret_cast<const float4*>(x + (size_t)m * E_);

    float s[H_] = {0.f, 0.f, 0.f, 0.f, 0.f, 0.f, 0.f, 0.f};
    #pragma unroll
    for (int c = 0; c < 4; c++) {
        const int fi = c * 32 + lane;
        const float4 v = xr[fi];
        const int e = fi * 4;
        #pragma unroll
        for (int h = 0; h < H_; h++)
            s[h] += v.x * wT[h][e] + v.y * wT[h][e + 1] + v.z * wT[h][e + 2] + v.w * wT[h][e + 3];
        const __half h0 = __float2half(v.x), h1 = __float2half(v.y);
        const __half h2 = __float2half(v.z), h3 = __float2half(v.w);
        __half2* hp = reinterpret_cast<__half2*>(ah + (size_t)m * E_ + e);
        hp[0] = __half2(h0, h1); hp[1] = __half2(h2, h3);
        __half2* lp = reinterpret_cast<__half2*>(al + (size_t)m * E_ + e);
        lp[0] = __half2(__float2half(v.x - __half2float(h0)),
                        __float2half(v.y - __half2float(h1)));
        lp[1] = __half2(__float2half(v.z - __half2float(h2)),
                        __float2half(v.w - __half2float(h3)));
    }
    #pragma unroll
    for (int off = 16; off; off >>= 1)
        #pragma unroll
        for (int h = 0; h < H_; h++) s[h] += __shfl_xor_sync(0xffffffffu, s[h], off);
    if (lane < H_) S[(size_t)m * H_ + lane] = s[lane] + bsh[lane];
}

// k_scores with per-batch C, reading fp16 x
__global__ __launch_bounds__(256)
void scores_pb_kernel(const __half* __restrict__ xh, const float* __restrict__ C,
                      const float* __restrict__ cv, float* __restrict__ S)
{
    const int b = blockIdx.x >> 9;
    __shared__ float wT[H_][E_];
    __shared__ float bsh[H_];
    const int tid = threadIdx.x;
    const float* Cb = C + (size_t)b * E_ * H_;
    for (int i = tid; i < E_ * H_; i += 256) wT[i & 7][i >> 3] = Cb[i];
    if (tid < H_) bsh[tid] = cv[b * H_ + tid];
    __syncthreads();

    const int warp = tid >> 5, lane = tid & 31;
    const int m = blockIdx.x * 8 + warp;
    const uint4* xr = reinterpret_cast<const uint4*>(xh + (size_t)m * E_);

    float s[H_] = {0.f, 0.f, 0.f, 0.f, 0.f, 0.f, 0.f, 0.f};
    #pragma unroll
    for (int c = 0; c < 2; c++) {
        const int fi = c * 32 + lane;
        const uint4 raw = xr[fi];
        const int e = fi * 8;
        const __half2* p = reinterpret_cast<const __half2*>(&raw);
        #pragma unroll
        for (int j = 0; j < 4; j++) {
            const float2 f = __half22float2(p[j]);
            #pragma unroll
            for (int h = 0; h < H_; h++)
                s[h] += f.x * wT[h][e + 2 * j] + f.y * wT[h][e + 2 * j + 1];
        }
    }
    #pragma unroll
    for (int off = 16; off; off >>= 1)
        #pragma unroll
        for (int h = 0; h < H_; h++) s[h] += __shfl_xor_sync(0xffffffffu, s[h], off);
    if (lane < H_) S[(size_t)m * H_ + lane] = s[lane] + bsh[lane];
}

// ---------------------------------------------------------------------------
// softmax weights per (b,h) — 1024 threads
// ---------------------------------------------------------------------------
__global__ __launch_bounds__(1024)
void softmax_kernel(const float* __restrict__ S, const unsigned char* __restrict__ mask,
                    float* __restrict__ w)
{
    const int bh = blockIdx.x;
    const int b = bh >> 3, h = bh & 7;
    __shared__ float buf[T_];
    __shared__ float red[1024];
    const int tid = threadIdx.x;

    float mx = -INFINITY;
    #pragma unroll
    for (int c = 0; c < 4; c++) {
        const int t = c * 1024 + tid;
        float s = S[((size_t)b * T_ + t) * H_ + h] * 0.125f;
        if (mask[b * T_ + t]) s = -INFINITY;
        buf[t] = s;
        mx = fmaxf(mx, s);
    }
    red[tid] = mx; __syncthreads();
    #pragma unroll
    for (int s2 = 512; s2 > 0; s2 >>= 1) {
        if (tid < s2) red[tid] = fmaxf(red[tid], red[tid + s2]);
        __syncthreads();
    }
    mx = red[0];
    __syncthreads();

    float sum = 0.f;
    #pragma unroll
    for (int c = 0; c < 4; c++) {
        const int t = c * 1024 + tid;
        const float e = expf(buf[t] - mx);
        buf[t] = e;
        sum += e;
    }
    red[tid] = sum; __syncthreads();
    #pragma unroll
    for (int s2 = 512; s2 > 0; s2 >>= 1) {
        if (tid < s2) red[tid] += red[tid + s2];
        __syncthreads();
    }
    const float inv = 1.f / red[0];
    __syncthreads();
    #pragma unroll
    for (int c = 0; c < 4; c++) {
        const int t = c * 1024 + tid;
        w[(size_t)bh * T_ + t] = buf[t] * inv;
    }
}

// ---------------------------------------------------------------------------
// pool fp16 x with all 8 head-weights: partial[chunk][b][h][e], 64 t per chunk
// ---------------------------------------------------------------------------
__global__ __launch_bounds__(256)
void pool_x_kernel(const float* __restrict__ w, const __half* __restrict__ xh,
                   float* __restrict__ partial)
{
    const int chunk = blockIdx.x, b = blockIdx.y;
    __shared__ float ws[H_][64];
    const int tid = threadIdx.x;
    for (int i = tid; i < H_ * 64; i += 256)
        ws[i >> 6][i & 63] = w[(size_t)(b * 8 + (i >> 6)) * T_ + chunk * 64 + (i & 63)];
    __syncthreads();

    float acc[H_][2];
    #pragma unroll
    for (int h = 0; h < H_; h++) { acc[h][0] = 0.f; acc[h][1] = 0.f; }

    const __half* xp = xh + (size_t)b * T_ * E_ + (size_t)chunk * 64 * E_;
    for (int tt = 0; tt < 64; tt++) {
        const __half2 hv = *reinterpret_cast<const __half2*>(xp + (size_t)tt * E_ + tid * 2);
        const float2 v = __half22float2(hv);
        #pragma unroll
        for (int h = 0; h < H_; h++) {
            acc[h][0] = fmaf(ws[h][tt], v.x, acc[h][0]);
            acc[h][1] = fmaf(ws[h][tt], v.y, acc[h][1]);
        }
    }
    #pragma unroll
    for (int h = 0; h < H_; h++) {
        float* pp = partial + (((size_t)chunk * 8 + b) * 8 + h) * E_ + tid * 2;
        pp[0] = acc[h][0]; pp[1] = acc[h][1];
    }
}

// ---------------------------------------------------------------------------
// flat: out[b, h*64+d] = (sum_c partial[c][b][h][:]) @ W[:, h*64+d] + bvec  (*qf)
// ---------------------------------------------------------------------------
template<bool MULQF>
__global__ __launch_bounds__(256)
void flat_kernel(const float* __restrict__ partial, const float* __restrict__ W,
                 const float* __restrict__ bvec, const float* __restrict__ qf_in,
                 float* __restrict__ out)
{
    const int b = blockIdx.x, h = blockIdx.y;
    __shared__ float px[E_];
    __shared__ float red[256];
    const int tid = threadIdx.x;
    for (int e = tid; e < E_; e += 256) {
        float a = 0.f;
        #pragma unroll
        for (int c = 0; c < NCHUNK; c++) a += partial[(((size_t)c * 8 + b) * 8 + h) * E_ + e];
        px[e] = a;
    }
    __syncthreads();
    const int d = tid & 63, q = tid >> 6;
    float acc = 0.f;
    for (int k = q * 128; k < q * 128 + 128; k++)
        acc = fmaf(px[k], W[(size_t)k * E_ + h * D_ + d], acc);
    red[tid] = acc; __syncthreads();
    if (tid < 64) {
        float v = red[tid] + red[tid + 64] + red[tid + 128] + red[tid + 192] + bvec[h * D_ + d];
        if (MULQF) v *= qf_in[b * E_ + h * D_ + d];
        out[b * E_ + h * D_ + d] = v;
    }
}

// cb[b][n] = sum_e bq[e]*kf[b,e]*Wo[e,n] + bo[n] + bq[n]
__global__ __launch_bounds__(128)
void cbias_kernel(const float* __restrict__ Wo, const float* __restrict__ bq,
                  const float* __restrict__ bo, const float* __restrict__ kf,
                  float* __restrict__ cb)
{
    const int b = blockIdx.y;
    const int n = blockIdx.x * 128 + threadIdx.x;
    float a = 0.f;
    for (int e = 0; e < E_; e++) a = fmaf(bq[e] * kf[b * E_ + e], Wo[(size_t)e * E_ + n], a);
    cb[b * E_ + n] = a + bo[n] + bq[n];
}

// ---------------------------------------------------------------------------
// Launch sequence
// ---------------------------------------------------------------------------
extern "C" void kernel_launch(void* const* d_in, const int* in_sizes, int n_in,
                              void* d_out, int out_size)
{
    const float* x            = (const float*)d_in[0];
    const unsigned char* mask = (const unsigned char*)d_in[3];
    const float* Wq  = (const float*)d_in[4];
    const float* bq  = (const float*)d_in[5];
    const float* Waq = (const float*)d_in[6];
    const float* baq = (const float*)d_in[7];
    const float* Wk  = (const float*)d_in[8];
    const float* bk  = (const float*)d_in[9];
    const float* Wak = (const float*)d_in[10];
    const float* bak = (const float*)d_in[11];
    const float* Wo  = (const float*)d_in[12];
    const float* bo  = (const float*)d_in[13];
    float* out = (float*)d_out;

    float *sc_, *w_, *pp_, *qf_, *kf_, *Cq_, *cq_, *Ck_, *ck_, *cb_;
    __half *ah, *al, *mt, *wakt, *wqh;
    cudaGetSymbolAddress((void**)&sc_, g_scores);
    cudaGetSymbolAddress((void**)&w_,  g_w);
    cudaGetSymbolAddress((void**)&pp_, g_partial);
    cudaGetSymbolAddress((void**)&qf_, g_qf);
    cudaGetSymbolAddress((void**)&kf_, g_kf);
    cudaGetSymbolAddress((void**)&Cq_, g_Cq);
    cudaGetSymbolAddress((void**)&cq_, g_cq);
    cudaGetSymbolAddress((void**)&Ck_, g_Ck);
    cudaGetSymbolAddress((void**)&ck_, g_ck);
    cudaGetSymbolAddress((void**)&cb_, g_cb);
    cudaGetSymbolAddress((void**)&ah,  g_ah);
    cudaGetSymbolAddress((void**)&al,  g_al);
    cudaGetSymbolAddress((void**)&mt,  g_mt);
    cudaGetSymbolAddress((void**)&wakt, g_wakt);
    cudaGetSymbolAddress((void**)&wqh, g_wqh);

    cudaFuncSetAttribute(hmma_gemm_fused, cudaFuncAttributeMaxDynamicSharedMemorySize, GEMM_SMEM);

    // 1) Cq = Wq@Waq; fused split of x + q_scores; Wq fp16 convert
    cmat_kernel<false><<<dim3(16, 1), 256>>>(Wq, Waq, bq, baq, nullptr, Cq_, cq_);
    wq_conv_kernel<<<E_ * E_ / 1024, 256>>>(Wq, wqh);
    split_scores_kernel<<<M_ / 8, 256>>>(x, ah, al, Cq_, cq_, sc_);
    // 2) q softmax + pool (fp16 x) + q_flat
    softmax_kernel<<<B_ * H_, 1024>>>(sc_, mask, w_);
    pool_x_kernel<<<dim3(NCHUNK, B_), 256>>>(w_, ah, pp_);
    flat_kernel<false><<<dim3(B_, H_), 256>>>(pp_, Wq, bq, nullptr, qf_);
    // 3) per-batch Ck; k_scores from fp16 x
    cmat_kernel<true><<<dim3(16, B_), 256>>>(Wk, Wak, bk, bak, qf_, Ck_, ck_);
    scores_pb_kernel<<<M_ / 8, 256>>>(ah, Ck_, ck_, sc_);
    // 4) k softmax + pool (fp16 x) + k_flat
    softmax_kernel<<<B_ * H_, 1024>>>(sc_, mask, w_);
    pool_x_kernel<<<dim3(NCHUNK, B_), 256>>>(w_, ah, pp_);
    flat_kernel<true><<<dim3(B_, H_), 256>>>(pp_, Wk, bk, qf_, kf_);
    // 5) M^T via tensor cores
    woTkf_kernel<<<dim3(E_ / 32, E_ / 32, B_), 256>>>(Wo, kf_, wakt);
    cbias_kernel<<<dim3(4, B_), 128>>>(Wo, bq, bo, kf_, cb_);
    hmma_buildM<<<dim3(E_ / 128, B_ * E_ / 128), 256>>>(wakt, wqh, Wq, mt);
    // 6) final GEMM: out = (Ah+Al) @ M_b + cb_b   (fused segments, cp.async pipeline)
    hmma_gemm_fused<<<dim3(E_ / 128, M_ / 128), 256, GEMM_SMEM>>>(ah, al, mt, cb_, out);
}

// round 11
// speedup vs baseline: 4.6455x; 1.1696x over previous
#include <cuda_runtime.h>
#include <cuda_fp16.h>
#include <cstdint>
#include <cmath>

// Problem constants
#define B_ 8
#define T_ 4096
#define E_ 512
#define H_ 8
#define D_ 64
#define M_ (B_*T_)   // 32768

#define NCHUNK 64    // pool chunks

// ---------------------------------------------------------------------------
// Scratch (__device__ globals per allocation-free rule)
// ---------------------------------------------------------------------------
__device__ float g_scores[(size_t)M_ * H_];          // 1 MB
__device__ float g_w[B_ * H_ * T_];                  // softmax weights, 1 MB
__device__ float g_partial[NCHUNK * B_ * H_ * E_];   // pool partials, 8 MB
__device__ float g_qf[B_ * E_];                      // q_flat
__device__ float g_kf[B_ * E_];                      // k_flat
__device__ float g_Cq[E_ * H_];                      // Wq@Waq
__device__ float g_cq[H_];
__device__ float g_Ck[B_ * E_ * H_];                 // per-batch Wk@diag(qf)@Wak
__device__ float g_ck[B_ * H_];
__device__ float g_cb[B_ * E_];                      // final bias per batch
__device__ __half g_ah[(size_t)M_ * E_];             // 32 MB  x (fp16)
__device__ __half g_mt[B_ * E_ * E_];                // 4 MB   M^T per batch, fp16
__device__ __half g_wakt[B_ * E_ * E_];              // 4 MB   Wo^T*kf per batch, fp16
__device__ __half g_wqh[E_ * E_];                    // 0.5 MB Wq fp16 (row-major)

// ---------------------------------------------------------------------------
// HMMA / async helpers
// ---------------------------------------------------------------------------
__device__ __forceinline__ uint32_t smem_u32(const void* p) {
    uint32_t a;
    asm("{ .reg .u64 t; cvta.to.shared.u64 t, %1; cvt.u32.u64 %0, t; }" : "=r"(a) : "l"(p));
    return a;
}
__device__ __forceinline__ void ldm_x4(uint32_t& r0, uint32_t& r1, uint32_t& r2, uint32_t& r3,
                                       uint32_t addr) {
    asm volatile("ldmatrix.sync.aligned.m8n8.x4.shared.b16 {%0,%1,%2,%3}, [%4];"
                 : "=r"(r0), "=r"(r1), "=r"(r2), "=r"(r3) : "r"(addr));
}
__device__ __forceinline__ void mma16816(float* c, const uint32_t* a, const uint32_t* b) {
    asm volatile(
        "mma.sync.aligned.m16n8k16.row.col.f32.f16.f16.f32 "
        "{%0,%1,%2,%3}, {%4,%5,%6,%7}, {%8,%9}, {%0,%1,%2,%3};"
        : "+f"(c[0]), "+f"(c[1]), "+f"(c[2]), "+f"(c[3])
        : "r"(a[0]), "r"(a[1]), "r"(a[2]), "r"(a[3]), "r"(b[0]), "r"(b[1]));
}
__device__ __forceinline__ void cp16(uint32_t saddr, const void* gaddr) {
    asm volatile("cp.async.cg.shared.global [%0], [%1], 16;" :: "r"(saddr), "l"(gaddr));
}
#define CP_COMMIT() asm volatile("cp.async.commit_group;" ::: "memory")
#define CP_WAIT(n)  asm volatile("cp.async.wait_group %0;" :: "n"(n) : "memory")

// ---------------------------------------------------------------------------
// Final HMMA GEMM, single fp16 segment, cp.async 3-stage pipeline.
// out[m,n] = A[m,:] @ Bt_b[n,:] + bias_b[n]
// Tile 128x128, BK=32, 16 K-steps, 8 warps (2x4).
// ---------------------------------------------------------------------------
#define LDT    40                 // padded smem row stride in halves
#define TILEH  (128 * LDT)        // tile size in halves (5120)
#define STAGEH (2 * TILEH)        // A, B per stage
#define NSTAGE 3
#define GEMM_SMEM (NSTAGE * STAGEH * 2)   // bytes = 61440

__global__ __launch_bounds__(256, 2)
void hmma_gemm_fused(const __half* __restrict__ A0,
                     const __half* __restrict__ Bt,
                     const float* __restrict__ bias, float* __restrict__ C)
{
    extern __shared__ __half smem[];

    const int tid  = threadIdx.x;
    const int wid  = tid >> 5;
    const int lane = tid & 31;
    const int wm   = wid & 1;
    const int wn   = wid >> 1;
    const int row0 = blockIdx.y * 128;
    const int col0 = blockIdx.x * 128;
    const int b    = row0 / T_;

    const __half* Btb = Bt + (size_t)b * E_ * E_;
    const float* bias_b = bias + b * E_;

    const int r0c = tid >> 2,           kg0 = tid & 3;
    const int r1c = (tid + 256) >> 2,   kg1 = (tid + 256) & 3;
    const uint32_t sbase = smem_u32(smem);

    float acc[4][4][4];
    #pragma unroll
    for (int i = 0; i < 4; i++)
        #pragma unroll
        for (int j = 0; j < 4; j++)
            #pragma unroll
            for (int u = 0; u < 4; u++) acc[i][j][u] = 0.f;

    auto issue = [&](int s) {
        const int k0 = s * 32;
        const uint32_t st = sbase + (uint32_t)((s % NSTAGE) * STAGEH) * 2;
        const uint32_t o0 = (uint32_t)(r0c * LDT + kg0 * 8) * 2;
        const uint32_t o1 = (uint32_t)(r1c * LDT + kg1 * 8) * 2;
        cp16(st + o0,             A0  + (size_t)(row0 + r0c) * E_ + k0 + kg0 * 8);
        cp16(st + o1,             A0  + (size_t)(row0 + r1c) * E_ + k0 + kg1 * 8);
        cp16(st + TILEH * 2 + o0, Btb + (size_t)(col0 + r0c) * E_ + k0 + kg0 * 8);
        cp16(st + TILEH * 2 + o1, Btb + (size_t)(col0 + r1c) * E_ + k0 + kg1 * 8);
        CP_COMMIT();
    };

    issue(0);
    issue(1);

    const int r   = lane & 7;
    const int sel = lane >> 3;

    for (int i = 0; i < 16; i++) {
        CP_WAIT(1);
        __syncthreads();

        if (i + 2 < 16) issue(i + 2);

        const uint32_t st = sbase + (uint32_t)((i % NSTAGE) * STAGEH) * 2;
        const uint32_t a_base = st;
        const uint32_t b_base = st + TILEH * 2;

        #pragma unroll
        for (int ks = 0; ks < 2; ks++) {
            const int k = ks * 16;
            uint32_t bfr[4][2];
            #pragma unroll
            for (int p = 0; p < 2; p++) {
                uint32_t addr = b_base +
                    (uint32_t)((wn * 32 + p * 16 + r + (sel >> 1) * 8) * LDT + k + (sel & 1) * 8) * 2;
                ldm_x4(bfr[2 * p][0], bfr[2 * p][1], bfr[2 * p + 1][0], bfr[2 * p + 1][1], addr);
            }
            const uint32_t a_off = a_base +
                (uint32_t)((wm * 64 + r + (sel & 1) * 8) * LDT + k + (sel >> 1) * 8) * 2;
            #pragma unroll
            for (int mt = 0; mt < 4; mt++) {
                uint32_t af[4];
                ldm_x4(af[0], af[1], af[2], af[3], a_off + (uint32_t)(mt * 16 * LDT) * 2);
                #pragma unroll
                for (int nt = 0; nt < 4; nt++)
                    mma16816(acc[mt][nt], af, bfr[nt]);
            }
        }
        __syncthreads();
    }

    #pragma unroll
    for (int mt = 0; mt < 4; mt++) {
        const int mg = row0 + wm * 64 + mt * 16 + (lane >> 2);
        #pragma unroll
        for (int nt = 0; nt < 4; nt++) {
            const int ng = col0 + wn * 32 + nt * 8 + (lane & 3) * 2;
            const float bi0 = bias_b[ng], bi1 = bias_b[ng + 1];
            *reinterpret_cast<float2*>(C + (size_t)mg * E_ + ng) =
                make_float2(acc[mt][nt][0] + bi0, acc[mt][nt][1] + bi1);
            *reinterpret_cast<float2*>(C + (size_t)(mg + 8) * E_ + ng) =
                make_float2(acc[mt][nt][2] + bi0, acc[mt][nt][3] + bi1);
        }
    }
}

// ---------------------------------------------------------------------------
// buildM HMMA: mt[m=b*512+n][e1] = fp16( sum_e2 wakt[m][e2]*wqh[e1][e2] + Wq[e1][n] )
// ---------------------------------------------------------------------------
__global__ __launch_bounds__(256, 2)
void hmma_buildM(const __half* __restrict__ A0, const __half* __restrict__ Bt,
                 const float* __restrict__ Wq, __half* __restrict__ Cmt)
{
    __shared__ __align__(16) __half As[2][128 * LDT];
    __shared__ __align__(16) __half Bs[2][128 * LDT];

    const int tid  = threadIdx.x;
    const int wid  = tid >> 5;
    const int lane = tid & 31;
    const int wm   = wid & 1;
    const int wn   = wid >> 1;
    const int row0 = blockIdx.y * 128;
    const int col0 = blockIdx.x * 128;

    const int lrow  = tid & 127;
    const int lhalf = tid >> 7;

    float acc[4][4][4];
    #pragma unroll
    for (int i = 0; i < 4; i++)
        #pragma unroll
        for (int j = 0; j < 4; j++)
            #pragma unroll
            for (int u = 0; u < 4; u++) acc[i][j][u] = 0.f;

    uint4 ar0, ar1, br0, br1;
    {
        const __half* ga = A0 + (size_t)(row0 + lrow) * E_ + lhalf * 16;
        const __half* gb = Bt + (size_t)(col0 + lrow) * E_ + lhalf * 16;
        ar0 = reinterpret_cast<const uint4*>(ga)[0];
        ar1 = reinterpret_cast<const uint4*>(ga)[1];
        br0 = reinterpret_cast<const uint4*>(gb)[0];
        br1 = reinterpret_cast<const uint4*>(gb)[1];
        __half* sa = &As[0][lrow * LDT + lhalf * 16];
        __half* sb = &Bs[0][lrow * LDT + lhalf * 16];
        reinterpret_cast<uint4*>(sa)[0] = ar0;
        reinterpret_cast<uint4*>(sa)[1] = ar1;
        reinterpret_cast<uint4*>(sb)[0] = br0;
        reinterpret_cast<uint4*>(sb)[1] = br1;
    }
    __syncthreads();

    const int r   = lane & 7;
    const int sel = lane >> 3;

    for (int i = 0; i < 16; i++) {
        const int buf = i & 1;
        if (i + 1 < 16) {
            const int k0 = (i + 1) * 32;
            const __half* ga = A0 + (size_t)(row0 + lrow) * E_ + k0 + lhalf * 16;
            const __half* gb = Bt + (size_t)(col0 + lrow) * E_ + k0 + lhalf * 16;
            ar0 = reinterpret_cast<const uint4*>(ga)[0];
            ar1 = reinterpret_cast<const uint4*>(ga)[1];
            br0 = reinterpret_cast<const uint4*>(gb)[0];
            br1 = reinterpret_cast<const uint4*>(gb)[1];
        }

        const uint32_t abase = smem_u32(&As[buf][0]);
        const uint32_t bbase = smem_u32(&Bs[buf][0]);
        #pragma unroll
        for (int ks = 0; ks < 2; ks++) {
            const int k = ks * 16;
            uint32_t bfr[4][2];
            #pragma unroll
            for (int p = 0; p < 2; p++) {
                uint32_t addr = bbase +
                    (uint32_t)((wn * 32 + p * 16 + r + (sel >> 1) * 8) * LDT + k + (sel & 1) * 8) * 2;
                ldm_x4(bfr[2 * p][0], bfr[2 * p][1], bfr[2 * p + 1][0], bfr[2 * p + 1][1], addr);
            }
            #pragma unroll
            for (int mt = 0; mt < 4; mt++) {
                uint32_t af[4];
                uint32_t addr = abase +
                    (uint32_t)((wm * 64 + mt * 16 + r + (sel & 1) * 8) * LDT + k + (sel >> 1) * 8) * 2;
                ldm_x4(af[0], af[1], af[2], af[3], addr);
                #pragma unroll
                for (int nt = 0; nt < 4; nt++)
                    mma16816(acc[mt][nt], af, bfr[nt]);
            }
        }

        if (i + 1 < 16) {
            const int nb = (i + 1) & 1;
            __half* sa = &As[nb][lrow * LDT + lhalf * 16];
            __half* sb = &Bs[nb][lrow * LDT + lhalf * 16];
            reinterpret_cast<uint4*>(sa)[0] = ar0;
            reinterpret_cast<uint4*>(sa)[1] = ar1;
            reinterpret_cast<uint4*>(sb)[0] = br0;
            reinterpret_cast<uint4*>(sb)[1] = br1;
            __syncthreads();
        }
    }

    #pragma unroll
    for (int mt = 0; mt < 4; mt++) {
        const int mg = row0 + wm * 64 + mt * 16 + (lane >> 2);
        const int n  = mg & 511;
        #pragma unroll
        for (int nt = 0; nt < 4; nt++) {
            const int ng = col0 + wn * 32 + nt * 8 + (lane & 3) * 2;
            float v0 = acc[mt][nt][0] + Wq[(size_t)ng * E_ + n];
            float v1 = acc[mt][nt][1] + Wq[(size_t)(ng + 1) * E_ + n];
            float v2 = acc[mt][nt][2] + Wq[(size_t)ng * E_ + n + 8];
            float v3 = acc[mt][nt][3] + Wq[(size_t)(ng + 1) * E_ + n + 8];
            *reinterpret_cast<__half2*>(Cmt + (size_t)mg * E_ + ng) =
                __half2(__float2half(v0), __float2half(v1));
            *reinterpret_cast<__half2*>(Cmt + (size_t)(mg + 8) * E_ + ng) =
                __half2(__float2half(v2), __float2half(v3));
        }
    }
}

// ---------------------------------------------------------------------------
// wakt[b*512+n][e2] = fp16( Wo[e2][n] * kf[b][e2] )
// ---------------------------------------------------------------------------
__global__ __launch_bounds__(256)
void woTkf_kernel(const float* __restrict__ Wo, const float* __restrict__ kf,
                  __half* __restrict__ wakt)
{
    __shared__ float t[32][33];
    const int n0 = blockIdx.x * 32, e20 = blockIdx.y * 32, b = blockIdx.z;
    const int tx = threadIdx.x & 31, ty = threadIdx.x >> 5;
    #pragma unroll
    for (int j = 0; j < 4; j++) {
        const int e2 = e20 + ty * 4 + j;
        t[ty * 4 + j][tx] = Wo[(size_t)e2 * E_ + n0 + tx] * kf[b * E_ + e2];
    }
    __syncthreads();
    #pragma unroll
    for (int j = 0; j < 4; j++) {
        const int n = n0 + ty * 4 + j;
        wakt[((size_t)b * E_ + n) * E_ + e20 + tx] = __float2half(t[tx][ty * 4 + j]);
    }
}

__global__ __launch_bounds__(256)
void wq_conv_kernel(const float* __restrict__ Wq, __half* __restrict__ wqh)
{
    const int i = blockIdx.x * 256 + threadIdx.x;
    const float4 v = reinterpret_cast<const float4*>(Wq)[i];
    __half2* hp = reinterpret_cast<__half2*>(wqh) + 2 * i;
    hp[0] = __half2(__float2half(v.x), __float2half(v.y));
    hp[1] = __half2(__float2half(v.z), __float2half(v.w));
}

// ---------------------------------------------------------------------------
// C[bb][e1][h] = sum_e2 W[e1,e2] * s[e2] * Wa[e2,h]
// ---------------------------------------------------------------------------
template<bool SCALED>
__global__ __launch_bounds__(256)
void cmat_kernel(const float* __restrict__ W, const float* __restrict__ Wa,
                 const float* __restrict__ bvec, const float* __restrict__ ba,
                 const float* __restrict__ scale,
                 float* __restrict__ C, float* __restrict__ cv)
{
    const int bb = blockIdx.y;
    __shared__ float s[E_][H_];
    const int tid = threadIdx.x;
    for (int i = tid; i < E_ * H_; i += 256) {
        const int e2 = i >> 3, h = i & 7;
        const float sc = SCALED ? scale[bb * E_ + e2] : 1.f;
        s[e2][h] = sc * Wa[i];
    }
    __syncthreads();
    const int e1 = blockIdx.x * 32 + (tid >> 3);
    const int h  = tid & 7;
    const float* wr = W + (size_t)e1 * E_;
    float acc = 0.f;
    for (int e2 = 0; e2 < E_; e2++) acc = fmaf(wr[e2], s[e2][h], acc);
    C[((size_t)bb * E_ + e1) * H_ + h] = acc;
    if (blockIdx.x == 0 && tid < H_) {
        float a = 0.f;
        for (int e2 = 0; e2 < E_; e2++) a = fmaf(bvec[e2], s[e2][tid], a);
        cv[bb * H_ + tid] = a + ba[tid];
    }
}

// ---------------------------------------------------------------------------
// Fused: convert x -> fp16 AND q_scores = x@Cq + cq
// ---------------------------------------------------------------------------
__global__ __launch_bounds__(256)
void split_scores_kernel(const float* __restrict__ x, __half* __restrict__ ah,
                         const float* __restrict__ Cq, const float* __restrict__ cq,
                         float* __restrict__ S)
{
    __shared__ float wT[H_][E_];
    __shared__ float bsh[H_];
    const int tid = threadIdx.x;
    for (int i = tid; i < E_ * H_; i += 256) wT[i & 7][i >> 3] = Cq[i];
    if (tid < H_) bsh[tid] = cq[tid];
    __syncthreads();

    const int warp = tid >> 5, lane = tid & 31;
    const int m = blockIdx.x * 8 + warp;
    const float4* xr = reinterpret_cast<const float4*>(x + (size_t)m * E_);

    float s[H_] = {0.f, 0.f, 0.f, 0.f, 0.f, 0.f, 0.f, 0.f};
    #pragma unroll
    for (int c = 0; c < 4; c++) {
        const int fi = c * 32 + lane;
        const float4 v = xr[fi];
        const int e = fi * 4;
        #pragma unroll
        for (int h = 0; h < H_; h++)
            s[h] += v.x * wT[h][e] + v.y * wT[h][e + 1] + v.z * wT[h][e + 2] + v.w * wT[h][e + 3];
        __half2* hp = reinterpret_cast<__half2*>(ah + (size_t)m * E_ + e);
        hp[0] = __half2(__float2half(v.x), __float2half(v.y));
        hp[1] = __half2(__float2half(v.z), __float2half(v.w));
    }
    #pragma unroll
    for (int off = 16; off; off >>= 1)
        #pragma unroll
        for (int h = 0; h < H_; h++) s[h] += __shfl_xor_sync(0xffffffffu, s[h], off);
    if (lane < H_) S[(size_t)m * H_ + lane] = s[lane] + bsh[lane];
}

// k_scores with per-batch C, reading fp16 x
__global__ __launch_bounds__(256)
void scores_pb_kernel(const __half* __restrict__ xh, const float* __restrict__ C,
                      const float* __restrict__ cv, float* __restrict__ S)
{
    const int b = blockIdx.x >> 9;
    __shared__ float wT[H_][E_];
    __shared__ float bsh[H_];
    const int tid = threadIdx.x;
    const float* Cb = C + (size_t)b * E_ * H_;
    for (int i = tid; i < E_ * H_; i += 256) wT[i & 7][i >> 3] = Cb[i];
    if (tid < H_) bsh[tid] = cv[b * H_ + tid];
    __syncthreads();

    const int warp = tid >> 5, lane = tid & 31;
    const int m = blockIdx.x * 8 + warp;
    const uint4* xr = reinterpret_cast<const uint4*>(xh + (size_t)m * E_);

    float s[H_] = {0.f, 0.f, 0.f, 0.f, 0.f, 0.f, 0.f, 0.f};
    #pragma unroll
    for (int c = 0; c < 2; c++) {
        const int fi = c * 32 + lane;
        const uint4 raw = xr[fi];
        const int e = fi * 8;
        const __half2* p = reinterpret_cast<const __half2*>(&raw);
        #pragma unroll
        for (int j = 0; j < 4; j++) {
            const float2 f = __half22float2(p[j]);
            #pragma unroll
            for (int h = 0; h < H_; h++)
                s[h] += f.x * wT[h][e + 2 * j] + f.y * wT[h][e + 2 * j + 1];
        }
    }
    #pragma unroll
    for (int off = 16; off; off >>= 1)
        #pragma unroll
        for (int h = 0; h < H_; h++) s[h] += __shfl_xor_sync(0xffffffffu, s[h], off);
    if (lane < H_) S[(size_t)m * H_ + lane] = s[lane] + bsh[lane];
}

// ---------------------------------------------------------------------------
// softmax weights per (b,h) — 1024 threads
// ---------------------------------------------------------------------------
__global__ __launch_bounds__(1024)
void softmax_kernel(const float* __restrict__ S, const unsigned char* __restrict__ mask,
                    float* __restrict__ w)
{
    const int bh = blockIdx.x;
    const int b = bh >> 3, h = bh & 7;
    __shared__ float buf[T_];
    __shared__ float red[1024];
    const int tid = threadIdx.x;

    float mx = -INFINITY;
    #pragma unroll
    for (int c = 0; c < 4; c++) {
        const int t = c * 1024 + tid;
        float s = S[((size_t)b * T_ + t) * H_ + h] * 0.125f;
        if (mask[b * T_ + t]) s = -INFINITY;
        buf[t] = s;
        mx = fmaxf(mx, s);
    }
    red[tid] = mx; __syncthreads();
    #pragma unroll
    for (int s2 = 512; s2 > 0; s2 >>= 1) {
        if (tid < s2) red[tid] = fmaxf(red[tid], red[tid + s2]);
        __syncthreads();
    }
    mx = red[0];
    __syncthreads();

    float sum = 0.f;
    #pragma unroll
    for (int c = 0; c < 4; c++) {
        const int t = c * 1024 + tid;
        const float e = expf(buf[t] - mx);
        buf[t] = e;
        sum += e;
    }
    red[tid] = sum; __syncthreads();
    #pragma unroll
    for (int s2 = 512; s2 > 0; s2 >>= 1) {
        if (tid < s2) red[tid] += red[tid + s2];
        __syncthreads();
    }
    const float inv = 1.f / red[0];
    __syncthreads();
    #pragma unroll
    for (int c = 0; c < 4; c++) {
        const int t = c * 1024 + tid;
        w[(size_t)bh * T_ + t] = buf[t] * inv;
    }
}

// ---------------------------------------------------------------------------
// pool fp16 x with all 8 head-weights: partial[chunk][b][h][e], 64 t per chunk
// ---------------------------------------------------------------------------
__global__ __launch_bounds__(256)
void pool_x_kernel(const float* __restrict__ w, const __half* __restrict__ xh,
                   float* __restrict__ partial)
{
    const int chunk = blockIdx.x, b = blockIdx.y;
    __shared__ float ws[H_][64];
    const int tid = threadIdx.x;
    for (int i = tid; i < H_ * 64; i += 256)
        ws[i >> 6][i & 63] = w[(size_t)(b * 8 + (i >> 6)) * T_ + chunk * 64 + (i & 63)];
    __syncthreads();

    float acc[H_][2];
    #pragma unroll
    for (int h = 0; h < H_; h++) { acc[h][0] = 0.f; acc[h][1] = 0.f; }

    const __half* xp = xh + (size_t)b * T_ * E_ + (size_t)chunk * 64 * E_;
    for (int tt = 0; tt < 64; tt++) {
        const __half2 hv = *reinterpret_cast<const __half2*>(xp + (size_t)tt * E_ + tid * 2);
        const float2 v = __half22float2(hv);
        #pragma unroll
        for (int h = 0; h < H_; h++) {
            acc[h][0] = fmaf(ws[h][tt], v.x, acc[h][0]);
            acc[h][1] = fmaf(ws[h][tt], v.y, acc[h][1]);
        }
    }
    #pragma unroll
    for (int h = 0; h < H_; h++) {
        float* pp = partial + (((size_t)chunk * 8 + b) * 8 + h) * E_ + tid * 2;
        pp[0] = acc[h][0]; pp[1] = acc[h][1];
    }
}

// ---------------------------------------------------------------------------
// flat: out[b, h*64+d] = (sum_c partial[c][b][h][:]) @ W[:, h*64+d] + bvec  (*qf)
// ---------------------------------------------------------------------------
template<bool MULQF>
__global__ __launch_bounds__(256)
void flat_kernel(const float* __restrict__ partial, const float* __restrict__ W,
                 const float* __restrict__ bvec, const float* __restrict__ qf_in,
                 float* __restrict__ out)
{
    const int b = blockIdx.x, h = blockIdx.y;
    __shared__ float px[E_];
    __shared__ float red[256];
    const int tid = threadIdx.x;
    for (int e = tid; e < E_; e += 256) {
        float a = 0.f;
        #pragma unroll
        for (int c = 0; c < NCHUNK; c++) a += partial[(((size_t)c * 8 + b) * 8 + h) * E_ + e];
        px[e] = a;
    }
    __syncthreads();
    const int d = tid & 63, q = tid >> 6;
    float acc = 0.f;
    for (int k = q * 128; k < q * 128 + 128; k++)
        acc = fmaf(px[k], W[(size_t)k * E_ + h * D_ + d], acc);
    red[tid] = acc; __syncthreads();
    if (tid < 64) {
        float v = red[tid] + red[tid + 64] + red[tid + 128] + red[tid + 192] + bvec[h * D_ + d];
        if (MULQF) v *= qf_in[b * E_ + h * D_ + d];
        out[b * E_ + h * D_ + d] = v;
    }
}

// cb[b][n] = sum_e bq[e]*kf[b,e]*Wo[e,n] + bo[n] + bq[n]
__global__ __launch_bounds__(128)
void cbias_kernel(const float* __restrict__ Wo, const float* __restrict__ bq,
                  const float* __restrict__ bo, const float* __restrict__ kf,
                  float* __restrict__ cb)
{
    const int b = blockIdx.y;
    const int n = blockIdx.x * 128 + threadIdx.x;
    float a = 0.f;
    for (int e = 0; e < E_; e++) a = fmaf(bq[e] * kf[b * E_ + e], Wo[(size_t)e * E_ + n], a);
    cb[b * E_ + n] = a + bo[n] + bq[n];
}

// ---------------------------------------------------------------------------
// Launch sequence
// ---------------------------------------------------------------------------
extern "C" void kernel_launch(void* const* d_in, const int* in_sizes, int n_in,
                              void* d_out, int out_size)
{
    const float* x            = (const float*)d_in[0];
    const unsigned char* mask = (const unsigned char*)d_in[3];
    const float* Wq  = (const float*)d_in[4];
    const float* bq  = (const float*)d_in[5];
    const float* Waq = (const float*)d_in[6];
    const float* baq = (const float*)d_in[7];
    const float* Wk  = (const float*)d_in[8];
    const float* bk  = (const float*)d_in[9];
    const float* Wak = (const float*)d_in[10];
    const float* bak = (const float*)d_in[11];
    const float* Wo  = (const float*)d_in[12];
    const float* bo  = (const float*)d_in[13];
    float* out = (float*)d_out;

    float *sc_, *w_, *pp_, *qf_, *kf_, *Cq_, *cq_, *Ck_, *ck_, *cb_;
    __half *ah, *mt, *wakt, *wqh;
    cudaGetSymbolAddress((void**)&sc_, g_scores);
    cudaGetSymbolAddress((void**)&w_,  g_w);
    cudaGetSymbolAddress((void**)&pp_, g_partial);
    cudaGetSymbolAddress((void**)&qf_, g_qf);
    cudaGetSymbolAddress((void**)&kf_, g_kf);
    cudaGetSymbolAddress((void**)&Cq_, g_Cq);
    cudaGetSymbolAddress((void**)&cq_, g_cq);
    cudaGetSymbolAddress((void**)&Ck_, g_Ck);
    cudaGetSymbolAddress((void**)&ck_, g_ck);
    cudaGetSymbolAddress((void**)&cb_, g_cb);
    cudaGetSymbolAddress((void**)&ah,  g_ah);
    cudaGetSymbolAddress((void**)&mt,  g_mt);
    cudaGetSymbolAddress((void**)&wakt, g_wakt);
    cudaGetSymbolAddress((void**)&wqh, g_wqh);

    cudaFuncSetAttribute(hmma_gemm_fused, cudaFuncAttributeMaxDynamicSharedMemorySize, GEMM_SMEM);

    // 1) Cq = Wq@Waq; fused fp16 convert of x + q_scores; Wq fp16 convert
    cmat_kernel<false><<<dim3(16, 1), 256>>>(Wq, Waq, bq, baq, nullptr, Cq_, cq_);
    wq_conv_kernel<<<E_ * E_ / 1024, 256>>>(Wq, wqh);
    split_scores_kernel<<<M_ / 8, 256>>>(x, ah, Cq_, cq_, sc_);
    // 2) q softmax + pool (fp16 x) + q_flat
    softmax_kernel<<<B_ * H_, 1024>>>(sc_, mask, w_);
    pool_x_kernel<<<dim3(NCHUNK, B_), 256>>>(w_, ah, pp_);
    flat_kernel<false><<<dim3(B_, H_), 256>>>(pp_, Wq, bq, nullptr, qf_);
    // 3) per-batch Ck; k_scores from fp16 x
    cmat_kernel<true><<<dim3(16, B_), 256>>>(Wk, Wak, bk, bak, qf_, Ck_, ck_);
    scores_pb_kernel<<<M_ / 8, 256>>>(ah, Ck_, ck_, sc_);
    // 4) k softmax + pool (fp16 x) + k_flat
    softmax_kernel<<<B_ * H_, 1024>>>(sc_, mask, w_);
    pool_x_kernel<<<dim3(NCHUNK, B_), 256>>>(w_, ah, pp_);
    flat_kernel<true><<<dim3(B_, H_), 256>>>(pp_, Wk, bk, qf_, kf_);
    // 5) M^T via tensor cores
    woTkf_kernel<<<dim3(E_ / 32, E_ / 32, B_), 256>>>(Wo, kf_, wakt);
    cbias_kernel<<<dim3(4, B_), 128>>>(Wo, bq, bo, kf_, cb_);
    hmma_buildM<<<dim3(E_ / 128, B_ * E_ / 128), 256>>>(wakt, wqh, Wq, mt);
    // 6) final GEMM: out = x @ M_b + cb_b   (single fp16 segment, cp.async pipeline)
    hmma_gemm_fused<<<dim3(E_ / 128, M_ / 128), 256, GEMM_SMEM>>>(ah, mt, cb_, out);
}